// round 2
// baseline (speedup 1.0000x reference)
#include <cuda_runtime.h>
#include <cuda_bf16.h>

// ---------------- problem constants (shapes fixed by setup_inputs) ----------
#define BS    16
#define NTOK  3900
#define DIM   512
#define HEADS 8
#define DH    64
#define CTX   200
#define NB    20          // ceil(3900/200)
#define MROWS (BS*NTOK)   // 62400
#define MAXPOS 512

// table rows needed: dist in [-199,199] -> global rows 313..711 (399 rows)
#define TROWS 399
#define TBASE 313
#define KSTRIDE 68        // padded k stride (floats) for conflict-light LDS.128
#define TSTRIDE 66        // padded bf16 table stride (bank stride 1)

// ---------------- scratch (no allocations allowed) ---------------------------
__device__ float g_q [(size_t)MROWS * DIM];        // 127.8 MB
__device__ float g_kv[(size_t)MROWS * 2 * DIM];    // 255.6 MB
__device__ float g_ao[(size_t)MROWS * DIM];        // 127.8 MB

// ---------------- generic fp32 SGEMM: C[M,N] = A[M,K] @ B[K,N] (+bias) ------
#define BM 128
#define BN 128
#define BK 8

template<bool BIAS>
__global__ void __launch_bounds__(256)
sgemm_kernel(const float* __restrict__ A, const float* __restrict__ B,
             const float* __restrict__ bias, float* __restrict__ C,
             int M, int N, int K)
{
    __shared__ float As[BK][BM];
    __shared__ float Bs[BK][BN];

    const int tid = threadIdx.x;
    const int m0 = blockIdx.y * BM;
    const int n0 = blockIdx.x * BN;
    const int tx = tid & 15, ty = tid >> 4;

    const int row_a = tid >> 1;          // 0..127
    const int kgrp  = (tid & 1) * 4;     // 0 or 4
    const int row_b = tid >> 5;          // 0..7
    const int col_b = (tid & 31) * 4;

    float acc[8][8];
#pragma unroll
    for (int i = 0; i < 8; i++)
#pragma unroll
        for (int j = 0; j < 8; j++) acc[i][j] = 0.f;

    for (int k0 = 0; k0 < K; k0 += BK) {
        float4 av;
        if (m0 + row_a < M)
            av = *(const float4*)&A[(size_t)(m0 + row_a) * K + k0 + kgrp];
        else
            av = make_float4(0.f, 0.f, 0.f, 0.f);
        As[kgrp + 0][row_a] = av.x;
        As[kgrp + 1][row_a] = av.y;
        As[kgrp + 2][row_a] = av.z;
        As[kgrp + 3][row_a] = av.w;

        float4 bv = *(const float4*)&B[(size_t)(k0 + row_b) * N + n0 + col_b];
        *(float4*)&Bs[row_b][col_b] = bv;
        __syncthreads();

#pragma unroll
        for (int kk = 0; kk < BK; kk++) {
            float a[8], b[8];
            *(float4*)&a[0] = *(const float4*)&As[kk][ty * 8];
            *(float4*)&a[4] = *(const float4*)&As[kk][ty * 8 + 4];
            *(float4*)&b[0] = *(const float4*)&Bs[kk][tx * 8];
            *(float4*)&b[4] = *(const float4*)&Bs[kk][tx * 8 + 4];
#pragma unroll
            for (int i = 0; i < 8; i++)
#pragma unroll
                for (int j = 0; j < 8; j++)
                    acc[i][j] += a[i] * b[j];
        }
        __syncthreads();
    }

#pragma unroll
    for (int i = 0; i < 8; i++) {
        int m = m0 + ty * 8 + i;
        if (m >= M) break;
        float* crow = &C[(size_t)m * N + n0 + tx * 8];
#pragma unroll
        for (int j = 0; j < 8; j += 4) {
            float4 o;
            o.x = acc[i][j];     o.y = acc[i][j + 1];
            o.z = acc[i][j + 2]; o.w = acc[i][j + 3];
            if (BIAS) {
                const float* bb = &bias[n0 + tx * 8 + j];
                o.x += bb[0]; o.y += bb[1]; o.z += bb[2]; o.w += bb[3];
            }
            *(float4*)&crow[j] = o;
        }
    }
}

// ---------------- chunked attention with relative position bias --------------
// grid: (NB*HEADS, BS), block 256 (8 warps).  One block = one (b, chunk, head).
// SMEM: qs[200][64] fp32 | ks[200][68] fp32 | vs[200][64] fp32 |
//       ts[399][66] bf16 | ps[8][200] fp32   ~= 215.9 KB dynamic

#define ATTN_SMEM_BYTES ((CTX*DH + CTX*KSTRIDE + CTX*DH) * 4 \
                         + TROWS * TSTRIDE * 2 + 8 * CTX * 4)

__global__ void __launch_bounds__(256)
attn_kernel(const float* __restrict__ Q, const float* __restrict__ KV,
            const float* __restrict__ T, float* __restrict__ AO)
{
    extern __shared__ float sm[];
    float* qs = sm;                               // [CTX][64]
    float* ks = qs + CTX * DH;                    // [CTX][68]
    float* vs = ks + CTX * KSTRIDE;               // [CTX][64]
    __nv_bfloat16* ts = (__nv_bfloat16*)(vs + CTX * DH);  // [399][66]
    float* ps = (float*)(ts + TROWS * TSTRIDE);   // [8][CTX]

    const int b  = blockIdx.y;
    const int m  = blockIdx.x / HEADS;
    const int h  = blockIdx.x % HEADS;
    const int t0 = m * CTX;
    const int cv = (NTOK - t0 < CTX) ? (NTOK - t0) : CTX;   // 200, or 100 on last chunk
    const int tid = threadIdx.x;

    // stage q/k/v chunk tiles
    for (int idx = tid; idx < cv * 16; idx += 256) {
        const int i = idx >> 4;
        const int d = (idx & 15) * 4;
        const size_t row = (size_t)(b * NTOK + t0 + i);
        float4 qv = *(const float4*)&Q[row * DIM + h * DH + d];
        *(float4*)&qs[i * DH + d] = qv;
        float4 kv4 = *(const float4*)&KV[row * (2 * DIM) + h * DH + d];
        *(float4*)&ks[i * KSTRIDE + d] = kv4;
        float4 vv = *(const float4*)&KV[row * (2 * DIM) + DIM + h * DH + d];
        *(float4*)&vs[i * DH + d] = vv;
    }
    // stage rel-pos table rows 313..711 as bf16
    for (int idx = tid; idx < TROWS * 32; idx += 256) {
        const int r  = idx >> 5;
        const int e2 = (idx & 31) * 2;
        float2 tv = *(const float2*)&T[(size_t)(TBASE + r) * DH + e2];
        ts[r * TSTRIDE + e2]     = __float2bfloat16(tv.x);
        ts[r * TSTRIDE + e2 + 1] = __float2bfloat16(tv.y);
    }
    __syncthreads();

    const int w    = tid >> 5;
    const int lane = tid & 31;
    float* p = ps + w * CTX;

    for (int i = w; i < cv; i += 8) {
        const float* qrow = &qs[i * DH];
        float lmax = -1e30f;
        for (int j = lane; j < cv; j += 32) {
            const float* krow = &ks[j * KSTRIDE];
            const __nv_bfloat16* trow = &ts[(i - j + CTX - 1) * TSTRIDE];
            float dot = 0.f, rdot = 0.f;
#pragma unroll
            for (int d = 0; d < DH; d += 4) {
                float4 q4 = *(const float4*)&qrow[d];
                float4 k4 = *(const float4*)&krow[d];
                __nv_bfloat162 t01 = *(const __nv_bfloat162*)&trow[d];
                __nv_bfloat162 t23 = *(const __nv_bfloat162*)&trow[d + 2];
                float2 f01 = __bfloat1622float2(t01);
                float2 f23 = __bfloat1622float2(t23);
                dot  += q4.x * k4.x + q4.y * k4.y + q4.z * k4.z + q4.w * k4.w;
                rdot += q4.x * f01.x + q4.y * f01.y + q4.z * f23.x + q4.w * f23.y;
            }
            float s = (dot + rdot) * 0.125f;   // dh^-0.5
            p[j] = s;
            lmax = fmaxf(lmax, s);
        }
#pragma unroll
        for (int o = 16; o; o >>= 1) lmax = fmaxf(lmax, __shfl_xor_sync(~0u, lmax, o));
        __syncwarp();
        float lsum = 0.f;
        for (int j = lane; j < cv; j += 32) {
            float e = __expf(p[j] - lmax);
            p[j] = e;
            lsum += e;
        }
#pragma unroll
        for (int o = 16; o; o >>= 1) lsum += __shfl_xor_sync(~0u, lsum, o);
        const float inv = 1.f / lsum;
        __syncwarp();

        float acc0 = 0.f, acc1 = 0.f;
        const int d0 = lane, d1 = lane + 32;
        for (int j = 0; j < cv; j++) {
            float pj = p[j];
            acc0 += pj * vs[j * DH + d0];
            acc1 += pj * vs[j * DH + d1];
        }
        const size_t orow = (size_t)(b * NTOK + t0 + i) * DIM + h * DH;
        AO[orow + d0] = acc0 * inv;
        AO[orow + d1] = acc1 * inv;
        __syncwarp();   // p reused next row
    }
}

// ---------------- launcher ----------------------------------------------------
extern "C" void kernel_launch(void* const* d_in, const int* in_sizes, int n_in,
                              void* d_out, int out_size)
{
    const float* x      = (const float*)d_in[0];
    const float* wq     = (const float*)d_in[1];
    const float* wkv    = (const float*)d_in[2];
    const float* wout_w = (const float*)d_in[3];
    const float* wout_b = (const float*)d_in[4];
    const float* rel    = (const float*)d_in[5];
    float* out = (float*)d_out;

    void *pq, *pkv, *pao;
    cudaGetSymbolAddress(&pq,  g_q);
    cudaGetSymbolAddress(&pkv, g_kv);
    cudaGetSymbolAddress(&pao, g_ao);

    cudaFuncSetAttribute(attn_kernel,
                         cudaFuncAttributeMaxDynamicSharedMemorySize,
                         ATTN_SMEM_BYTES);

    const int M = MROWS;
    dim3 blk(256);
    dim3 gq (DIM / BN,       (M + BM - 1) / BM);
    dim3 gkv(2 * DIM / BN,   (M + BM - 1) / BM);

    // Q = X @ Wq ; KV = X @ Wkv
    sgemm_kernel<false><<<gq,  blk>>>(x, wq,  nullptr, (float*)pq,  M, DIM,     DIM);
    sgemm_kernel<false><<<gkv, blk>>>(x, wkv, nullptr, (float*)pkv, M, 2 * DIM, DIM);

    // chunked attention
    attn_kernel<<<dim3(NB * HEADS, BS), blk, ATTN_SMEM_BYTES>>>(
        (const float*)pq, (const float*)pkv, rel, (float*)pao);

    // out = AO @ Wout + b
    sgemm_kernel<true><<<gq, blk>>>((const float*)pao, wout_w, wout_b, out, M, DIM, DIM);
}

// round 3
// speedup vs baseline: 1.3798x; 1.3798x over previous
#include <cuda_runtime.h>
#include <cuda_bf16.h>

// ---------------- problem constants ----------------
#define BS    16
#define NTOK  3900
#define DIM   512
#define HEADS 8
#define DH    64
#define CTX   200
#define NB    20
#define MROWS (BS*NTOK)   // 62400
#define TROWS 399
#define TBASE 313
#define KSTRIDE 68
#define TSTRIDE 66
#define NQKV  1536        // fused q|k|v output width

// ---------------- scratch ----------------
__device__ float g_qkv[(size_t)MROWS * NQKV];   // 383 MB
__device__ float g_ao [(size_t)MROWS * DIM];    // 128 MB
__device__ float g_w  [DIM * NQKV];             // packed [Wq|Wkv]

// ---------------- pack [Wq | Wkv] ----------------
__global__ void pack_w(const float* __restrict__ wq, const float* __restrict__ wkv,
                       float* __restrict__ w)
{
    int idx = blockIdx.x * 256 + threadIdx.x;
    if (idx >= DIM * NQKV) return;
    int k = idx / NQKV, c = idx % NQKV;
    w[idx] = (c < DIM) ? wq[k * DIM + c] : wkv[k * 1024 + (c - DIM)];
}

// ---------------- tf32 tensor-core GEMM ----------------
// C[M,N] = A[M,K] @ B[K,N] (+ bias). BM=128 BN=128 BK=16, 256 thr (8 warps 2x4),
// warp tile 64x32 via 4x4 m16n8k8 tf32 mma.

#define BM 128
#define BN 128
#define BK 16
#define ASTR 136   // 136 % 32 == 8 -> conflict-free fragment LDS
#define BSTR 136

__device__ __forceinline__ unsigned f2tf(float f) {
    unsigned u; asm("cvt.rna.tf32.f32 %0, %1;" : "=r"(u) : "f"(f)); return u;
}

template<bool BIAS>
__global__ void __launch_bounds__(256, 2)
gemm_tf32(const float* __restrict__ A, const float* __restrict__ B,
          const float* __restrict__ bias, float* __restrict__ C,
          int M, int N, int K)
{
    __shared__ unsigned As[BK][ASTR];   // [k][m]
    __shared__ unsigned Bs[BK][BSTR];   // [k][n]

    const int tid  = threadIdx.x;
    const int m0   = blockIdx.y * BM;
    const int n0   = blockIdx.x * BN;
    const int lane = tid & 31;
    const int wid  = tid >> 5;
    const int wm   = (wid & 1) * 64;
    const int wn   = (wid >> 1) * 32;
    const int lq   = lane & 3;        // k within fragment
    const int lr   = lane >> 2;       // row/col within fragment

    float acc[4][4][4];
#pragma unroll
    for (int i = 0; i < 4; i++)
#pragma unroll
        for (int j = 0; j < 4; j++)
#pragma unroll
            for (int c = 0; c < 4; c++) acc[i][j][c] = 0.f;

    for (int k0 = 0; k0 < K; k0 += BK) {
        // stage A: 128 rows x 16 k, transposed into As[k][m]
#pragma unroll
        for (int s = 0; s < 2; s++) {
            int idx = tid * 2 + s;              // 0..511
            int row = idx >> 2;                 // 0..127
            int kq  = (idx & 3) * 4;            // 0,4,8,12
            float4 v;
            if (m0 + row < M)
                v = *(const float4*)&A[(size_t)(m0 + row) * K + k0 + kq];
            else
                v = make_float4(0.f, 0.f, 0.f, 0.f);
            As[kq + 0][row] = f2tf(v.x);
            As[kq + 1][row] = f2tf(v.y);
            As[kq + 2][row] = f2tf(v.z);
            As[kq + 3][row] = f2tf(v.w);
        }
        // stage B: 16 k x 128 n
#pragma unroll
        for (int s = 0; s < 2; s++) {
            int idx = tid * 2 + s;              // 0..511
            int row = idx >> 5;                 // 0..15
            int col = (idx & 31) * 4;           // 0..124
            float4 v = *(const float4*)&B[(size_t)(k0 + row) * N + n0 + col];
            Bs[row][col + 0] = f2tf(v.x);
            Bs[row][col + 1] = f2tf(v.y);
            Bs[row][col + 2] = f2tf(v.z);
            Bs[row][col + 3] = f2tf(v.w);
        }
        __syncthreads();

#pragma unroll
        for (int ks = 0; ks < BK; ks += 8) {
            unsigned af[4][4], bf[4][2];
#pragma unroll
            for (int tm = 0; tm < 4; tm++) {
                int m = wm + tm * 16 + lr;
                af[tm][0] = As[ks + lq    ][m];
                af[tm][1] = As[ks + lq    ][m + 8];
                af[tm][2] = As[ks + lq + 4][m];
                af[tm][3] = As[ks + lq + 4][m + 8];
            }
#pragma unroll
            for (int tn = 0; tn < 4; tn++) {
                int n = wn + tn * 8 + lr;
                bf[tn][0] = Bs[ks + lq    ][n];
                bf[tn][1] = Bs[ks + lq + 4][n];
            }
#pragma unroll
            for (int tm = 0; tm < 4; tm++)
#pragma unroll
                for (int tn = 0; tn < 4; tn++) {
                    float* c = acc[tm][tn];
                    asm volatile(
                        "mma.sync.aligned.m16n8k8.row.col.f32.tf32.tf32.f32 "
                        "{%0,%1,%2,%3}, {%4,%5,%6,%7}, {%8,%9}, {%0,%1,%2,%3};\n"
                        : "+f"(c[0]), "+f"(c[1]), "+f"(c[2]), "+f"(c[3])
                        : "r"(af[tm][0]), "r"(af[tm][1]), "r"(af[tm][2]), "r"(af[tm][3]),
                          "r"(bf[tn][0]), "r"(bf[tn][1]));
                }
        }
        __syncthreads();
    }

    // epilogue
#pragma unroll
    for (int tm = 0; tm < 4; tm++) {
#pragma unroll
        for (int half = 0; half < 2; half++) {
            int row = m0 + wm + tm * 16 + lr + half * 8;
            if (row >= M) continue;
#pragma unroll
            for (int tn = 0; tn < 4; tn++) {
                int col = n0 + wn + tn * 8 + 2 * lq;
                float2 o;
                o.x = acc[tm][tn][half * 2 + 0];
                o.y = acc[tm][tn][half * 2 + 1];
                if (BIAS) { o.x += bias[col]; o.y += bias[col + 1]; }
                *(float2*)&C[(size_t)row * N + col] = o;
            }
        }
    }
}

// ---------------- chunked attention (round-2 validated, fused qkv input) -----
#define ATTN_SMEM_BYTES ((CTX*DH + CTX*KSTRIDE + CTX*DH) * 4 \
                         + TROWS * TSTRIDE * 2 + 8 * CTX * 4)

__global__ void __launch_bounds__(256)
attn_kernel(const float* __restrict__ QKV, const float* __restrict__ T,
            float* __restrict__ AO)
{
    extern __shared__ float sm[];
    float* qs = sm;                               // [CTX][64]
    float* ks = qs + CTX * DH;                    // [CTX][68]
    float* vs = ks + CTX * KSTRIDE;               // [CTX][64]
    __nv_bfloat16* ts = (__nv_bfloat16*)(vs + CTX * DH);  // [399][66]
    float* ps = (float*)(ts + TROWS * TSTRIDE);   // [8][CTX]

    const int b  = blockIdx.y;
    const int m  = blockIdx.x / HEADS;
    const int h  = blockIdx.x % HEADS;
    const int t0 = m * CTX;
    const int cv = (NTOK - t0 < CTX) ? (NTOK - t0) : CTX;
    const int tid = threadIdx.x;

    for (int idx = tid; idx < cv * 16; idx += 256) {
        const int i = idx >> 4;
        const int d = (idx & 15) * 4;
        const size_t base = (size_t)(b * NTOK + t0 + i) * NQKV + h * DH;
        float4 qv = *(const float4*)&QKV[base + d];
        *(float4*)&qs[i * DH + d] = qv;
        float4 kv4 = *(const float4*)&QKV[base + DIM + d];
        *(float4*)&ks[i * KSTRIDE + d] = kv4;
        float4 vv = *(const float4*)&QKV[base + 2 * DIM + d];
        *(float4*)&vs[i * DH + d] = vv;
    }
    for (int idx = tid; idx < TROWS * 32; idx += 256) {
        const int r  = idx >> 5;
        const int e2 = (idx & 31) * 2;
        float2 tv = *(const float2*)&T[(size_t)(TBASE + r) * DH + e2];
        ts[r * TSTRIDE + e2]     = __float2bfloat16(tv.x);
        ts[r * TSTRIDE + e2 + 1] = __float2bfloat16(tv.y);
    }
    __syncthreads();

    const int w    = tid >> 5;
    const int lane = tid & 31;
    float* p = ps + w * CTX;

    for (int i = w; i < cv; i += 8) {
        const float* qrow = &qs[i * DH];
        float lmax = -1e30f;
        for (int j = lane; j < cv; j += 32) {
            const float* krow = &ks[j * KSTRIDE];
            const __nv_bfloat16* trow = &ts[(i - j + CTX - 1) * TSTRIDE];
            float dot = 0.f, rdot = 0.f;
#pragma unroll
            for (int d = 0; d < DH; d += 4) {
                float4 q4 = *(const float4*)&qrow[d];
                float4 k4 = *(const float4*)&krow[d];
                __nv_bfloat162 t01 = *(const __nv_bfloat162*)&trow[d];
                __nv_bfloat162 t23 = *(const __nv_bfloat162*)&trow[d + 2];
                float2 f01 = __bfloat1622float2(t01);
                float2 f23 = __bfloat1622float2(t23);
                dot  += q4.x * k4.x + q4.y * k4.y + q4.z * k4.z + q4.w * k4.w;
                rdot += q4.x * f01.x + q4.y * f01.y + q4.z * f23.x + q4.w * f23.y;
            }
            float s = (dot + rdot) * 0.125f;
            p[j] = s;
            lmax = fmaxf(lmax, s);
        }
#pragma unroll
        for (int o = 16; o; o >>= 1) lmax = fmaxf(lmax, __shfl_xor_sync(~0u, lmax, o));
        __syncwarp();
        float lsum = 0.f;
        for (int j = lane; j < cv; j += 32) {
            float e = __expf(p[j] - lmax);
            p[j] = e;
            lsum += e;
        }
#pragma unroll
        for (int o = 16; o; o >>= 1) lsum += __shfl_xor_sync(~0u, lsum, o);
        const float inv = 1.f / lsum;
        __syncwarp();

        float acc0 = 0.f, acc1 = 0.f;
        const int d0 = lane, d1 = lane + 32;
        for (int j = 0; j < cv; j++) {
            float pj = p[j];
            acc0 += pj * vs[j * DH + d0];
            acc1 += pj * vs[j * DH + d1];
        }
        const size_t orow = (size_t)(b * NTOK + t0 + i) * DIM + h * DH;
        AO[orow + d0] = acc0 * inv;
        AO[orow + d1] = acc1 * inv;
        __syncwarp();
    }
}

// ---------------- launcher ----------------
extern "C" void kernel_launch(void* const* d_in, const int* in_sizes, int n_in,
                              void* d_out, int out_size)
{
    const float* x      = (const float*)d_in[0];
    const float* wq     = (const float*)d_in[1];
    const float* wkv    = (const float*)d_in[2];
    const float* wout_w = (const float*)d_in[3];
    const float* wout_b = (const float*)d_in[4];
    const float* rel    = (const float*)d_in[5];
    float* out = (float*)d_out;

    void *pqkv, *pao, *pw;
    cudaGetSymbolAddress(&pqkv, g_qkv);
    cudaGetSymbolAddress(&pao,  g_ao);
    cudaGetSymbolAddress(&pw,   g_w);

    cudaFuncSetAttribute(attn_kernel,
                         cudaFuncAttributeMaxDynamicSharedMemorySize,
                         ATTN_SMEM_BYTES);

    const int M = MROWS;
    dim3 blk(256);

    // pack fused weight [Wq | Wkv]
    pack_w<<<(DIM * NQKV + 255) / 256, 256>>>(wq, wkv, (float*)pw);

    // QKV = X @ [Wq|Wkv]
    dim3 gqkv(NQKV / BN, (M + BM - 1) / BM);
    gemm_tf32<false><<<gqkv, blk>>>(x, (const float*)pw, nullptr,
                                    (float*)pqkv, M, NQKV, DIM);

    // chunked attention
    attn_kernel<<<dim3(NB * HEADS, BS), blk, ATTN_SMEM_BYTES>>>(
        (const float*)pqkv, rel, (float*)pao);

    // out = AO @ Wout + b
    dim3 gout(DIM / BN, (M + BM - 1) / BM);
    gemm_tf32<true><<<gout, blk>>>((const float*)pao, wout_w, wout_b, out,
                                   M, DIM, DIM);
}

// round 5
// speedup vs baseline: 2.9930x; 2.1692x over previous
#include <cuda_runtime.h>
#include <cuda_bf16.h>

// ---------------- problem constants ----------------
#define BS    16
#define NTOK  3900
#define DIM   512
#define HEADS 8
#define DH    64
#define CTX   200
#define NB    20
#define MROWS (BS*NTOK)   // 62400
#define NQKV  1536        // fused q|k|v output width

// ---------------- scratch ----------------
__device__ float g_qkv[(size_t)MROWS * NQKV];   // 383 MB
__device__ float g_ao [(size_t)MROWS * DIM];    // 128 MB
__device__ float g_w  [DIM * NQKV];             // packed [Wq|Wkv]

// ---------------- pack [Wq | Wkv] ----------------
__global__ void pack_w(const float* __restrict__ wq, const float* __restrict__ wkv,
                       float* __restrict__ w)
{
    int idx = blockIdx.x * 256 + threadIdx.x;
    if (idx >= DIM * NQKV) return;
    int k = idx / NQKV, c = idx % NQKV;
    w[idx] = (c < DIM) ? wq[k * DIM + c] : wkv[k * 1024 + (c - DIM)];
}

__device__ __forceinline__ unsigned f2tf(float f) {
    unsigned u; asm("cvt.rna.tf32.f32 %0, %1;" : "=r"(u) : "f"(f)); return u;
}

__device__ __forceinline__ void mma_tf32(float* c, const unsigned* a,
                                         unsigned b0, unsigned b1)
{
    asm volatile(
        "mma.sync.aligned.m16n8k8.row.col.f32.tf32.tf32.f32 "
        "{%0,%1,%2,%3}, {%4,%5,%6,%7}, {%8,%9}, {%0,%1,%2,%3};\n"
        : "+f"(c[0]), "+f"(c[1]), "+f"(c[2]), "+f"(c[3])
        : "r"(a[0]), "r"(a[1]), "r"(a[2]), "r"(a[3]), "r"(b0), "r"(b1));
}

// ---------------- tf32 tensor-core GEMM (round-3 validated) ----------------
#define BM 128
#define BN 128
#define BK 16
#define ASTR 136
#define BSTR 136

template<bool BIAS>
__global__ void __launch_bounds__(256, 2)
gemm_tf32(const float* __restrict__ A, const float* __restrict__ B,
          const float* __restrict__ bias, float* __restrict__ C,
          int M, int N, int K)
{
    __shared__ unsigned As[BK][ASTR];
    __shared__ unsigned Bs[BK][BSTR];

    const int tid  = threadIdx.x;
    const int m0   = blockIdx.y * BM;
    const int n0   = blockIdx.x * BN;
    const int lane = tid & 31;
    const int wid  = tid >> 5;
    const int wm   = (wid & 1) * 64;
    const int wn   = (wid >> 1) * 32;
    const int lq   = lane & 3;
    const int lr   = lane >> 2;

    float acc[4][4][4];
#pragma unroll
    for (int i = 0; i < 4; i++)
#pragma unroll
        for (int j = 0; j < 4; j++)
#pragma unroll
            for (int c = 0; c < 4; c++) acc[i][j][c] = 0.f;

    for (int k0 = 0; k0 < K; k0 += BK) {
#pragma unroll
        for (int s = 0; s < 2; s++) {
            int idx = tid * 2 + s;
            int row = idx >> 2;
            int kq  = (idx & 3) * 4;
            float4 v;
            if (m0 + row < M)
                v = *(const float4*)&A[(size_t)(m0 + row) * K + k0 + kq];
            else
                v = make_float4(0.f, 0.f, 0.f, 0.f);
            As[kq + 0][row] = f2tf(v.x);
            As[kq + 1][row] = f2tf(v.y);
            As[kq + 2][row] = f2tf(v.z);
            As[kq + 3][row] = f2tf(v.w);
        }
#pragma unroll
        for (int s = 0; s < 2; s++) {
            int idx = tid * 2 + s;
            int row = idx >> 5;
            int col = (idx & 31) * 4;
            float4 v = *(const float4*)&B[(size_t)(k0 + row) * N + n0 + col];
            Bs[row][col + 0] = f2tf(v.x);
            Bs[row][col + 1] = f2tf(v.y);
            Bs[row][col + 2] = f2tf(v.z);
            Bs[row][col + 3] = f2tf(v.w);
        }
        __syncthreads();

#pragma unroll
        for (int ks = 0; ks < BK; ks += 8) {
            unsigned af[4][4], bf[4][2];
#pragma unroll
            for (int tm = 0; tm < 4; tm++) {
                int m = wm + tm * 16 + lr;
                af[tm][0] = As[ks + lq    ][m];
                af[tm][1] = As[ks + lq    ][m + 8];
                af[tm][2] = As[ks + lq + 4][m];
                af[tm][3] = As[ks + lq + 4][m + 8];
            }
#pragma unroll
            for (int tn = 0; tn < 4; tn++) {
                int n = wn + tn * 8 + lr;
                bf[tn][0] = Bs[ks + lq    ][n];
                bf[tn][1] = Bs[ks + lq + 4][n];
            }
#pragma unroll
            for (int tm = 0; tm < 4; tm++)
#pragma unroll
                for (int tn = 0; tn < 4; tn++)
                    mma_tf32(acc[tm][tn], af[tm], bf[tn][0], bf[tn][1]);
        }
        __syncthreads();
    }

#pragma unroll
    for (int tm = 0; tm < 4; tm++) {
#pragma unroll
        for (int half = 0; half < 2; half++) {
            int row = m0 + wm + tm * 16 + lr + half * 8;
            if (row >= M) continue;
#pragma unroll
            for (int tn = 0; tn < 4; tn++) {
                int col = n0 + wn + tn * 8 + 2 * lq;
                float2 o;
                o.x = acc[tm][tn][half * 2 + 0];
                o.y = acc[tm][tn][half * 2 + 1];
                if (BIAS) { o.x += bias[col]; o.y += bias[col + 1]; }
                *(float2*)&C[(size_t)row * N + col] = o;
            }
        }
    }
}

// ---------------- tensor-core chunked attention ------------------------------
// block = (b, chunk, head), 8 warps; each warp owns 16-row i-tiles.
// smem: K tf32 [208][68] | V^T tf32 [64][212] | per-warp E/P buf f32 [16][220]

#define KS2 68
#define VS2 212
#define AEB 220
#define ATTN_SMEM ((208*KS2 + 64*VS2 + 8*16*AEB) * 4)   // 223488 bytes

__global__ void __launch_bounds__(256, 1)
attn_mma(const float* __restrict__ QKV, const float* __restrict__ T,
         float* __restrict__ AO)
{
    extern __shared__ unsigned smu[];
    unsigned* ksm = smu;                       // [208][KS2]
    unsigned* vsm = ksm + 208 * KS2;           // [64][VS2]
    float* ebase  = (float*)(vsm + 64 * VS2);  // [8][16][AEB]

    const int b   = blockIdx.y;
    const int m   = blockIdx.x / HEADS;
    const int h   = blockIdx.x % HEADS;
    const int t0  = m * CTX;
    const int cv  = (NTOK - t0 < CTX) ? (NTOK - t0) : CTX;
    const int tid = threadIdx.x;
    const int w   = tid >> 5, lane = tid & 31;
    const int lr  = lane >> 2, lq = lane & 3;

    // ---- stage K as tf32, rows >= cv zeroed ----
    for (int idx = tid; idx < 208 * 16; idx += 256) {
        int i = idx >> 4, d = (idx & 15) * 4;
        if (i < cv) {
            const float* p = &QKV[(size_t)(b*NTOK + t0 + i)*NQKV + DIM + h*DH + d];
            float4 v = *(const float4*)p;
            ksm[i*KS2 + d]     = f2tf(v.x);
            ksm[i*KS2 + d + 1] = f2tf(v.y);
            ksm[i*KS2 + d + 2] = f2tf(v.z);
            ksm[i*KS2 + d + 3] = f2tf(v.w);
        } else {
            ksm[i*KS2 + d] = ksm[i*KS2 + d+1] = ksm[i*KS2 + d+2] = ksm[i*KS2 + d+3] = 0u;
        }
    }
    // ---- stage V transposed [d][j], cols >= cv zeroed ----
    for (int idx = tid; idx < 208 * 64; idx += 256) {
        int j = idx >> 6, d = idx & 63;
        unsigned v = 0u;
        if (j < cv)
            v = f2tf(QKV[(size_t)(b*NTOK + t0 + j)*NQKV + 2*DIM + h*DH + d]);
        vsm[d*VS2 + j] = v;
    }
    __syncthreads();

    float* E0 = ebase + w * 16 * AEB;

    for (int it = w; it * 16 < cv; it += 8) {
        const int i0 = it * 16;
        const int r0 = i0 + lr, r1 = r0 + 8;
        const bool v0 = r0 < cv, v1 = r1 < cv;
        float* Ea = E0 + lr * AEB;
        float* Eb = E0 + (lr + 8) * AEB;

        // ---- Q fragments, prescaled by dh^-0.5 ----
        unsigned aq[8][4];
        {
            const float* q0 = &QKV[(size_t)(b*NTOK + t0 + r0)*NQKV + h*DH + lq];
            const float* q1 = &QKV[(size_t)(b*NTOK + t0 + r1)*NQKV + h*DH + lq];
#pragma unroll
            for (int kt = 0; kt < 8; kt++) {
                aq[kt][0] = v0 ? f2tf(0.125f * q0[kt*8])     : 0u;
                aq[kt][1] = v1 ? f2tf(0.125f * q1[kt*8])     : 0u;
                aq[kt][2] = v0 ? f2tf(0.125f * q0[kt*8 + 4]) : 0u;
                aq[kt][3] = v1 ? f2tf(0.125f * q1[kt*8 + 4]) : 0u;
            }
        }

        // ---- E[16][216] = Q @ T^T (table rows i0 .. i0+215) ----
#pragma unroll 1
        for (int rt = 0; rt < 27; rt++) {
            float ec[4] = {0.f, 0.f, 0.f, 0.f};
            int rg = i0 + rt * 8 + lr;                 // r_global = i-j+199 index
            const float* trow = &T[(size_t)(rg + 313) * DH + lq];
            bool tv = rg <= 398;
#pragma unroll
            for (int kt = 0; kt < 8; kt++) {
                unsigned b0 = tv ? f2tf(trow[kt*8])     : 0u;
                unsigned b1 = tv ? f2tf(trow[kt*8 + 4]) : 0u;
                mma_tf32(ec, aq[kt], b0, b1);
            }
            int c0 = rt * 8 + 2 * lq;
            Ea[c0]     = ec[0];
            Ea[c0 + 1] = ec[1];
            Eb[c0]     = ec[2];
            Eb[c0 + 1] = ec[3];
        }
        __syncwarp();

        // ---- S = Q @ K^T (25 n-tiles of 8 cols) ----
        float s[25][4];
#pragma unroll
        for (int nt = 0; nt < 25; nt++)
            s[nt][0] = s[nt][1] = s[nt][2] = s[nt][3] = 0.f;
#pragma unroll
        for (int kt = 0; kt < 8; kt++) {
#pragma unroll
            for (int nt = 0; nt < 25; nt++) {
                unsigned b0 = ksm[(nt*8 + lr)*KS2 + kt*8 + lq];
                unsigned b1 = ksm[(nt*8 + lr)*KS2 + kt*8 + lq + 4];
                mma_tf32(s[nt], aq[kt], b0, b1);
            }
        }

        // ---- bias gather + mask + row max ----
        float mx0 = -1e30f, mx1 = -1e30f;
#pragma unroll
        for (int nt = 0; nt < 25; nt++) {
            int j0 = nt * 8 + 2 * lq;
#pragma unroll
            for (int e = 0; e < 2; e++) {
                int j = j0 + e;
                float a0 = s[nt][e]     + Ea[lr     + 199 - j];
                float a1 = s[nt][2 + e] + Eb[lr + 8 + 199 - j];
                if (j >= cv) { a0 = -1e30f; a1 = -1e30f; }
                s[nt][e] = a0; s[nt][2 + e] = a1;
                mx0 = fmaxf(mx0, a0); mx1 = fmaxf(mx1, a1);
            }
        }
        mx0 = fmaxf(mx0, __shfl_xor_sync(~0u, mx0, 1));
        mx0 = fmaxf(mx0, __shfl_xor_sync(~0u, mx0, 2));
        mx1 = fmaxf(mx1, __shfl_xor_sync(~0u, mx1, 1));
        mx1 = fmaxf(mx1, __shfl_xor_sync(~0u, mx1, 2));

        float sum0 = 0.f, sum1 = 0.f;
#pragma unroll
        for (int nt = 0; nt < 25; nt++) {
#pragma unroll
            for (int e = 0; e < 2; e++) {
                float p0 = __expf(s[nt][e]     - mx0);
                float p1 = __expf(s[nt][2 + e] - mx1);
                s[nt][e] = p0; s[nt][2 + e] = p1;
                sum0 += p0; sum1 += p1;
            }
        }
        sum0 += __shfl_xor_sync(~0u, sum0, 1);
        sum0 += __shfl_xor_sync(~0u, sum0, 2);
        sum1 += __shfl_xor_sync(~0u, sum1, 1);
        sum1 += __shfl_xor_sync(~0u, sum1, 2);
        const float inv0 = 1.f / sum0, inv1 = 1.f / sum1;

        __syncwarp();   // all E reads done before overwriting with P

        // ---- P (unnormalized exp, tf32) into the E buffer ----
        unsigned* Pa = (unsigned*)Ea;
        unsigned* Pb = (unsigned*)Eb;
#pragma unroll
        for (int nt = 0; nt < 25; nt++) {
            int j0 = nt * 8 + 2 * lq;
            Pa[j0]     = f2tf(s[nt][0]);
            Pa[j0 + 1] = f2tf(s[nt][1]);
            Pb[j0]     = f2tf(s[nt][2]);
            Pb[j0 + 1] = f2tf(s[nt][3]);
        }
        unsigned* P = (unsigned*)E0;
        for (int z = lane; z < 128; z += 32)               // zero cols 200..207
            P[(z >> 3)*AEB + 200 + (z & 7)] = 0u;
        __syncwarp();

        // ---- O = P @ V (k = 208, n = 64) ----
        float o[8][4];
#pragma unroll
        for (int nt = 0; nt < 8; nt++)
            o[nt][0] = o[nt][1] = o[nt][2] = o[nt][3] = 0.f;
#pragma unroll 1
        for (int kt = 0; kt < 26; kt++) {
            unsigned pa[4];
            pa[0] = P[lr*AEB     + kt*8 + lq];
            pa[1] = P[(lr+8)*AEB + kt*8 + lq];
            pa[2] = P[lr*AEB     + kt*8 + lq + 4];
            pa[3] = P[(lr+8)*AEB + kt*8 + lq + 4];
#pragma unroll
            for (int nt = 0; nt < 8; nt++) {
                unsigned b0 = vsm[(nt*8 + lr)*VS2 + kt*8 + lq];
                unsigned b1 = vsm[(nt*8 + lr)*VS2 + kt*8 + lq + 4];
                mma_tf32(o[nt], pa, b0, b1);
            }
        }

        // ---- write O (normalized) ----
#pragma unroll
        for (int nt = 0; nt < 8; nt++) {
            int col = h*DH + nt*8 + 2*lq;
            if (v0) {
                float2 t2 = make_float2(o[nt][0]*inv0, o[nt][1]*inv0);
                *(float2*)&AO[(size_t)(b*NTOK + t0 + r0)*DIM + col] = t2;
            }
            if (v1) {
                float2 t2 = make_float2(o[nt][2]*inv1, o[nt][3]*inv1);
                *(float2*)&AO[(size_t)(b*NTOK + t0 + r1)*DIM + col] = t2;
            }
        }
        __syncwarp();   // P buffer reused as E next i-tile
    }
}

// ---------------- launcher ----------------
extern "C" void kernel_launch(void* const* d_in, const int* in_sizes, int n_in,
                              void* d_out, int out_size)
{
    const float* x      = (const float*)d_in[0];
    const float* wq     = (const float*)d_in[1];
    const float* wkv    = (const float*)d_in[2];
    const float* wout_w = (const float*)d_in[3];
    const float* wout_b = (const float*)d_in[4];
    const float* rel    = (const float*)d_in[5];
    float* out = (float*)d_out;

    void *pqkv, *pao, *pw;
    cudaGetSymbolAddress(&pqkv, g_qkv);
    cudaGetSymbolAddress(&pao,  g_ao);
    cudaGetSymbolAddress(&pw,   g_w);

    cudaFuncSetAttribute(attn_mma,
                         cudaFuncAttributeMaxDynamicSharedMemorySize,
                         ATTN_SMEM);

    const int M = MROWS;
    dim3 blk(256);

    pack_w<<<(DIM * NQKV + 255) / 256, 256>>>(wq, wkv, (float*)pw);

    dim3 gqkv(NQKV / BN, (M + BM - 1) / BM);
    gemm_tf32<false><<<gqkv, blk>>>(x, (const float*)pw, nullptr,
                                    (float*)pqkv, M, NQKV, DIM);

    attn_mma<<<dim3(NB * HEADS, BS), blk, ATTN_SMEM>>>(
        (const float*)pqkv, rel, (float*)pao);

    dim3 gout(DIM / BN, (M + BM - 1) / BM);
    gemm_tf32<true><<<gout, blk>>>((const float*)pao, wout_w, wout_b, out,
                                   M, DIM, DIM);
}

// round 6
// speedup vs baseline: 3.2694x; 1.0923x over previous
#include <cuda_runtime.h>
#include <cuda_bf16.h>

// ---------------- problem constants ----------------
#define BS    16
#define NTOK  3900
#define DIM   512
#define HEADS 8
#define DH    64
#define CTX   200
#define NB    20
#define MROWS (BS*NTOK)   // 62400
#define NQKV  1536        // fused q|k|v output width

// ---------------- scratch ----------------
__device__ float g_qkv[(size_t)MROWS * NQKV];   // 383 MB
__device__ float g_ao [(size_t)MROWS * DIM];    // 128 MB
__device__ float g_w  [DIM * NQKV];             // packed [Wq|Wkv]

// ---------------- pack [Wq | Wkv] ----------------
__global__ void pack_w(const float* __restrict__ wq, const float* __restrict__ wkv,
                       float* __restrict__ w)
{
    int idx = blockIdx.x * 256 + threadIdx.x;
    if (idx >= DIM * NQKV) return;
    int k = idx / NQKV, c = idx % NQKV;
    w[idx] = (c < DIM) ? wq[k * DIM + c] : wkv[k * 1024 + (c - DIM)];
}

__device__ __forceinline__ unsigned f2tf(float f) {
    unsigned u; asm("cvt.rna.tf32.f32 %0, %1;" : "=r"(u) : "f"(f)); return u;
}

__device__ __forceinline__ void mma_tf32(float* c, const unsigned* a,
                                         unsigned b0, unsigned b1)
{
    asm volatile(
        "mma.sync.aligned.m16n8k8.row.col.f32.tf32.tf32.f32 "
        "{%0,%1,%2,%3}, {%4,%5,%6,%7}, {%8,%9}, {%0,%1,%2,%3};\n"
        : "+f"(c[0]), "+f"(c[1]), "+f"(c[2]), "+f"(c[3])
        : "r"(a[0]), "r"(a[1]), "r"(a[2]), "r"(a[3]), "r"(b0), "r"(b1));
}

__device__ __forceinline__ void cp16(unsigned dst, const void* src, bool pred) {
    int sz = pred ? 16 : 0;
    asm volatile("cp.async.cg.shared.global [%0], [%1], 16, %2;\n"
                 :: "r"(dst), "l"(src), "r"(sz));
}

// ---------------- pipelined tf32 tensor-core GEMM ----------------
// C[M,N] = A[M,K] @ B[K,N] (+bias). BM=128 BN=128 BK=16, 4-stage cp.async.
// A staged row-major [m][k] stride 20 (conflict-free frag LDS);
// B staged [k][n] stride 136. Raw fp32 bits -> mma.tf32 (hw truncation).

#define BM 128
#define BN 128
#define BK 16
#define NSTAGE 4
#define ASTR2 20
#define BSTR 136
#define A_TILE_U32 (BM * ASTR2)          // 2560
#define B_TILE_U32 (BK * BSTR)           // 2176
#define GEMM_SMEM ((NSTAGE * (A_TILE_U32 + B_TILE_U32)) * 4)  // 75776 B

template<bool BIAS>
__global__ void __launch_bounds__(256, 2)
gemm_tf32(const float* __restrict__ A, const float* __restrict__ B,
          const float* __restrict__ bias, float* __restrict__ C,
          int M, int N, int K)
{
    extern __shared__ unsigned gsm[];
    unsigned* As = gsm;                          // [NSTAGE][BM][ASTR2]
    unsigned* Bs = gsm + NSTAGE * A_TILE_U32;    // [NSTAGE][BK][BSTR]

    const int tid  = threadIdx.x;
    const int m0   = blockIdx.y * BM;
    const int n0   = blockIdx.x * BN;
    const int lane = tid & 31;
    const int wid  = tid >> 5;
    const int wm   = (wid & 1) * 64;
    const int wn   = (wid >> 1) * 32;
    const int lq   = lane & 3;
    const int lr   = lane >> 2;

    const unsigned aBase = (unsigned)__cvta_generic_to_shared(As);
    const unsigned bBase = (unsigned)__cvta_generic_to_shared(Bs);

    // per-thread copy coordinates (2 x 16B chunks each for A and B)
    const int a_row0 = (tid * 2)     >> 2, a_ch0 = (tid * 2)     & 3;
    const int a_row1 = (tid * 2 + 1) >> 2, a_ch1 = (tid * 2 + 1) & 3;
    const int b_row0 = (tid * 2)     >> 5, b_ch0 = (tid * 2)     & 31;
    const int b_row1 = (tid * 2 + 1) >> 5, b_ch1 = (tid * 2 + 1) & 31;

    auto loadA = [&](int st, int k0) {
        bool v0 = (m0 + a_row0) < M;
        bool v1 = (m0 + a_row1) < M;
        cp16(aBase + (st * A_TILE_U32 + a_row0 * ASTR2 + a_ch0 * 4) * 4,
             v0 ? &A[(size_t)(m0 + a_row0) * K + k0 + a_ch0 * 4] : (const void*)A, v0);
        cp16(aBase + (st * A_TILE_U32 + a_row1 * ASTR2 + a_ch1 * 4) * 4,
             v1 ? &A[(size_t)(m0 + a_row1) * K + k0 + a_ch1 * 4] : (const void*)A, v1);
    };
    auto loadB = [&](int st, int k0) {
        cp16(bBase + (st * B_TILE_U32 + b_row0 * BSTR + b_ch0 * 4) * 4,
             &B[(size_t)(k0 + b_row0) * N + n0 + b_ch0 * 4], true);
        cp16(bBase + (st * B_TILE_U32 + b_row1 * BSTR + b_ch1 * 4) * 4,
             &B[(size_t)(k0 + b_row1) * N + n0 + b_ch1 * 4], true);
    };

    float acc[4][4][4];
#pragma unroll
    for (int i = 0; i < 4; i++)
#pragma unroll
        for (int j = 0; j < 4; j++)
#pragma unroll
            for (int c = 0; c < 4; c++) acc[i][j][c] = 0.f;

    const int KT = K / BK;

    // prologue: fill NSTAGE-1 stages
#pragma unroll
    for (int st = 0; st < NSTAGE - 1; st++) {
        loadA(st, st * BK);
        loadB(st, st * BK);
        asm volatile("cp.async.commit_group;\n");
    }

    for (int it = 0; it < KT; it++) {
        asm volatile("cp.async.wait_group %0;\n" :: "n"(NSTAGE - 2));
        __syncthreads();

        int pf = it + NSTAGE - 1;
        if (pf < KT) {
            loadA(pf & (NSTAGE - 1), pf * BK);
            loadB(pf & (NSTAGE - 1), pf * BK);
        }
        asm volatile("cp.async.commit_group;\n");

        const unsigned* Ast = As + (it & (NSTAGE - 1)) * A_TILE_U32;
        const unsigned* Bst = Bs + (it & (NSTAGE - 1)) * B_TILE_U32;

#pragma unroll
        for (int ks = 0; ks < BK; ks += 8) {
            unsigned af[4][4], bf[4][2];
#pragma unroll
            for (int tm = 0; tm < 4; tm++) {
                int m = wm + tm * 16 + lr;
                af[tm][0] = Ast[m * ASTR2 + ks + lq];
                af[tm][1] = Ast[(m + 8) * ASTR2 + ks + lq];
                af[tm][2] = Ast[m * ASTR2 + ks + lq + 4];
                af[tm][3] = Ast[(m + 8) * ASTR2 + ks + lq + 4];
            }
#pragma unroll
            for (int tn = 0; tn < 4; tn++) {
                int n = wn + tn * 8 + lr;
                bf[tn][0] = Bst[(ks + lq) * BSTR + n];
                bf[tn][1] = Bst[(ks + lq + 4) * BSTR + n];
            }
#pragma unroll
            for (int tm = 0; tm < 4; tm++)
#pragma unroll
                for (int tn = 0; tn < 4; tn++)
                    mma_tf32(acc[tm][tn], af[tm], bf[tn][0], bf[tn][1]);
        }
    }

    // epilogue
#pragma unroll
    for (int tm = 0; tm < 4; tm++) {
#pragma unroll
        for (int half = 0; half < 2; half++) {
            int row = m0 + wm + tm * 16 + lr + half * 8;
            if (row >= M) continue;
#pragma unroll
            for (int tn = 0; tn < 4; tn++) {
                int col = n0 + wn + tn * 8 + 2 * lq;
                float2 o;
                o.x = acc[tm][tn][half * 2 + 0];
                o.y = acc[tm][tn][half * 2 + 1];
                if (BIAS) { o.x += bias[col]; o.y += bias[col + 1]; }
                *(float2*)&C[(size_t)row * N + col] = o;
            }
        }
    }
}

// ---------------- tensor-core chunked attention (round-5 validated) ----------
#define KS2 68
#define VS2 212
#define AEB 220
#define ATTN_SMEM ((208*KS2 + 64*VS2 + 8*16*AEB) * 4)   // 223488 bytes

__global__ void __launch_bounds__(256, 1)
attn_mma(const float* __restrict__ QKV, const float* __restrict__ T,
         float* __restrict__ AO)
{
    extern __shared__ unsigned smu[];
    unsigned* ksm = smu;                       // [208][KS2]
    unsigned* vsm = ksm + 208 * KS2;           // [64][VS2]
    float* ebase  = (float*)(vsm + 64 * VS2);  // [8][16][AEB]

    const int b   = blockIdx.y;
    const int m   = blockIdx.x / HEADS;
    const int h   = blockIdx.x % HEADS;
    const int t0  = m * CTX;
    const int cv  = (NTOK - t0 < CTX) ? (NTOK - t0) : CTX;
    const int tid = threadIdx.x;
    const int w   = tid >> 5, lane = tid & 31;
    const int lr  = lane >> 2, lq = lane & 3;

    for (int idx = tid; idx < 208 * 16; idx += 256) {
        int i = idx >> 4, d = (idx & 15) * 4;
        if (i < cv) {
            const float* p = &QKV[(size_t)(b*NTOK + t0 + i)*NQKV + DIM + h*DH + d];
            float4 v = *(const float4*)p;
            ksm[i*KS2 + d]     = f2tf(v.x);
            ksm[i*KS2 + d + 1] = f2tf(v.y);
            ksm[i*KS2 + d + 2] = f2tf(v.z);
            ksm[i*KS2 + d + 3] = f2tf(v.w);
        } else {
            ksm[i*KS2 + d] = ksm[i*KS2 + d+1] = ksm[i*KS2 + d+2] = ksm[i*KS2 + d+3] = 0u;
        }
    }
    for (int idx = tid; idx < 208 * 64; idx += 256) {
        int j = idx >> 6, d = idx & 63;
        unsigned v = 0u;
        if (j < cv)
            v = f2tf(QKV[(size_t)(b*NTOK + t0 + j)*NQKV + 2*DIM + h*DH + d]);
        vsm[d*VS2 + j] = v;
    }
    __syncthreads();

    float* E0 = ebase + w * 16 * AEB;

    for (int it = w; it * 16 < cv; it += 8) {
        const int i0 = it * 16;
        const int r0 = i0 + lr, r1 = r0 + 8;
        const bool v0 = r0 < cv, v1 = r1 < cv;
        float* Ea = E0 + lr * AEB;
        float* Eb = E0 + (lr + 8) * AEB;

        unsigned aq[8][4];
        {
            const float* q0 = &QKV[(size_t)(b*NTOK + t0 + r0)*NQKV + h*DH + lq];
            const float* q1 = &QKV[(size_t)(b*NTOK + t0 + r1)*NQKV + h*DH + lq];
#pragma unroll
            for (int kt = 0; kt < 8; kt++) {
                aq[kt][0] = v0 ? f2tf(0.125f * q0[kt*8])     : 0u;
                aq[kt][1] = v1 ? f2tf(0.125f * q1[kt*8])     : 0u;
                aq[kt][2] = v0 ? f2tf(0.125f * q0[kt*8 + 4]) : 0u;
                aq[kt][3] = v1 ? f2tf(0.125f * q1[kt*8 + 4]) : 0u;
            }
        }

#pragma unroll 1
        for (int rt = 0; rt < 27; rt++) {
            float ec[4] = {0.f, 0.f, 0.f, 0.f};
            int rg = i0 + rt * 8 + lr;
            const float* trow = &T[(size_t)(rg + 313) * DH + lq];
            bool tv = rg <= 398;
#pragma unroll
            for (int kt = 0; kt < 8; kt++) {
                unsigned b0 = tv ? f2tf(trow[kt*8])     : 0u;
                unsigned b1 = tv ? f2tf(trow[kt*8 + 4]) : 0u;
                mma_tf32(ec, aq[kt], b0, b1);
            }
            int c0 = rt * 8 + 2 * lq;
            Ea[c0]     = ec[0];
            Ea[c0 + 1] = ec[1];
            Eb[c0]     = ec[2];
            Eb[c0 + 1] = ec[3];
        }
        __syncwarp();

        float s[25][4];
#pragma unroll
        for (int nt = 0; nt < 25; nt++)
            s[nt][0] = s[nt][1] = s[nt][2] = s[nt][3] = 0.f;
#pragma unroll
        for (int kt = 0; kt < 8; kt++) {
#pragma unroll
            for (int nt = 0; nt < 25; nt++) {
                unsigned b0 = ksm[(nt*8 + lr)*KS2 + kt*8 + lq];
                unsigned b1 = ksm[(nt*8 + lr)*KS2 + kt*8 + lq + 4];
                mma_tf32(s[nt], aq[kt], b0, b1);
            }
        }

        float mx0 = -1e30f, mx1 = -1e30f;
#pragma unroll
        for (int nt = 0; nt < 25; nt++) {
            int j0 = nt * 8 + 2 * lq;
#pragma unroll
            for (int e = 0; e < 2; e++) {
                int j = j0 + e;
                float a0 = s[nt][e]     + Ea[lr     + 199 - j];
                float a1 = s[nt][2 + e] + Eb[lr + 8 + 199 - j];
                if (j >= cv) { a0 = -1e30f; a1 = -1e30f; }
                s[nt][e] = a0; s[nt][2 + e] = a1;
                mx0 = fmaxf(mx0, a0); mx1 = fmaxf(mx1, a1);
            }
        }
        mx0 = fmaxf(mx0, __shfl_xor_sync(~0u, mx0, 1));
        mx0 = fmaxf(mx0, __shfl_xor_sync(~0u, mx0, 2));
        mx1 = fmaxf(mx1, __shfl_xor_sync(~0u, mx1, 1));
        mx1 = fmaxf(mx1, __shfl_xor_sync(~0u, mx1, 2));

        float sum0 = 0.f, sum1 = 0.f;
#pragma unroll
        for (int nt = 0; nt < 25; nt++) {
#pragma unroll
            for (int e = 0; e < 2; e++) {
                float p0 = __expf(s[nt][e]     - mx0);
                float p1 = __expf(s[nt][2 + e] - mx1);
                s[nt][e] = p0; s[nt][2 + e] = p1;
                sum0 += p0; sum1 += p1;
            }
        }
        sum0 += __shfl_xor_sync(~0u, sum0, 1);
        sum0 += __shfl_xor_sync(~0u, sum0, 2);
        sum1 += __shfl_xor_sync(~0u, sum1, 1);
        sum1 += __shfl_xor_sync(~0u, sum1, 2);
        const float inv0 = 1.f / sum0, inv1 = 1.f / sum1;

        __syncwarp();

        unsigned* Pa = (unsigned*)Ea;
        unsigned* Pb = (unsigned*)Eb;
#pragma unroll
        for (int nt = 0; nt < 25; nt++) {
            int j0 = nt * 8 + 2 * lq;
            Pa[j0]     = f2tf(s[nt][0]);
            Pa[j0 + 1] = f2tf(s[nt][1]);
            Pb[j0]     = f2tf(s[nt][2]);
            Pb[j0 + 1] = f2tf(s[nt][3]);
        }
        unsigned* P = (unsigned*)E0;
        for (int z = lane; z < 128; z += 32)
            P[(z >> 3)*AEB + 200 + (z & 7)] = 0u;
        __syncwarp();

        float o[8][4];
#pragma unroll
        for (int nt = 0; nt < 8; nt++)
            o[nt][0] = o[nt][1] = o[nt][2] = o[nt][3] = 0.f;
#pragma unroll 1
        for (int kt = 0; kt < 26; kt++) {
            unsigned pa[4];
            pa[0] = P[lr*AEB     + kt*8 + lq];
            pa[1] = P[(lr+8)*AEB + kt*8 + lq];
            pa[2] = P[lr*AEB     + kt*8 + lq + 4];
            pa[3] = P[(lr+8)*AEB + kt*8 + lq + 4];
#pragma unroll
            for (int nt = 0; nt < 8; nt++) {
                unsigned b0 = vsm[(nt*8 + lr)*VS2 + kt*8 + lq];
                unsigned b1 = vsm[(nt*8 + lr)*VS2 + kt*8 + lq + 4];
                mma_tf32(o[nt], pa, b0, b1);
            }
        }

#pragma unroll
        for (int nt = 0; nt < 8; nt++) {
            int col = h*DH + nt*8 + 2*lq;
            if (v0) {
                float2 t2 = make_float2(o[nt][0]*inv0, o[nt][1]*inv0);
                *(float2*)&AO[(size_t)(b*NTOK + t0 + r0)*DIM + col] = t2;
            }
            if (v1) {
                float2 t2 = make_float2(o[nt][2]*inv1, o[nt][3]*inv1);
                *(float2*)&AO[(size_t)(b*NTOK + t0 + r1)*DIM + col] = t2;
            }
        }
        __syncwarp();
    }
}

// ---------------- launcher ----------------
extern "C" void kernel_launch(void* const* d_in, const int* in_sizes, int n_in,
                              void* d_out, int out_size)
{
    const float* x      = (const float*)d_in[0];
    const float* wq     = (const float*)d_in[1];
    const float* wkv    = (const float*)d_in[2];
    const float* wout_w = (const float*)d_in[3];
    const float* wout_b = (const float*)d_in[4];
    const float* rel    = (const float*)d_in[5];
    float* out = (float*)d_out;

    void *pqkv, *pao, *pw;
    cudaGetSymbolAddress(&pqkv, g_qkv);
    cudaGetSymbolAddress(&pao,  g_ao);
    cudaGetSymbolAddress(&pw,   g_w);

    cudaFuncSetAttribute(attn_mma,
                         cudaFuncAttributeMaxDynamicSharedMemorySize, ATTN_SMEM);
    cudaFuncSetAttribute(gemm_tf32<false>,
                         cudaFuncAttributeMaxDynamicSharedMemorySize, GEMM_SMEM);
    cudaFuncSetAttribute(gemm_tf32<true>,
                         cudaFuncAttributeMaxDynamicSharedMemorySize, GEMM_SMEM);

    const int M = MROWS;
    dim3 blk(256);

    pack_w<<<(DIM * NQKV + 255) / 256, 256>>>(wq, wkv, (float*)pw);

    dim3 gqkv(NQKV / BN, (M + BM - 1) / BM);
    gemm_tf32<false><<<gqkv, blk, GEMM_SMEM>>>(x, (const float*)pw, nullptr,
                                               (float*)pqkv, M, NQKV, DIM);

    attn_mma<<<dim3(NB * HEADS, BS), blk, ATTN_SMEM>>>(
        (const float*)pqkv, rel, (float*)pao);

    dim3 gout(DIM / BN, (M + BM - 1) / BM);
    gemm_tf32<true><<<gout, blk, GEMM_SMEM>>>((const float*)pao, wout_w, wout_b,
                                              out, M, DIM, DIM);
}

// round 7
// speedup vs baseline: 3.6114x; 1.1046x over previous
#include <cuda_runtime.h>
#include <cuda_bf16.h>

// ---------------- problem constants ----------------
#define BS    16
#define NTOK  3900
#define DIM   512
#define HEADS 8
#define DH    64
#define CTX   200
#define NB    20
#define MROWS (BS*NTOK)   // 62400
#define NQKV  1536        // fused q|k|v output width

// ---------------- scratch ----------------
__device__ float g_qkv[(size_t)MROWS * NQKV];   // 383 MB
__device__ float g_ao [(size_t)MROWS * DIM];    // 128 MB
__device__ float g_x  [(size_t)MROWS * DIM];    // 128 MB (tf32-rounded X)
__device__ float g_w  [DIM * NQKV];             // packed tf32 [Wq|Wkv]
__device__ float g_wo [DIM * DIM];              // tf32 Wout

__device__ __forceinline__ unsigned f2tf(float f) {
    unsigned u; asm("cvt.rna.tf32.f32 %0, %1;" : "=r"(u) : "f"(f)); return u;
}
__device__ __forceinline__ float f2tf_f(float f) {
    return __uint_as_float(f2tf(f));
}

// ---------------- rounding / packing kernels ----------------
__global__ void round_x(const float* __restrict__ x, float* __restrict__ y)
{
    size_t i = ((size_t)blockIdx.x * 256 + threadIdx.x) * 4;
    if (i >= (size_t)MROWS * DIM) return;
    float4 v = *(const float4*)&x[i];
    v.x = f2tf_f(v.x); v.y = f2tf_f(v.y); v.z = f2tf_f(v.z); v.w = f2tf_f(v.w);
    *(float4*)&y[i] = v;
}

__global__ void pack_w(const float* __restrict__ wq, const float* __restrict__ wkv,
                       float* __restrict__ w)
{
    int idx = blockIdx.x * 256 + threadIdx.x;
    if (idx >= DIM * NQKV) return;
    int k = idx / NQKV, c = idx % NQKV;
    float v = (c < DIM) ? wq[k * DIM + c] : wkv[k * 1024 + (c - DIM)];
    w[idx] = f2tf_f(v);
}

__global__ void pack_wo(const float* __restrict__ wo, float* __restrict__ w)
{
    int idx = blockIdx.x * 256 + threadIdx.x;
    if (idx >= DIM * DIM) return;
    w[idx] = f2tf_f(wo[idx]);
}

__device__ __forceinline__ void mma_tf32(float* c, const unsigned* a,
                                         unsigned b0, unsigned b1)
{
    asm volatile(
        "mma.sync.aligned.m16n8k8.row.col.f32.tf32.tf32.f32 "
        "{%0,%1,%2,%3}, {%4,%5,%6,%7}, {%8,%9}, {%0,%1,%2,%3};\n"
        : "+f"(c[0]), "+f"(c[1]), "+f"(c[2]), "+f"(c[3])
        : "r"(a[0]), "r"(a[1]), "r"(a[2]), "r"(a[3]), "r"(b0), "r"(b1));
}

__device__ __forceinline__ void cp16(unsigned dst, const void* src, bool pred) {
    int sz = pred ? 16 : 0;
    asm volatile("cp.async.cg.shared.global [%0], [%1], 16, %2;\n"
                 :: "r"(dst), "l"(src), "r"(sz));
}

// ---------------- pipelined tf32 tensor-core GEMM (BK=32, 3 stages) ---------
// Operands are pre-rounded tf32 values stored as fp32 -> hw truncation exact.
#define BM 128
#define BN 128
#define BK2 32
#define NSTAGE 3
#define ASTR3 36
#define BSTR 136
#define A_TILE_U32 (BM * ASTR3)          // 4608
#define B_TILE_U32 (BK2 * BSTR)          // 4352
#define GEMM_SMEM ((NSTAGE * (A_TILE_U32 + B_TILE_U32)) * 4)  // 107520 B

template<bool BIAS>
__global__ void __launch_bounds__(256, 2)
gemm_tf32(const float* __restrict__ A, const float* __restrict__ B,
          const float* __restrict__ bias, float* __restrict__ C,
          int M, int N, int K)
{
    extern __shared__ unsigned gsm[];
    unsigned* As = gsm;                          // [NSTAGE][BM][ASTR3]
    unsigned* Bs = gsm + NSTAGE * A_TILE_U32;    // [NSTAGE][BK2][BSTR]

    const int tid  = threadIdx.x;
    const int m0   = blockIdx.y * BM;
    const int n0   = blockIdx.x * BN;
    const int lane = tid & 31;
    const int wid  = tid >> 5;
    const int wm   = (wid & 1) * 64;
    const int wn   = (wid >> 1) * 32;
    const int lq   = lane & 3;
    const int lr   = lane >> 2;

    const unsigned aBase = (unsigned)__cvta_generic_to_shared(As);
    const unsigned bBase = (unsigned)__cvta_generic_to_shared(Bs);

    // 4 x 16B chunks per thread for A (128x32) and B (32x128)
    auto loadA = [&](int st, int k0) {
#pragma unroll
        for (int c = 0; c < 4; c++) {
            int chunk = c * 256 + tid;          // 0..1023
            int row = chunk >> 3;               // 0..127
            int ch  = chunk & 7;                // 0..7 (16B units in 32-float row)
            bool v = (m0 + row) < M;
            cp16(aBase + (st * A_TILE_U32 + row * ASTR3 + ch * 4) * 4,
                 v ? &A[(size_t)(m0 + row) * K + k0 + ch * 4] : (const void*)A, v);
        }
    };
    auto loadB = [&](int st, int k0) {
#pragma unroll
        for (int c = 0; c < 4; c++) {
            int chunk = c * 256 + tid;
            int row = chunk >> 5;               // 0..31
            int ch  = chunk & 31;               // 0..31
            cp16(bBase + (st * B_TILE_U32 + row * BSTR + ch * 4) * 4,
                 &B[(size_t)(k0 + row) * N + n0 + ch * 4], true);
        }
    };

    float acc[4][4][4];
#pragma unroll
    for (int i = 0; i < 4; i++)
#pragma unroll
        for (int j = 0; j < 4; j++)
#pragma unroll
            for (int c = 0; c < 4; c++) acc[i][j][c] = 0.f;

    const int KT = K / BK2;

    loadA(0, 0); loadB(0, 0);
    asm volatile("cp.async.commit_group;\n");
    loadA(1, BK2); loadB(1, BK2);
    asm volatile("cp.async.commit_group;\n");

    int cur = 0, nxt = 2;
    for (int it = 0; it < KT; it++) {
        asm volatile("cp.async.wait_group %0;\n" :: "n"(1));
        __syncthreads();

        int pf = it + 2;
        if (pf < KT) { loadA(nxt, pf * BK2); loadB(nxt, pf * BK2); }
        asm volatile("cp.async.commit_group;\n");

        const unsigned* Ast = As + cur * A_TILE_U32;
        const unsigned* Bst = Bs + cur * B_TILE_U32;

#pragma unroll
        for (int ks = 0; ks < BK2; ks += 8) {
            unsigned af[4][4], bf[4][2];
#pragma unroll
            for (int tm = 0; tm < 4; tm++) {
                int m = wm + tm * 16 + lr;
                af[tm][0] = Ast[m * ASTR3 + ks + lq];
                af[tm][1] = Ast[(m + 8) * ASTR3 + ks + lq];
                af[tm][2] = Ast[m * ASTR3 + ks + lq + 4];
                af[tm][3] = Ast[(m + 8) * ASTR3 + ks + lq + 4];
            }
#pragma unroll
            for (int tn = 0; tn < 4; tn++) {
                int n = wn + tn * 8 + lr;
                bf[tn][0] = Bst[(ks + lq) * BSTR + n];
                bf[tn][1] = Bst[(ks + lq + 4) * BSTR + n];
            }
#pragma unroll
            for (int tm = 0; tm < 4; tm++)
#pragma unroll
                for (int tn = 0; tn < 4; tn++)
                    mma_tf32(acc[tm][tn], af[tm], bf[tn][0], bf[tn][1]);
        }
        cur = (cur == 2) ? 0 : cur + 1;
        nxt = (nxt == 2) ? 0 : nxt + 1;
    }

#pragma unroll
    for (int tm = 0; tm < 4; tm++) {
#pragma unroll
        for (int half = 0; half < 2; half++) {
            int row = m0 + wm + tm * 16 + lr + half * 8;
            if (row >= M) continue;
#pragma unroll
            for (int tn = 0; tn < 4; tn++) {
                int col = n0 + wn + tn * 8 + 2 * lq;
                float2 o;
                o.x = acc[tm][tn][half * 2 + 0];
                o.y = acc[tm][tn][half * 2 + 1];
                if (BIAS) { o.x += bias[col]; o.y += bias[col + 1]; }
                *(float2*)&C[(size_t)row * N + col] = o;
            }
        }
    }
}

// ---------------- tensor-core chunked attention ------------------------------
#define KS2 68
#define VS2 212
#define AEB 220
#define ATTN_SMEM ((208*KS2 + 64*VS2 + 8*16*AEB) * 4)   // 223488 bytes

__global__ void __launch_bounds__(256, 1)
attn_mma(const float* __restrict__ QKV, const float* __restrict__ T,
         float* __restrict__ AO)
{
    extern __shared__ unsigned smu[];
    unsigned* ksm = smu;                       // [208][KS2]
    unsigned* vsm = ksm + 208 * KS2;           // [64][VS2]
    float* ebase  = (float*)(vsm + 64 * VS2);  // [8][16][AEB]

    const int b   = blockIdx.y;
    const int m   = blockIdx.x / HEADS;
    const int h   = blockIdx.x % HEADS;
    const int t0  = m * CTX;
    const int cv  = (NTOK - t0 < CTX) ? (NTOK - t0) : CTX;
    const int tid = threadIdx.x;
    const int w   = tid >> 5, lane = tid & 31;
    const int lr  = lane >> 2, lq = lane & 3;

    for (int idx = tid; idx < 208 * 16; idx += 256) {
        int i = idx >> 4, d = (idx & 15) * 4;
        if (i < cv) {
            const float* p = &QKV[(size_t)(b*NTOK + t0 + i)*NQKV + DIM + h*DH + d];
            float4 v = *(const float4*)p;
            ksm[i*KS2 + d]     = f2tf(v.x);
            ksm[i*KS2 + d + 1] = f2tf(v.y);
            ksm[i*KS2 + d + 2] = f2tf(v.z);
            ksm[i*KS2 + d + 3] = f2tf(v.w);
        } else {
            ksm[i*KS2 + d] = ksm[i*KS2 + d+1] = ksm[i*KS2 + d+2] = ksm[i*KS2 + d+3] = 0u;
        }
    }
    for (int idx = tid; idx < 208 * 64; idx += 256) {
        int j = idx >> 6, d = idx & 63;
        unsigned v = 0u;
        if (j < cv)
            v = f2tf(QKV[(size_t)(b*NTOK + t0 + j)*NQKV + 2*DIM + h*DH + d]);
        vsm[d*VS2 + j] = v;
    }
    __syncthreads();

    float* E0 = ebase + w * 16 * AEB;

    for (int it = w; it * 16 < cv; it += 8) {
        const int i0 = it * 16;
        const int r0 = i0 + lr, r1 = r0 + 8;
        const bool v0 = r0 < cv, v1 = r1 < cv;
        float* Ea = E0 + lr * AEB;
        float* Eb = E0 + (lr + 8) * AEB;

        unsigned aq[8][4];
        {
            const float* q0 = &QKV[(size_t)(b*NTOK + t0 + r0)*NQKV + h*DH + lq];
            const float* q1 = &QKV[(size_t)(b*NTOK + t0 + r1)*NQKV + h*DH + lq];
#pragma unroll
            for (int kt = 0; kt < 8; kt++) {
                aq[kt][0] = v0 ? f2tf(0.125f * q0[kt*8])     : 0u;
                aq[kt][1] = v1 ? f2tf(0.125f * q1[kt*8])     : 0u;
                aq[kt][2] = v0 ? f2tf(0.125f * q0[kt*8 + 4]) : 0u;
                aq[kt][3] = v1 ? f2tf(0.125f * q1[kt*8 + 4]) : 0u;
            }
        }

#pragma unroll 3
        for (int rt = 0; rt < 27; rt++) {
            float ec[4] = {0.f, 0.f, 0.f, 0.f};
            int rg = i0 + rt * 8 + lr;
            const float* trow = &T[(size_t)(rg + 313) * DH + lq];
            bool tv = rg <= 398;
#pragma unroll
            for (int kt = 0; kt < 8; kt++) {
                unsigned b0 = tv ? f2tf(trow[kt*8])     : 0u;
                unsigned b1 = tv ? f2tf(trow[kt*8 + 4]) : 0u;
                mma_tf32(ec, aq[kt], b0, b1);
            }
            int c0 = rt * 8 + 2 * lq;
            Ea[c0]     = ec[0];
            Ea[c0 + 1] = ec[1];
            Eb[c0]     = ec[2];
            Eb[c0 + 1] = ec[3];
        }
        __syncwarp();

        float s[25][4];
#pragma unroll
        for (int nt = 0; nt < 25; nt++)
            s[nt][0] = s[nt][1] = s[nt][2] = s[nt][3] = 0.f;
#pragma unroll
        for (int kt = 0; kt < 8; kt++) {
#pragma unroll
            for (int nt = 0; nt < 25; nt++) {
                unsigned b0 = ksm[(nt*8 + lr)*KS2 + kt*8 + lq];
                unsigned b1 = ksm[(nt*8 + lr)*KS2 + kt*8 + lq + 4];
                mma_tf32(s[nt], aq[kt], b0, b1);
            }
        }

        float mx0 = -1e30f, mx1 = -1e30f;
#pragma unroll
        for (int nt = 0; nt < 25; nt++) {
            int j0 = nt * 8 + 2 * lq;
#pragma unroll
            for (int e = 0; e < 2; e++) {
                int j = j0 + e;
                float a0 = s[nt][e]     + Ea[lr     + 199 - j];
                float a1 = s[nt][2 + e] + Eb[lr + 8 + 199 - j];
                if (j >= cv) { a0 = -1e30f; a1 = -1e30f; }
                s[nt][e] = a0; s[nt][2 + e] = a1;
                mx0 = fmaxf(mx0, a0); mx1 = fmaxf(mx1, a1);
            }
        }
        mx0 = fmaxf(mx0, __shfl_xor_sync(~0u, mx0, 1));
        mx0 = fmaxf(mx0, __shfl_xor_sync(~0u, mx0, 2));
        mx1 = fmaxf(mx1, __shfl_xor_sync(~0u, mx1, 1));
        mx1 = fmaxf(mx1, __shfl_xor_sync(~0u, mx1, 2));

        float sum0 = 0.f, sum1 = 0.f;
#pragma unroll
        for (int nt = 0; nt < 25; nt++) {
#pragma unroll
            for (int e = 0; e < 2; e++) {
                float p0 = __expf(s[nt][e]     - mx0);
                float p1 = __expf(s[nt][2 + e] - mx1);
                s[nt][e] = p0; s[nt][2 + e] = p1;
                sum0 += p0; sum1 += p1;
            }
        }
        sum0 += __shfl_xor_sync(~0u, sum0, 1);
        sum0 += __shfl_xor_sync(~0u, sum0, 2);
        sum1 += __shfl_xor_sync(~0u, sum1, 1);
        sum1 += __shfl_xor_sync(~0u, sum1, 2);
        const float inv0 = 1.f / sum0, inv1 = 1.f / sum1;

        __syncwarp();

        unsigned* Pa = (unsigned*)Ea;
        unsigned* Pb = (unsigned*)Eb;
#pragma unroll
        for (int nt = 0; nt < 25; nt++) {
            int j0 = nt * 8 + 2 * lq;
            Pa[j0]     = f2tf(s[nt][0]);
            Pa[j0 + 1] = f2tf(s[nt][1]);
            Pb[j0]     = f2tf(s[nt][2]);
            Pb[j0 + 1] = f2tf(s[nt][3]);
        }
        unsigned* P = (unsigned*)E0;
        for (int z = lane; z < 128; z += 32)
            P[(z >> 3)*AEB + 200 + (z & 7)] = 0u;
        __syncwarp();

        float o[8][4];
#pragma unroll
        for (int nt = 0; nt < 8; nt++)
            o[nt][0] = o[nt][1] = o[nt][2] = o[nt][3] = 0.f;
#pragma unroll 2
        for (int kt = 0; kt < 26; kt++) {
            unsigned pa[4];
            pa[0] = P[lr*AEB     + kt*8 + lq];
            pa[1] = P[(lr+8)*AEB + kt*8 + lq];
            pa[2] = P[lr*AEB     + kt*8 + lq + 4];
            pa[3] = P[(lr+8)*AEB + kt*8 + lq + 4];
#pragma unroll
            for (int nt = 0; nt < 8; nt++) {
                unsigned b0 = vsm[(nt*8 + lr)*VS2 + kt*8 + lq];
                unsigned b1 = vsm[(nt*8 + lr)*VS2 + kt*8 + lq + 4];
                mma_tf32(o[nt], pa, b0, b1);
            }
        }

#pragma unroll
        for (int nt = 0; nt < 8; nt++) {
            int col = h*DH + nt*8 + 2*lq;
            if (v0) {
                float2 t2 = make_float2(f2tf_f(o[nt][0]*inv0), f2tf_f(o[nt][1]*inv0));
                *(float2*)&AO[(size_t)(b*NTOK + t0 + r0)*DIM + col] = t2;
            }
            if (v1) {
                float2 t2 = make_float2(f2tf_f(o[nt][2]*inv1), f2tf_f(o[nt][3]*inv1));
                *(float2*)&AO[(size_t)(b*NTOK + t0 + r1)*DIM + col] = t2;
            }
        }
        __syncwarp();
    }
}

// ---------------- launcher ----------------
extern "C" void kernel_launch(void* const* d_in, const int* in_sizes, int n_in,
                              void* d_out, int out_size)
{
    const float* x      = (const float*)d_in[0];
    const float* wq     = (const float*)d_in[1];
    const float* wkv    = (const float*)d_in[2];
    const float* wout_w = (const float*)d_in[3];
    const float* wout_b = (const float*)d_in[4];
    const float* rel    = (const float*)d_in[5];
    float* out = (float*)d_out;

    void *pqkv, *pao, *px, *pw, *pwo;
    cudaGetSymbolAddress(&pqkv, g_qkv);
    cudaGetSymbolAddress(&pao,  g_ao);
    cudaGetSymbolAddress(&px,   g_x);
    cudaGetSymbolAddress(&pw,   g_w);
    cudaGetSymbolAddress(&pwo,  g_wo);

    cudaFuncSetAttribute(attn_mma,
                         cudaFuncAttributeMaxDynamicSharedMemorySize, ATTN_SMEM);
    cudaFuncSetAttribute(gemm_tf32<false>,
                         cudaFuncAttributeMaxDynamicSharedMemorySize, GEMM_SMEM);
    cudaFuncSetAttribute(gemm_tf32<true>,
                         cudaFuncAttributeMaxDynamicSharedMemorySize, GEMM_SMEM);

    const int M = MROWS;
    dim3 blk(256);

    round_x<<<(MROWS * DIM / 4 + 255) / 256, 256>>>(x, (float*)px);
    pack_w<<<(DIM * NQKV + 255) / 256, 256>>>(wq, wkv, (float*)pw);
    pack_wo<<<(DIM * DIM + 255) / 256, 256>>>(wout_w, (float*)pwo);

    dim3 gqkv(NQKV / BN, (M + BM - 1) / BM);
    gemm_tf32<false><<<gqkv, blk, GEMM_SMEM>>>((const float*)px, (const float*)pw,
                                               nullptr, (float*)pqkv, M, NQKV, DIM);

    attn_mma<<<dim3(NB * HEADS, BS), blk, ATTN_SMEM>>>(
        (const float*)pqkv, rel, (float*)pao);

    dim3 gout(DIM / BN, (M + BM - 1) / BM);
    gemm_tf32<true><<<gout, blk, GEMM_SMEM>>>((const float*)pao, (const float*)pwo,
                                              wout_b, out, M, DIM, DIM);
}

// round 8
// speedup vs baseline: 4.1450x; 1.1477x over previous
#include <cuda_runtime.h>
#include <cuda_bf16.h>

// ---------------- problem constants ----------------
#define BS    16
#define NTOK  3900
#define DIM   512
#define HEADS 8
#define DH    64
#define CTX   200
#define NB    20
#define MROWS (BS*NTOK)   // 62400
#define NQKV  1536        // fused q|k|v output width

// ---------------- scratch ----------------
__device__ float g_qkv[(size_t)MROWS * NQKV];   // 383 MB
__device__ float g_ao [(size_t)MROWS * DIM];    // 128 MB
__device__ float g_x  [(size_t)MROWS * DIM];    // 128 MB (tf32-rounded X)
__device__ float g_w  [DIM * NQKV];             // packed tf32 [Wq|Wkv]
__device__ float g_wo [DIM * DIM];              // tf32 Wout

__device__ __forceinline__ unsigned f2tf(float f) {
    unsigned u; asm("cvt.rna.tf32.f32 %0, %1;" : "=r"(u) : "f"(f)); return u;
}
__device__ __forceinline__ float f2tf_f(float f) {
    return __uint_as_float(f2tf(f));
}

// ---------------- rounding / packing kernels ----------------
__global__ void round_x(const float* __restrict__ x, float* __restrict__ y)
{
    size_t i = ((size_t)blockIdx.x * 256 + threadIdx.x) * 4;
    if (i >= (size_t)MROWS * DIM) return;
    float4 v = *(const float4*)&x[i];
    v.x = f2tf_f(v.x); v.y = f2tf_f(v.y); v.z = f2tf_f(v.z); v.w = f2tf_f(v.w);
    *(float4*)&y[i] = v;
}

__global__ void pack_w(const float* __restrict__ wq, const float* __restrict__ wkv,
                       float* __restrict__ w)
{
    int idx = blockIdx.x * 256 + threadIdx.x;
    if (idx >= DIM * NQKV) return;
    int k = idx / NQKV, c = idx % NQKV;
    float v = (c < DIM) ? wq[k * DIM + c] : wkv[k * 1024 + (c - DIM)];
    w[idx] = f2tf_f(v);
}

__global__ void pack_wo(const float* __restrict__ wo, float* __restrict__ w)
{
    int idx = blockIdx.x * 256 + threadIdx.x;
    if (idx >= DIM * DIM) return;
    w[idx] = f2tf_f(wo[idx]);
}

__device__ __forceinline__ void mma_tf32(float* c, const unsigned* a,
                                         unsigned b0, unsigned b1)
{
    asm volatile(
        "mma.sync.aligned.m16n8k8.row.col.f32.tf32.tf32.f32 "
        "{%0,%1,%2,%3}, {%4,%5,%6,%7}, {%8,%9}, {%0,%1,%2,%3};\n"
        : "+f"(c[0]), "+f"(c[1]), "+f"(c[2]), "+f"(c[3])
        : "r"(a[0]), "r"(a[1]), "r"(a[2]), "r"(a[3]), "r"(b0), "r"(b1));
}

__device__ __forceinline__ void cp16(unsigned dst, const void* src, bool pred) {
    int sz = pred ? 16 : 0;
    asm volatile("cp.async.cg.shared.global [%0], [%1], 16, %2;\n"
                 :: "r"(dst), "l"(src), "r"(sz));
}

// ---------------- pipelined tf32 tensor-core GEMM (round-7 validated) --------
#define BM 128
#define BN 128
#define BK2 32
#define NSTAGE 3
#define ASTR3 36
#define BSTR 136
#define A_TILE_U32 (BM * ASTR3)          // 4608
#define B_TILE_U32 (BK2 * BSTR)          // 4352
#define GEMM_SMEM ((NSTAGE * (A_TILE_U32 + B_TILE_U32)) * 4)  // 107520 B

template<bool BIAS>
__global__ void __launch_bounds__(256, 2)
gemm_tf32(const float* __restrict__ A, const float* __restrict__ B,
          const float* __restrict__ bias, float* __restrict__ C,
          int M, int N, int K)
{
    extern __shared__ unsigned gsm[];
    unsigned* As = gsm;                          // [NSTAGE][BM][ASTR3]
    unsigned* Bs = gsm + NSTAGE * A_TILE_U32;    // [NSTAGE][BK2][BSTR]

    const int tid  = threadIdx.x;
    const int m0   = blockIdx.y * BM;
    const int n0   = blockIdx.x * BN;
    const int lane = tid & 31;
    const int wid  = tid >> 5;
    const int wm   = (wid & 1) * 64;
    const int wn   = (wid >> 1) * 32;
    const int lq   = lane & 3;
    const int lr   = lane >> 2;

    const unsigned aBase = (unsigned)__cvta_generic_to_shared(As);
    const unsigned bBase = (unsigned)__cvta_generic_to_shared(Bs);

    auto loadA = [&](int st, int k0) {
#pragma unroll
        for (int c = 0; c < 4; c++) {
            int chunk = c * 256 + tid;
            int row = chunk >> 3;
            int ch  = chunk & 7;
            bool v = (m0 + row) < M;
            cp16(aBase + (st * A_TILE_U32 + row * ASTR3 + ch * 4) * 4,
                 v ? &A[(size_t)(m0 + row) * K + k0 + ch * 4] : (const void*)A, v);
        }
    };
    auto loadB = [&](int st, int k0) {
#pragma unroll
        for (int c = 0; c < 4; c++) {
            int chunk = c * 256 + tid;
            int row = chunk >> 5;
            int ch  = chunk & 31;
            cp16(bBase + (st * B_TILE_U32 + row * BSTR + ch * 4) * 4,
                 &B[(size_t)(k0 + row) * N + n0 + ch * 4], true);
        }
    };

    float acc[4][4][4];
#pragma unroll
    for (int i = 0; i < 4; i++)
#pragma unroll
        for (int j = 0; j < 4; j++)
#pragma unroll
            for (int c = 0; c < 4; c++) acc[i][j][c] = 0.f;

    const int KT = K / BK2;

    loadA(0, 0); loadB(0, 0);
    asm volatile("cp.async.commit_group;\n");
    loadA(1, BK2); loadB(1, BK2);
    asm volatile("cp.async.commit_group;\n");

    int cur = 0, nxt = 2;
    for (int it = 0; it < KT; it++) {
        asm volatile("cp.async.wait_group %0;\n" :: "n"(1));
        __syncthreads();

        int pf = it + 2;
        if (pf < KT) { loadA(nxt, pf * BK2); loadB(nxt, pf * BK2); }
        asm volatile("cp.async.commit_group;\n");

        const unsigned* Ast = As + cur * A_TILE_U32;
        const unsigned* Bst = Bs + cur * B_TILE_U32;

#pragma unroll
        for (int ks = 0; ks < BK2; ks += 8) {
            unsigned af[4][4], bf[4][2];
#pragma unroll
            for (int tm = 0; tm < 4; tm++) {
                int m = wm + tm * 16 + lr;
                af[tm][0] = Ast[m * ASTR3 + ks + lq];
                af[tm][1] = Ast[(m + 8) * ASTR3 + ks + lq];
                af[tm][2] = Ast[m * ASTR3 + ks + lq + 4];
                af[tm][3] = Ast[(m + 8) * ASTR3 + ks + lq + 4];
            }
#pragma unroll
            for (int tn = 0; tn < 4; tn++) {
                int n = wn + tn * 8 + lr;
                bf[tn][0] = Bst[(ks + lq) * BSTR + n];
                bf[tn][1] = Bst[(ks + lq + 4) * BSTR + n];
            }
#pragma unroll
            for (int tm = 0; tm < 4; tm++)
#pragma unroll
                for (int tn = 0; tn < 4; tn++)
                    mma_tf32(acc[tm][tn], af[tm], bf[tn][0], bf[tn][1]);
        }
        cur = (cur == 2) ? 0 : cur + 1;
        nxt = (nxt == 2) ? 0 : nxt + 1;
    }

#pragma unroll
    for (int tm = 0; tm < 4; tm++) {
#pragma unroll
        for (int half = 0; half < 2; half++) {
            int row = m0 + wm + tm * 16 + lr + half * 8;
            if (row >= M) continue;
#pragma unroll
            for (int tn = 0; tn < 4; tn++) {
                int col = n0 + wn + tn * 8 + 2 * lq;
                float2 o;
                o.x = acc[tm][tn][half * 2 + 0];
                o.y = acc[tm][tn][half * 2 + 1];
                if (BIAS) { o.x += bias[col]; o.y += bias[col + 1]; }
                *(float2*)&C[(size_t)row * N + col] = o;
            }
        }
    }
}

// ---------------- tensor-core chunked attention ------------------------------
// smem: K tf32 [200][68] | V^T tf32 [64][212] | T bf16 [399][66] |
//       per-warp E bf16 [16][224]   -> 218684 B, 1 CTA/SM
#define KS2 68
#define VS2 212
#define TS3 66
#define ESTR 224
#define ATTN_SMEM ((200*KS2 + 64*VS2) * 4 + 399*TS3*2 + 8*16*ESTR*2)

__global__ void __launch_bounds__(256, 1)
attn_mma(const float* __restrict__ QKV, const float* __restrict__ T,
         float* __restrict__ AO)
{
    extern __shared__ unsigned smu[];
    unsigned* ksm = smu;                                   // [200][KS2]
    unsigned* vsm = ksm + 200 * KS2;                       // [64][VS2]
    unsigned short* tsm = (unsigned short*)(vsm + 64 * VS2);  // [399][TS3]
    unsigned short* esm = tsm + 399 * TS3;                 // [8][16][ESTR]

    const int b   = blockIdx.y;
    const int m   = blockIdx.x / HEADS;
    const int h   = blockIdx.x % HEADS;
    const int t0  = m * CTX;
    const int cv  = (NTOK - t0 < CTX) ? (NTOK - t0) : CTX;
    const int tid = threadIdx.x;
    const int w   = tid >> 5, lane = tid & 31;
    const int lr  = lane >> 2, lq = lane & 3;

    // ---- stage K as tf32, rows >= cv zeroed ----
    for (int idx = tid; idx < 200 * 16; idx += 256) {
        int i = idx >> 4, d = (idx & 15) * 4;
        if (i < cv) {
            const float* p = &QKV[(size_t)(b*NTOK + t0 + i)*NQKV + DIM + h*DH + d];
            float4 v = *(const float4*)p;
            ksm[i*KS2 + d]     = f2tf(v.x);
            ksm[i*KS2 + d + 1] = f2tf(v.y);
            ksm[i*KS2 + d + 2] = f2tf(v.z);
            ksm[i*KS2 + d + 3] = f2tf(v.w);
        } else {
            ksm[i*KS2 + d] = ksm[i*KS2 + d+1] = ksm[i*KS2 + d+2] = ksm[i*KS2 + d+3] = 0u;
        }
    }
    // ---- stage V transposed [d][j], cols >= cv zeroed ----
    for (int idx = tid; idx < 200 * 64; idx += 256) {
        int j = idx >> 6, d = idx & 63;
        unsigned v = 0u;
        if (j < cv)
            v = f2tf(QKV[(size_t)(b*NTOK + t0 + j)*NQKV + 2*DIM + h*DH + d]);
        vsm[d*VS2 + j] = v;
    }
    // ---- stage rel-pos table rows 313..711 as bf16 ----
    for (int idx = tid; idx < 399 * 32; idx += 256) {
        int r = idx >> 5, e2 = (idx & 31) * 2;
        float2 tv = *(const float2*)&T[(size_t)(313 + r) * DH + e2];
        __nv_bfloat162 p2 = __floats2bfloat162_rn(tv.x, tv.y);
        *(__nv_bfloat162*)&tsm[r*TS3 + e2] = p2;
    }
    __syncthreads();

    unsigned short* E0 = esm + w * 16 * ESTR;

    for (int it = w; it * 16 < cv; it += 8) {
        const int i0 = it * 16;
        const int r0 = i0 + lr, r1 = r0 + 8;
        const bool v0 = r0 < cv, v1 = r1 < cv;
        unsigned short* Ea = E0 + lr * ESTR;
        unsigned short* Eb = E0 + (lr + 8) * ESTR;

        // ---- Q fragments, prescaled by dh^-0.5 ----
        unsigned aq[8][4];
        {
            const float* q0 = &QKV[(size_t)(b*NTOK + t0 + r0)*NQKV + h*DH + lq];
            const float* q1 = &QKV[(size_t)(b*NTOK + t0 + r1)*NQKV + h*DH + lq];
#pragma unroll
            for (int kt = 0; kt < 8; kt++) {
                aq[kt][0] = v0 ? f2tf(0.125f * q0[kt*8])     : 0u;
                aq[kt][1] = v1 ? f2tf(0.125f * q1[kt*8])     : 0u;
                aq[kt][2] = v0 ? f2tf(0.125f * q0[kt*8 + 4]) : 0u;
                aq[kt][3] = v1 ? f2tf(0.125f * q1[kt*8 + 4]) : 0u;
            }
        }

        // ---- E[16][216] = Q @ T^T (table from smem bf16) ----
#pragma unroll 3
        for (int rt = 0; rt < 27; rt++) {
            float ec[4] = {0.f, 0.f, 0.f, 0.f};
            int rg = i0 + rt * 8 + lr;
            bool tv = rg <= 398;
            const unsigned short* trow = &tsm[rg * TS3 + lq];
#pragma unroll
            for (int kt = 0; kt < 8; kt++) {
                unsigned b0 = tv ? ((unsigned)trow[kt*8]     << 16) : 0u;
                unsigned b1 = tv ? ((unsigned)trow[kt*8 + 4] << 16) : 0u;
                mma_tf32(ec, aq[kt], b0, b1);
            }
            int c0 = rt * 8 + 2 * lq;
            *(__nv_bfloat162*)&Ea[c0] = __floats2bfloat162_rn(ec[0], ec[1]);
            *(__nv_bfloat162*)&Eb[c0] = __floats2bfloat162_rn(ec[2], ec[3]);
        }
        __syncwarp();

        // ---- S = Q @ K^T ----
        float s[25][4];
#pragma unroll
        for (int nt = 0; nt < 25; nt++)
            s[nt][0] = s[nt][1] = s[nt][2] = s[nt][3] = 0.f;
#pragma unroll
        for (int kt = 0; kt < 8; kt++) {
#pragma unroll
            for (int nt = 0; nt < 25; nt++) {
                unsigned b0 = ksm[(nt*8 + lr)*KS2 + kt*8 + lq];
                unsigned b1 = ksm[(nt*8 + lr)*KS2 + kt*8 + lq + 4];
                mma_tf32(s[nt], aq[kt], b0, b1);
            }
        }

        // ---- bias gather (bf16) + mask + row max ----
        float mx0 = -1e30f, mx1 = -1e30f;
#pragma unroll
        for (int nt = 0; nt < 25; nt++) {
            int j0 = nt * 8 + 2 * lq;
#pragma unroll
            for (int e = 0; e < 2; e++) {
                int j = j0 + e;
                float b0f = __uint_as_float((unsigned)Ea[lr     + 199 - j] << 16);
                float b1f = __uint_as_float((unsigned)Eb[lr + 8 + 199 - j] << 16);
                float a0 = s[nt][e]     + b0f;
                float a1 = s[nt][2 + e] + b1f;
                if (j >= cv) { a0 = -1e30f; a1 = -1e30f; }
                s[nt][e] = a0; s[nt][2 + e] = a1;
                mx0 = fmaxf(mx0, a0); mx1 = fmaxf(mx1, a1);
            }
        }
        mx0 = fmaxf(mx0, __shfl_xor_sync(~0u, mx0, 1));
        mx0 = fmaxf(mx0, __shfl_xor_sync(~0u, mx0, 2));
        mx1 = fmaxf(mx1, __shfl_xor_sync(~0u, mx1, 1));
        mx1 = fmaxf(mx1, __shfl_xor_sync(~0u, mx1, 2));

        float sum0 = 0.f, sum1 = 0.f;
#pragma unroll
        for (int nt = 0; nt < 25; nt++) {
#pragma unroll
            for (int e = 0; e < 2; e++) {
                float p0 = __expf(s[nt][e]     - mx0);
                float p1 = __expf(s[nt][2 + e] - mx1);
                s[nt][e] = p0; s[nt][2 + e] = p1;
                sum0 += p0; sum1 += p1;
            }
        }
        sum0 += __shfl_xor_sync(~0u, sum0, 1);
        sum0 += __shfl_xor_sync(~0u, sum0, 2);
        sum1 += __shfl_xor_sync(~0u, sum1, 1);
        sum1 += __shfl_xor_sync(~0u, sum1, 2);
        const float inv0 = 1.f / sum0, inv1 = 1.f / sum1;

        // ---- O = P @ V, P A-fragments built by shuffle from s registers ----
        float o[8][4];
#pragma unroll
        for (int nt = 0; nt < 8; nt++)
            o[nt][0] = o[nt][1] = o[nt][2] = o[nt][3] = 0.f;

        const int src1 = (lane & ~3) | (lq >> 1);
        const int src2 = src1 + 2;
        const bool odd = lq & 1;
#pragma unroll
        for (int kt = 0; kt < 25; kt++) {
            float x0 = __shfl_sync(~0u, s[kt][0], src1);
            float x1 = __shfl_sync(~0u, s[kt][1], src1);
            float y0 = __shfl_sync(~0u, s[kt][2], src1);
            float y1 = __shfl_sync(~0u, s[kt][3], src1);
            float z0 = __shfl_sync(~0u, s[kt][0], src2);
            float z1 = __shfl_sync(~0u, s[kt][1], src2);
            float u0 = __shfl_sync(~0u, s[kt][2], src2);
            float u1 = __shfl_sync(~0u, s[kt][3], src2);
            unsigned pa[4];
            pa[0] = f2tf(odd ? x1 : x0);
            pa[1] = f2tf(odd ? y1 : y0);
            pa[2] = f2tf(odd ? z1 : z0);
            pa[3] = f2tf(odd ? u1 : u0);
#pragma unroll
            for (int nt = 0; nt < 8; nt++) {
                unsigned b0 = vsm[(nt*8 + lr)*VS2 + kt*8 + lq];
                unsigned b1 = vsm[(nt*8 + lr)*VS2 + kt*8 + lq + 4];
                mma_tf32(o[nt], pa, b0, b1);
            }
        }

        // ---- write O (normalized, tf32-rounded for exact out-proj) ----
#pragma unroll
        for (int nt = 0; nt < 8; nt++) {
            int col = h*DH + nt*8 + 2*lq;
            if (v0) {
                float2 t2 = make_float2(f2tf_f(o[nt][0]*inv0), f2tf_f(o[nt][1]*inv0));
                *(float2*)&AO[(size_t)(b*NTOK + t0 + r0)*DIM + col] = t2;
            }
            if (v1) {
                float2 t2 = make_float2(f2tf_f(o[nt][2]*inv1), f2tf_f(o[nt][3]*inv1));
                *(float2*)&AO[(size_t)(b*NTOK + t0 + r1)*DIM + col] = t2;
            }
        }
        __syncwarp();   // E buffer reused next i-tile
    }
}

// ---------------- launcher ----------------
extern "C" void kernel_launch(void* const* d_in, const int* in_sizes, int n_in,
                              void* d_out, int out_size)
{
    const float* x      = (const float*)d_in[0];
    const float* wq     = (const float*)d_in[1];
    const float* wkv    = (const float*)d_in[2];
    const float* wout_w = (const float*)d_in[3];
    const float* wout_b = (const float*)d_in[4];
    const float* rel    = (const float*)d_in[5];
    float* out = (float*)d_out;

    void *pqkv, *pao, *px, *pw, *pwo;
    cudaGetSymbolAddress(&pqkv, g_qkv);
    cudaGetSymbolAddress(&pao,  g_ao);
    cudaGetSymbolAddress(&px,   g_x);
    cudaGetSymbolAddress(&pw,   g_w);
    cudaGetSymbolAddress(&pwo,  g_wo);

    cudaFuncSetAttribute(attn_mma,
                         cudaFuncAttributeMaxDynamicSharedMemorySize, ATTN_SMEM);
    cudaFuncSetAttribute(gemm_tf32<false>,
                         cudaFuncAttributeMaxDynamicSharedMemorySize, GEMM_SMEM);
    cudaFuncSetAttribute(gemm_tf32<true>,
                         cudaFuncAttributeMaxDynamicSharedMemorySize, GEMM_SMEM);

    const int M = MROWS;
    dim3 blk(256);

    round_x<<<(MROWS * DIM / 4 + 255) / 256, 256>>>(x, (float*)px);
    pack_w<<<(DIM * NQKV + 255) / 256, 256>>>(wq, wkv, (float*)pw);
    pack_wo<<<(DIM * DIM + 255) / 256, 256>>>(wout_w, (float*)pwo);

    dim3 gqkv(NQKV / BN, (M + BM - 1) / BM);
    gemm_tf32<false><<<gqkv, blk, GEMM_SMEM>>>((const float*)px, (const float*)pw,
                                               nullptr, (float*)pqkv, M, NQKV, DIM);

    attn_mma<<<dim3(NB * HEADS, BS), blk, ATTN_SMEM>>>(
        (const float*)pqkv, rel, (float*)pao);

    dim3 gout(DIM / BN, (M + BM - 1) / BM);
    gemm_tf32<true><<<gout, blk, GEMM_SMEM>>>((const float*)pao, (const float*)pwo,
                                              wout_b, out, M, DIM, DIM);
}

// round 9
// speedup vs baseline: 4.4626x; 1.0766x over previous
#include <cuda_runtime.h>
#include <cuda_bf16.h>

// ---------------- problem constants ----------------
#define BS    16
#define NTOK  3900
#define DIM   512
#define HEADS 8
#define DH    64
#define CTX   200
#define NB    20
#define MROWS (BS*NTOK)   // 62400
#define NQKV  1536        // fused q|k|v output width

// ---------------- scratch ----------------
__device__ float g_qkv[(size_t)MROWS * NQKV];   // 383 MB
__device__ float g_ao [(size_t)MROWS * DIM];    // 128 MB
__device__ float g_x  [(size_t)MROWS * DIM];    // 128 MB (tf32-rounded X)
__device__ float g_w  [DIM * NQKV];             // packed tf32 [Wq|Wkv]
__device__ float g_wo [DIM * DIM];              // tf32 Wout

__device__ __forceinline__ unsigned f2tf(float f) {
    unsigned u; asm("cvt.rna.tf32.f32 %0, %1;" : "=r"(u) : "f"(f)); return u;
}
__device__ __forceinline__ float f2tf_f(float f) {
    return __uint_as_float(f2tf(f));
}
__device__ __forceinline__ unsigned pack_bf2(float lo, float hi) {
    __nv_bfloat162 p = __floats2bfloat162_rn(lo, hi);
    return *(unsigned*)&p;
}

// ---------------- rounding / packing kernels ----------------
__global__ void round_x(const float* __restrict__ x, float* __restrict__ y)
{
    size_t i = ((size_t)blockIdx.x * 256 + threadIdx.x) * 4;
    if (i >= (size_t)MROWS * DIM) return;
    float4 v = *(const float4*)&x[i];
    v.x = f2tf_f(v.x); v.y = f2tf_f(v.y); v.z = f2tf_f(v.z); v.w = f2tf_f(v.w);
    *(float4*)&y[i] = v;
}

__global__ void pack_w(const float* __restrict__ wq, const float* __restrict__ wkv,
                       float* __restrict__ w)
{
    int idx = blockIdx.x * 256 + threadIdx.x;
    if (idx >= DIM * NQKV) return;
    int k = idx / NQKV, c = idx % NQKV;
    float v = (c < DIM) ? wq[k * DIM + c] : wkv[k * 1024 + (c - DIM)];
    w[idx] = f2tf_f(v);
}

__global__ void pack_wo(const float* __restrict__ wo, float* __restrict__ w)
{
    int idx = blockIdx.x * 256 + threadIdx.x;
    if (idx >= DIM * DIM) return;
    w[idx] = f2tf_f(wo[idx]);
}

__device__ __forceinline__ void mma_tf32(float* c, const unsigned* a,
                                         unsigned b0, unsigned b1)
{
    asm volatile(
        "mma.sync.aligned.m16n8k8.row.col.f32.tf32.tf32.f32 "
        "{%0,%1,%2,%3}, {%4,%5,%6,%7}, {%8,%9}, {%0,%1,%2,%3};\n"
        : "+f"(c[0]), "+f"(c[1]), "+f"(c[2]), "+f"(c[3])
        : "r"(a[0]), "r"(a[1]), "r"(a[2]), "r"(a[3]), "r"(b0), "r"(b1));
}

__device__ __forceinline__ void mma_bf16(float* c, const unsigned* a,
                                         unsigned b0, unsigned b1)
{
    asm volatile(
        "mma.sync.aligned.m16n8k16.row.col.f32.bf16.bf16.f32 "
        "{%0,%1,%2,%3}, {%4,%5,%6,%7}, {%8,%9}, {%0,%1,%2,%3};\n"
        : "+f"(c[0]), "+f"(c[1]), "+f"(c[2]), "+f"(c[3])
        : "r"(a[0]), "r"(a[1]), "r"(a[2]), "r"(a[3]), "r"(b0), "r"(b1));
}

__device__ __forceinline__ void cp16(unsigned dst, const void* src, bool pred) {
    int sz = pred ? 16 : 0;
    asm volatile("cp.async.cg.shared.global [%0], [%1], 16, %2;\n"
                 :: "r"(dst), "l"(src), "r"(sz));
}

// ---------------- pipelined tf32 tensor-core GEMM (round-7 validated) --------
#define BM 128
#define BN 128
#define BK2 32
#define NSTAGE 3
#define ASTR3 36
#define BSTR 136
#define A_TILE_U32 (BM * ASTR3)          // 4608
#define B_TILE_U32 (BK2 * BSTR)          // 4352
#define GEMM_SMEM ((NSTAGE * (A_TILE_U32 + B_TILE_U32)) * 4)  // 107520 B

template<bool BIAS>
__global__ void __launch_bounds__(256, 2)
gemm_tf32(const float* __restrict__ A, const float* __restrict__ B,
          const float* __restrict__ bias, float* __restrict__ C,
          int M, int N, int K)
{
    extern __shared__ unsigned gsm[];
    unsigned* As = gsm;                          // [NSTAGE][BM][ASTR3]
    unsigned* Bs = gsm + NSTAGE * A_TILE_U32;    // [NSTAGE][BK2][BSTR]

    const int tid  = threadIdx.x;
    const int m0   = blockIdx.y * BM;
    const int n0   = blockIdx.x * BN;
    const int lane = tid & 31;
    const int wid  = tid >> 5;
    const int wm   = (wid & 1) * 64;
    const int wn   = (wid >> 1) * 32;
    const int lq   = lane & 3;
    const int lr   = lane >> 2;

    const unsigned aBase = (unsigned)__cvta_generic_to_shared(As);
    const unsigned bBase = (unsigned)__cvta_generic_to_shared(Bs);

    auto loadA = [&](int st, int k0) {
#pragma unroll
        for (int c = 0; c < 4; c++) {
            int chunk = c * 256 + tid;
            int row = chunk >> 3;
            int ch  = chunk & 7;
            bool v = (m0 + row) < M;
            cp16(aBase + (st * A_TILE_U32 + row * ASTR3 + ch * 4) * 4,
                 v ? &A[(size_t)(m0 + row) * K + k0 + ch * 4] : (const void*)A, v);
        }
    };
    auto loadB = [&](int st, int k0) {
#pragma unroll
        for (int c = 0; c < 4; c++) {
            int chunk = c * 256 + tid;
            int row = chunk >> 5;
            int ch  = chunk & 31;
            cp16(bBase + (st * B_TILE_U32 + row * BSTR + ch * 4) * 4,
                 &B[(size_t)(k0 + row) * N + n0 + ch * 4], true);
        }
    };

    float acc[4][4][4];
#pragma unroll
    for (int i = 0; i < 4; i++)
#pragma unroll
        for (int j = 0; j < 4; j++)
#pragma unroll
            for (int c = 0; c < 4; c++) acc[i][j][c] = 0.f;

    const int KT = K / BK2;

    loadA(0, 0); loadB(0, 0);
    asm volatile("cp.async.commit_group;\n");
    loadA(1, BK2); loadB(1, BK2);
    asm volatile("cp.async.commit_group;\n");

    int cur = 0, nxt = 2;
    for (int it = 0; it < KT; it++) {
        asm volatile("cp.async.wait_group %0;\n" :: "n"(1));
        __syncthreads();

        int pf = it + 2;
        if (pf < KT) { loadA(nxt, pf * BK2); loadB(nxt, pf * BK2); }
        asm volatile("cp.async.commit_group;\n");

        const unsigned* Ast = As + cur * A_TILE_U32;
        const unsigned* Bst = Bs + cur * B_TILE_U32;

#pragma unroll
        for (int ks = 0; ks < BK2; ks += 8) {
            unsigned af[4][4], bf[4][2];
#pragma unroll
            for (int tm = 0; tm < 4; tm++) {
                int m = wm + tm * 16 + lr;
                af[tm][0] = Ast[m * ASTR3 + ks + lq];
                af[tm][1] = Ast[(m + 8) * ASTR3 + ks + lq];
                af[tm][2] = Ast[m * ASTR3 + ks + lq + 4];
                af[tm][3] = Ast[(m + 8) * ASTR3 + ks + lq + 4];
            }
#pragma unroll
            for (int tn = 0; tn < 4; tn++) {
                int n = wn + tn * 8 + lr;
                bf[tn][0] = Bst[(ks + lq) * BSTR + n];
                bf[tn][1] = Bst[(ks + lq + 4) * BSTR + n];
            }
#pragma unroll
            for (int tm = 0; tm < 4; tm++)
#pragma unroll
                for (int tn = 0; tn < 4; tn++)
                    mma_tf32(acc[tm][tn], af[tm], bf[tn][0], bf[tn][1]);
        }
        cur = (cur == 2) ? 0 : cur + 1;
        nxt = (nxt == 2) ? 0 : nxt + 1;
    }

#pragma unroll
    for (int tm = 0; tm < 4; tm++) {
#pragma unroll
        for (int half = 0; half < 2; half++) {
            int row = m0 + wm + tm * 16 + lr + half * 8;
            if (row >= M) continue;
#pragma unroll
            for (int tn = 0; tn < 4; tn++) {
                int col = n0 + wn + tn * 8 + 2 * lq;
                float2 o;
                o.x = acc[tm][tn][half * 2 + 0];
                o.y = acc[tm][tn][half * 2 + 1];
                if (BIAS) { o.x += bias[col]; o.y += bias[col + 1]; }
                *(float2*)&C[(size_t)row * N + col] = o;
            }
        }
    }
}

// ---------------- tensor-core chunked attention ------------------------------
// S and E in bf16 m16n8k16 (half the MMAs); P@V stays tf32 (V precision).
// smem: K bf16 [200][72sh] | V^T tf32 [64][212] | T bf16 [399][72sh] |
//       per-warp E bf16 [16][224sh]  -> 197872 B
#define KSW 36     // K row stride in u32 words (72 shorts) -> bank-perfect
#define VS2 212
#define TSW 36     // T row stride in u32 words
#define ESTR 224
#define ATTN_SMEM ((200*KSW + 64*VS2 + 399*TSW + (8*16*ESTR)/2) * 4)

__global__ void __launch_bounds__(256, 1)
attn_mma(const float* __restrict__ QKV, const float* __restrict__ T,
         float* __restrict__ AO)
{
    extern __shared__ unsigned smu[];
    unsigned* ksm   = smu;                        // [200][KSW] u32 (bf16x2)
    unsigned* vsm   = ksm + 200 * KSW;            // [64][VS2] tf32
    unsigned* tsm32 = vsm + 64 * VS2;             // [399][TSW] u32 (bf16x2)
    unsigned short* esm = (unsigned short*)(tsm32 + 399 * TSW);  // [8][16][ESTR]

    const int b   = blockIdx.y;
    const int m   = blockIdx.x / HEADS;
    const int h   = blockIdx.x % HEADS;
    const int t0  = m * CTX;
    const int cv  = (NTOK - t0 < CTX) ? (NTOK - t0) : CTX;
    const int tid = threadIdx.x;
    const int w   = tid >> 5, lane = tid & 31;
    const int lr  = lane >> 2, lq = lane & 3;

    // ---- stage K as bf16 pairs, rows >= cv zeroed ----
    for (int idx = tid; idx < 200 * 16; idx += 256) {
        int i = idx >> 4, d = (idx & 15) * 4;
        unsigned p0 = 0u, p1 = 0u;
        if (i < cv) {
            const float* p = &QKV[(size_t)(b*NTOK + t0 + i)*NQKV + DIM + h*DH + d];
            float4 v = *(const float4*)p;
            p0 = pack_bf2(v.x, v.y);
            p1 = pack_bf2(v.z, v.w);
        }
        ksm[i*KSW + (d >> 1)]     = p0;
        ksm[i*KSW + (d >> 1) + 1] = p1;
    }
    // ---- stage V transposed [d][j] tf32, cols >= cv zeroed ----
    for (int idx = tid; idx < 200 * 64; idx += 256) {
        int j = idx >> 6, d = idx & 63;
        unsigned v = 0u;
        if (j < cv)
            v = f2tf(QKV[(size_t)(b*NTOK + t0 + j)*NQKV + 2*DIM + h*DH + d]);
        vsm[d*VS2 + j] = v;
    }
    // ---- stage rel-pos table rows 313..711 as bf16 pairs ----
    for (int idx = tid; idx < 399 * 32; idx += 256) {
        int r = idx >> 5, e2 = (idx & 31) * 2;
        float2 tv = *(const float2*)&T[(size_t)(313 + r) * DH + e2];
        tsm32[r*TSW + (e2 >> 1)] = pack_bf2(tv.x, tv.y);
    }
    __syncthreads();

    unsigned short* E0 = esm + w * 16 * ESTR;

    for (int it = w; it * 16 < cv; it += 8) {
        const int i0 = it * 16;
        const int r0 = i0 + lr, r1 = r0 + 8;
        const bool v0 = r0 < cv, v1 = r1 < cv;
        unsigned short* Ea = E0 + lr * ESTR;
        unsigned short* Eb = E0 + (lr + 8) * ESTR;

        // ---- Q fragments (bf16, m16n8k16), prescaled by dh^-0.5 ----
        unsigned aq[4][4];
        {
            const float* q0 = &QKV[(size_t)(b*NTOK + t0 + r0)*NQKV + h*DH];
            const float* q1 = &QKV[(size_t)(b*NTOK + t0 + r1)*NQKV + h*DH];
#pragma unroll
            for (int kt = 0; kt < 4; kt++) {
                float2 x0 = v0 ? *(const float2*)&q0[kt*16 + 2*lq]
                               : make_float2(0.f, 0.f);
                float2 x1 = v1 ? *(const float2*)&q1[kt*16 + 2*lq]
                               : make_float2(0.f, 0.f);
                float2 y0 = v0 ? *(const float2*)&q0[kt*16 + 2*lq + 8]
                               : make_float2(0.f, 0.f);
                float2 y1 = v1 ? *(const float2*)&q1[kt*16 + 2*lq + 8]
                               : make_float2(0.f, 0.f);
                aq[kt][0] = pack_bf2(0.125f*x0.x, 0.125f*x0.y);
                aq[kt][1] = pack_bf2(0.125f*x1.x, 0.125f*x1.y);
                aq[kt][2] = pack_bf2(0.125f*y0.x, 0.125f*y0.y);
                aq[kt][3] = pack_bf2(0.125f*y1.x, 0.125f*y1.y);
            }
        }

        // ---- E[16][216] = Q @ T^T (bf16 k16) ----
#pragma unroll 3
        for (int rt = 0; rt < 27; rt++) {
            float ec[4] = {0.f, 0.f, 0.f, 0.f};
            int rg = i0 + rt * 8 + lr;
            bool tv = rg <= 398;
            const unsigned* trow = tsm32 + rg * TSW + lq;
#pragma unroll
            for (int kt = 0; kt < 4; kt++) {
                unsigned b0 = tv ? trow[kt*8]     : 0u;
                unsigned b1 = tv ? trow[kt*8 + 4] : 0u;
                mma_bf16(ec, aq[kt], b0, b1);
            }
            int c0 = rt * 8 + 2 * lq;
            *(unsigned*)&Ea[c0] = pack_bf2(ec[0], ec[1]);
            *(unsigned*)&Eb[c0] = pack_bf2(ec[2], ec[3]);
        }
        __syncwarp();

        // ---- S = Q @ K^T (bf16 k16) ----
        float s[25][4];
#pragma unroll
        for (int nt = 0; nt < 25; nt++)
            s[nt][0] = s[nt][1] = s[nt][2] = s[nt][3] = 0.f;
#pragma unroll
        for (int kt = 0; kt < 4; kt++) {
#pragma unroll
            for (int nt = 0; nt < 25; nt++) {
                const unsigned* kr = ksm + (nt*8 + lr)*KSW + kt*8 + lq;
                mma_bf16(s[nt], aq[kt], kr[0], kr[4]);
            }
        }

        // ---- bias gather (bf16) + mask + row max ----
        float mx0 = -1e30f, mx1 = -1e30f;
#pragma unroll
        for (int nt = 0; nt < 25; nt++) {
            int j0 = nt * 8 + 2 * lq;
#pragma unroll
            for (int e = 0; e < 2; e++) {
                int j = j0 + e;
                float b0f = __uint_as_float((unsigned)Ea[lr     + 199 - j] << 16);
                float b1f = __uint_as_float((unsigned)Eb[lr + 8 + 199 - j] << 16);
                float a0 = s[nt][e]     + b0f;
                float a1 = s[nt][2 + e] + b1f;
                if (j >= cv) { a0 = -1e30f; a1 = -1e30f; }
                s[nt][e] = a0; s[nt][2 + e] = a1;
                mx0 = fmaxf(mx0, a0); mx1 = fmaxf(mx1, a1);
            }
        }
        mx0 = fmaxf(mx0, __shfl_xor_sync(~0u, mx0, 1));
        mx0 = fmaxf(mx0, __shfl_xor_sync(~0u, mx0, 2));
        mx1 = fmaxf(mx1, __shfl_xor_sync(~0u, mx1, 1));
        mx1 = fmaxf(mx1, __shfl_xor_sync(~0u, mx1, 2));

        float sum0 = 0.f, sum1 = 0.f;
#pragma unroll
        for (int nt = 0; nt < 25; nt++) {
#pragma unroll
            for (int e = 0; e < 2; e++) {
                float p0 = __expf(s[nt][e]     - mx0);
                float p1 = __expf(s[nt][2 + e] - mx1);
                s[nt][e] = p0; s[nt][2 + e] = p1;
                sum0 += p0; sum1 += p1;
            }
        }
        sum0 += __shfl_xor_sync(~0u, sum0, 1);
        sum0 += __shfl_xor_sync(~0u, sum0, 2);
        sum1 += __shfl_xor_sync(~0u, sum1, 1);
        sum1 += __shfl_xor_sync(~0u, sum1, 2);
        const float inv0 = 1.f / sum0, inv1 = 1.f / sum1;

        // ---- O = P @ V (tf32), P fragments via shuffle from s registers ----
        float o[8][4];
#pragma unroll
        for (int nt = 0; nt < 8; nt++)
            o[nt][0] = o[nt][1] = o[nt][2] = o[nt][3] = 0.f;

        const int src1 = (lane & ~3) | (lq >> 1);
        const int src2 = src1 + 2;
        const bool odd = lq & 1;
#pragma unroll
        for (int kt = 0; kt < 25; kt++) {
            float x0 = __shfl_sync(~0u, s[kt][0], src1);
            float x1 = __shfl_sync(~0u, s[kt][1], src1);
            float y0 = __shfl_sync(~0u, s[kt][2], src1);
            float y1 = __shfl_sync(~0u, s[kt][3], src1);
            float z0 = __shfl_sync(~0u, s[kt][0], src2);
            float z1 = __shfl_sync(~0u, s[kt][1], src2);
            float u0 = __shfl_sync(~0u, s[kt][2], src2);
            float u1 = __shfl_sync(~0u, s[kt][3], src2);
            unsigned pa[4];
            pa[0] = f2tf(odd ? x1 : x0);
            pa[1] = f2tf(odd ? y1 : y0);
            pa[2] = f2tf(odd ? z1 : z0);
            pa[3] = f2tf(odd ? u1 : u0);
#pragma unroll
            for (int nt = 0; nt < 8; nt++) {
                unsigned b0 = vsm[(nt*8 + lr)*VS2 + kt*8 + lq];
                unsigned b1 = vsm[(nt*8 + lr)*VS2 + kt*8 + lq + 4];
                mma_tf32(o[nt], pa, b0, b1);
            }
        }

        // ---- write O (normalized, tf32-rounded for exact out-proj) ----
#pragma unroll
        for (int nt = 0; nt < 8; nt++) {
            int col = h*DH + nt*8 + 2*lq;
            if (v0) {
                float2 t2 = make_float2(f2tf_f(o[nt][0]*inv0), f2tf_f(o[nt][1]*inv0));
                *(float2*)&AO[(size_t)(b*NTOK + t0 + r0)*DIM + col] = t2;
            }
            if (v1) {
                float2 t2 = make_float2(f2tf_f(o[nt][2]*inv1), f2tf_f(o[nt][3]*inv1));
                *(float2*)&AO[(size_t)(b*NTOK + t0 + r1)*DIM + col] = t2;
            }
        }
        __syncwarp();   // E buffer reused next i-tile
    }
}

// ---------------- launcher ----------------
extern "C" void kernel_launch(void* const* d_in, const int* in_sizes, int n_in,
                              void* d_out, int out_size)
{
    const float* x      = (const float*)d_in[0];
    const float* wq     = (const float*)d_in[1];
    const float* wkv    = (const float*)d_in[2];
    const float* wout_w = (const float*)d_in[3];
    const float* wout_b = (const float*)d_in[4];
    const float* rel    = (const float*)d_in[5];
    float* out = (float*)d_out;

    void *pqkv, *pao, *px, *pw, *pwo;
    cudaGetSymbolAddress(&pqkv, g_qkv);
    cudaGetSymbolAddress(&pao,  g_ao);
    cudaGetSymbolAddress(&px,   g_x);
    cudaGetSymbolAddress(&pw,   g_w);
    cudaGetSymbolAddress(&pwo,  g_wo);

    cudaFuncSetAttribute(attn_mma,
                         cudaFuncAttributeMaxDynamicSharedMemorySize, ATTN_SMEM);
    cudaFuncSetAttribute(gemm_tf32<false>,
                         cudaFuncAttributeMaxDynamicSharedMemorySize, GEMM_SMEM);
    cudaFuncSetAttribute(gemm_tf32<true>,
                         cudaFuncAttributeMaxDynamicSharedMemorySize, GEMM_SMEM);

    const int M = MROWS;
    dim3 blk(256);

    round_x<<<(MROWS * DIM / 4 + 255) / 256, 256>>>(x, (float*)px);
    pack_w<<<(DIM * NQKV + 255) / 256, 256>>>(wq, wkv, (float*)pw);
    pack_wo<<<(DIM * DIM + 255) / 256, 256>>>(wout_w, (float*)pwo);

    dim3 gqkv(NQKV / BN, (M + BM - 1) / BM);
    gemm_tf32<false><<<gqkv, blk, GEMM_SMEM>>>((const float*)px, (const float*)pw,
                                               nullptr, (float*)pqkv, M, NQKV, DIM);

    attn_mma<<<dim3(NB * HEADS, BS), blk, ATTN_SMEM>>>(
        (const float*)pqkv, rel, (float*)pao);

    dim3 gout(DIM / BN, (M + BM - 1) / BM);
    gemm_tf32<true><<<gout, blk, GEMM_SMEM>>>((const float*)pao, (const float*)pwo,
                                              wout_b, out, M, DIM, DIM);
}

// round 11
// speedup vs baseline: 4.9540x; 1.1101x over previous
#include <cuda_runtime.h>
#include <cuda_bf16.h>

// ---------------- problem constants ----------------
#define BS    16
#define NTOK  3900
#define DIM   512
#define HEADS 8
#define DH    64
#define CTX   200
#define NB    20
#define MROWS (BS*NTOK)   // 62400
#define NQKV  1536        // fused q|k|v output width

// ---------------- scratch ----------------
__device__ float g_qkv[(size_t)MROWS * NQKV];          // 383 MB
__device__ float g_ao [(size_t)MROWS * DIM];           // 128 MB
__device__ float g_x  [(size_t)MROWS * DIM];           // 128 MB tf32-rounded X
__device__ __nv_bfloat16 g_xh[(size_t)MROWS * DIM];    // 64 MB bf16 X
__device__ unsigned g_wqkh[(DIM/2) * 1024];            // bf16-pair W[Q|K] [kp][n]
__device__ float g_wv [DIM * DIM];                     // tf32 V weights
__device__ float g_wo [DIM * DIM];                     // tf32 Wout

__device__ __forceinline__ unsigned f2tf(float f) {
    unsigned u; asm("cvt.rna.tf32.f32 %0, %1;" : "=r"(u) : "f"(f)); return u;
}
__device__ __forceinline__ float f2tf_f(float f) {
    return __uint_as_float(f2tf(f));
}
__device__ __forceinline__ unsigned pack_bf2(float lo, float hi) {
    __nv_bfloat162 p = __floats2bfloat162_rn(lo, hi);
    return *(unsigned*)&p;
}

// ---------------- rounding / packing kernels ----------------
__global__ void round_x(const float* __restrict__ x, float* __restrict__ y,
                        __nv_bfloat16* __restrict__ yh)
{
    size_t i = ((size_t)blockIdx.x * 256 + threadIdx.x) * 4;
    if (i >= (size_t)MROWS * DIM) return;
    float4 v = *(const float4*)&x[i];
    float4 r;
    r.x = f2tf_f(v.x); r.y = f2tf_f(v.y); r.z = f2tf_f(v.z); r.w = f2tf_f(v.w);
    *(float4*)&y[i] = r;
    uint2 h;
    h.x = pack_bf2(v.x, v.y);
    h.y = pack_bf2(v.z, v.w);
    *(uint2*)&yh[i] = h;
}

// W[Q|K] into bf16 k-pair layout: word(kp, n) = (W[2kp][n], W[2kp+1][n])
__global__ void pack_wqk(const float* __restrict__ wq, const float* __restrict__ wkv,
                         unsigned* __restrict__ w)
{
    int idx = blockIdx.x * 256 + threadIdx.x;
    if (idx >= (DIM/2) * 1024) return;
    int kp = idx >> 10, n = idx & 1023;
    float a, b;
    if (n < DIM) { a = wq[(2*kp) * DIM + n];       b = wq[(2*kp+1) * DIM + n]; }
    else         { a = wkv[(2*kp) * 1024 + n-DIM]; b = wkv[(2*kp+1) * 1024 + n-DIM]; }
    w[idx] = pack_bf2(a, b);
}

__global__ void pack_wv(const float* __restrict__ wkv, float* __restrict__ w)
{
    int idx = blockIdx.x * 256 + threadIdx.x;
    if (idx >= DIM * DIM) return;
    int k = idx >> 9, c = idx & 511;
    w[idx] = f2tf_f(wkv[k * 1024 + DIM + c]);
}

__global__ void pack_wo(const float* __restrict__ wo, float* __restrict__ w)
{
    int idx = blockIdx.x * 256 + threadIdx.x;
    if (idx >= DIM * DIM) return;
    w[idx] = f2tf_f(wo[idx]);
}

__device__ __forceinline__ void mma_tf32(float* c, const unsigned* a,
                                         unsigned b0, unsigned b1)
{
    asm volatile(
        "mma.sync.aligned.m16n8k8.row.col.f32.tf32.tf32.f32 "
        "{%0,%1,%2,%3}, {%4,%5,%6,%7}, {%8,%9}, {%0,%1,%2,%3};\n"
        : "+f"(c[0]), "+f"(c[1]), "+f"(c[2]), "+f"(c[3])
        : "r"(a[0]), "r"(a[1]), "r"(a[2]), "r"(a[3]), "r"(b0), "r"(b1));
}

__device__ __forceinline__ void mma_bf16(float* c, const unsigned* a,
                                         unsigned b0, unsigned b1)
{
    asm volatile(
        "mma.sync.aligned.m16n8k16.row.col.f32.bf16.bf16.f32 "
        "{%0,%1,%2,%3}, {%4,%5,%6,%7}, {%8,%9}, {%0,%1,%2,%3};\n"
        : "+f"(c[0]), "+f"(c[1]), "+f"(c[2]), "+f"(c[3])
        : "r"(a[0]), "r"(a[1]), "r"(a[2]), "r"(a[3]), "r"(b0), "r"(b1));
}

__device__ __forceinline__ void cp16(unsigned dst, const void* src, bool pred) {
    int sz = pred ? 16 : 0;
    asm volatile("cp.async.cg.shared.global [%0], [%1], 16, %2;\n"
                 :: "r"(dst), "l"(src), "r"(sz));
}

// ---------------- pipelined tf32 GEMM (round-7 validated, + ldc) -------------
#define BM 128
#define BN 128
#define BK2 32
#define ASTR3 36
#define BSTR 136
#define A_TILE_U32 (BM * ASTR3)          // 4608
#define B_TILE_U32 (BK2 * BSTR)          // 4352
#define GEMM_SMEM ((3 * (A_TILE_U32 + B_TILE_U32)) * 4)  // 107520 B

template<bool BIAS>
__global__ void __launch_bounds__(256, 2)
gemm_tf32(const float* __restrict__ A, const float* __restrict__ B,
          const float* __restrict__ bias, float* __restrict__ C,
          int M, int N, int K, int ldc)
{
    extern __shared__ unsigned gsm[];
    unsigned* As = gsm;
    unsigned* Bs = gsm + 3 * A_TILE_U32;

    const int tid  = threadIdx.x;
    const int m0   = blockIdx.y * BM;
    const int n0   = blockIdx.x * BN;
    const int lane = tid & 31;
    const int wid  = tid >> 5;
    const int wm   = (wid & 1) * 64;
    const int wn   = (wid >> 1) * 32;
    const int lq   = lane & 3;
    const int lr   = lane >> 2;

    const unsigned aBase = (unsigned)__cvta_generic_to_shared(As);
    const unsigned bBase = (unsigned)__cvta_generic_to_shared(Bs);

    auto loadA = [&](int st, int k0) {
#pragma unroll
        for (int c = 0; c < 4; c++) {
            int chunk = c * 256 + tid;
            int row = chunk >> 3;
            int ch  = chunk & 7;
            bool v = (m0 + row) < M;
            cp16(aBase + (st * A_TILE_U32 + row * ASTR3 + ch * 4) * 4,
                 v ? &A[(size_t)(m0 + row) * K + k0 + ch * 4] : (const void*)A, v);
        }
    };
    auto loadB = [&](int st, int k0) {
#pragma unroll
        for (int c = 0; c < 4; c++) {
            int chunk = c * 256 + tid;
            int row = chunk >> 5;
            int ch  = chunk & 31;
            cp16(bBase + (st * B_TILE_U32 + row * BSTR + ch * 4) * 4,
                 &B[(size_t)(k0 + row) * N + n0 + ch * 4], true);
        }
    };

    float acc[4][4][4];
#pragma unroll
    for (int i = 0; i < 4; i++)
#pragma unroll
        for (int j = 0; j < 4; j++)
#pragma unroll
            for (int c = 0; c < 4; c++) acc[i][j][c] = 0.f;

    const int KT = K / BK2;

    loadA(0, 0); loadB(0, 0);
    asm volatile("cp.async.commit_group;\n");
    loadA(1, BK2); loadB(1, BK2);
    asm volatile("cp.async.commit_group;\n");

    int cur = 0, nxt = 2;
    for (int it = 0; it < KT; it++) {
        asm volatile("cp.async.wait_group %0;\n" :: "n"(1));
        __syncthreads();

        int pf = it + 2;
        if (pf < KT) { loadA(nxt, pf * BK2); loadB(nxt, pf * BK2); }
        asm volatile("cp.async.commit_group;\n");

        const unsigned* Ast = As + cur * A_TILE_U32;
        const unsigned* Bst = Bs + cur * B_TILE_U32;

#pragma unroll
        for (int ks = 0; ks < BK2; ks += 8) {
            unsigned af[4][4], bf[4][2];
#pragma unroll
            for (int tm = 0; tm < 4; tm++) {
                int m = wm + tm * 16 + lr;
                af[tm][0] = Ast[m * ASTR3 + ks + lq];
                af[tm][1] = Ast[(m + 8) * ASTR3 + ks + lq];
                af[tm][2] = Ast[m * ASTR3 + ks + lq + 4];
                af[tm][3] = Ast[(m + 8) * ASTR3 + ks + lq + 4];
            }
#pragma unroll
            for (int tn = 0; tn < 4; tn++) {
                int n = wn + tn * 8 + lr;
                bf[tn][0] = Bst[(ks + lq) * BSTR + n];
                bf[tn][1] = Bst[(ks + lq + 4) * BSTR + n];
            }
#pragma unroll
            for (int tm = 0; tm < 4; tm++)
#pragma unroll
                for (int tn = 0; tn < 4; tn++)
                    mma_tf32(acc[tm][tn], af[tm], bf[tn][0], bf[tn][1]);
        }
        cur = (cur == 2) ? 0 : cur + 1;
        nxt = (nxt == 2) ? 0 : nxt + 1;
    }

#pragma unroll
    for (int tm = 0; tm < 4; tm++) {
#pragma unroll
        for (int half = 0; half < 2; half++) {
            int row = m0 + wm + tm * 16 + lr + half * 8;
            if (row >= M) continue;
#pragma unroll
            for (int tn = 0; tn < 4; tn++) {
                int col = n0 + wn + tn * 8 + 2 * lq;
                float2 o;
                o.x = acc[tm][tn][half * 2 + 0];
                o.y = acc[tm][tn][half * 2 + 1];
                if (BIAS) { o.x += bias[col]; o.y += bias[col + 1]; }
                *(float2*)&C[(size_t)row * ldc + col] = o;
            }
        }
    }
}

// ---------------- pipelined bf16 GEMM (QK projection) ------------------------
// A bf16 row-major [m][k]; B pre-packed bf16-pair words [kp][n].
#define AH 20                             // A row stride in u32 words (40 bf16)
#define AH_TILE (BM * AH)                 // 2560
#define BH_TILE ((BK2/2) * BSTR)          // 2176
#define GEMMH_SMEM ((3 * (AH_TILE + BH_TILE)) * 4)   // 56832 B

__global__ void __launch_bounds__(256, 2)
gemm_bf16(const __nv_bfloat16* __restrict__ A, const unsigned* __restrict__ B,
          float* __restrict__ C, int M, int N, int K, int ldc)
{
    extern __shared__ unsigned gsm[];
    unsigned* As = gsm;                     // [3][BM][AH]
    unsigned* Bs = gsm + 3 * AH_TILE;       // [3][BK2/2][BSTR]

    const int tid  = threadIdx.x;
    const int m0   = blockIdx.y * BM;
    const int n0   = blockIdx.x * BN;
    const int lane = tid & 31;
    const int wid  = tid >> 5;
    const int wm   = (wid & 1) * 64;
    const int wn   = (wid >> 1) * 32;
    const int lq   = lane & 3;
    const int lr   = lane >> 2;

    const unsigned aBase = (unsigned)__cvta_generic_to_shared(As);
    const unsigned bBase = (unsigned)__cvta_generic_to_shared(Bs);

    auto loadA = [&](int st, int k0) {
#pragma unroll
        for (int c = 0; c < 2; c++) {
            int chunk = c * 256 + tid;      // 0..511
            int row = chunk >> 2;           // 0..127
            int ch  = chunk & 3;            // 16B = 8 bf16 = 4 words
            bool v = (m0 + row) < M;
            cp16(aBase + (st * AH_TILE + row * AH + ch * 4) * 4,
                 v ? (const void*)&A[(size_t)(m0 + row) * K + k0 + ch * 8]
                   : (const void*)A, v);
        }
    };
    auto loadB = [&](int st, int k0) {      // k0 in elements; rows kp = k0/2..
        int kp0 = k0 >> 1;
#pragma unroll
        for (int c = 0; c < 2; c++) {
            int chunk = c * 256 + tid;      // 0..511
            int row = chunk >> 5;           // 0..15
            int ch  = chunk & 31;
            cp16(bBase + (st * BH_TILE + row * BSTR + ch * 4) * 4,
                 &B[(size_t)(kp0 + row) * N + n0 + ch * 4], true);
        }
    };

    float acc[4][4][4];
#pragma unroll
    for (int i = 0; i < 4; i++)
#pragma unroll
        for (int j = 0; j < 4; j++)
#pragma unroll
            for (int c = 0; c < 4; c++) acc[i][j][c] = 0.f;

    const int KT = K / BK2;

    loadA(0, 0); loadB(0, 0);
    asm volatile("cp.async.commit_group;\n");
    loadA(1, BK2); loadB(1, BK2);
    asm volatile("cp.async.commit_group;\n");

    int cur = 0, nxt = 2;
    for (int it = 0; it < KT; it++) {
        asm volatile("cp.async.wait_group %0;\n" :: "n"(1));
        __syncthreads();

        int pf = it + 2;
        if (pf < KT) { loadA(nxt, pf * BK2); loadB(nxt, pf * BK2); }
        asm volatile("cp.async.commit_group;\n");

        const unsigned* Ast = As + cur * AH_TILE;
        const unsigned* Bst = Bs + cur * BH_TILE;

#pragma unroll
        for (int kt = 0; kt < 2; kt++) {            // two k16 steps per BK2=32
            unsigned af[4][4], bf[4][2];
#pragma unroll
            for (int tm = 0; tm < 4; tm++) {
                int m = wm + tm * 16 + lr;
                af[tm][0] = Ast[m * AH + kt * 8 + lq];
                af[tm][1] = Ast[(m + 8) * AH + kt * 8 + lq];
                af[tm][2] = Ast[m * AH + kt * 8 + lq + 4];
                af[tm][3] = Ast[(m + 8) * AH + kt * 8 + lq + 4];
            }
#pragma unroll
            for (int tn = 0; tn < 4; tn++) {
                int n = wn + tn * 8 + lr;
                bf[tn][0] = Bst[(kt * 8 + lq) * BSTR + n];
                bf[tn][1] = Bst[(kt * 8 + lq + 4) * BSTR + n];
            }
#pragma unroll
            for (int tm = 0; tm < 4; tm++)
#pragma unroll
                for (int tn = 0; tn < 4; tn++)
                    mma_bf16(acc[tm][tn], af[tm], bf[tn][0], bf[tn][1]);
        }
        cur = (cur == 2) ? 0 : cur + 1;
        nxt = (nxt == 2) ? 0 : nxt + 1;
    }

#pragma unroll
    for (int tm = 0; tm < 4; tm++) {
#pragma unroll
        for (int half = 0; half < 2; half++) {
            int row = m0 + wm + tm * 16 + lr + half * 8;
            if (row >= M) continue;
#pragma unroll
            for (int tn = 0; tn < 4; tn++) {
                int col = n0 + wn + tn * 8 + 2 * lq;
                float2 o;
                o.x = acc[tm][tn][half * 2 + 0];
                o.y = acc[tm][tn][half * 2 + 1];
                *(float2*)&C[(size_t)row * ldc + col] = o;
            }
        }
    }
}

// ---------------- tensor-core chunked attention (round-9 validated) ----------
#define KSW 36
#define VS2 212
#define TSW 36
#define ESTR 224
#define ATTN_SMEM ((200*KSW + 64*VS2 + 399*TSW + (8*16*ESTR)/2) * 4)

__global__ void __launch_bounds__(256, 1)
attn_mma(const float* __restrict__ QKV, const float* __restrict__ T,
         float* __restrict__ AO)
{
    extern __shared__ unsigned smu[];
    unsigned* ksm   = smu;
    unsigned* vsm   = ksm + 200 * KSW;
    unsigned* tsm32 = vsm + 64 * VS2;
    unsigned short* esm = (unsigned short*)(tsm32 + 399 * TSW);

    const int b   = blockIdx.y;
    const int m   = blockIdx.x / HEADS;
    const int h   = blockIdx.x % HEADS;
    const int t0  = m * CTX;
    const int cv  = (NTOK - t0 < CTX) ? (NTOK - t0) : CTX;
    const int tid = threadIdx.x;
    const int w   = tid >> 5, lane = tid & 31;
    const int lr  = lane >> 2, lq = lane & 3;

    for (int idx = tid; idx < 200 * 16; idx += 256) {
        int i = idx >> 4, d = (idx & 15) * 4;
        unsigned p0 = 0u, p1 = 0u;
        if (i < cv) {
            const float* p = &QKV[(size_t)(b*NTOK + t0 + i)*NQKV + DIM + h*DH + d];
            float4 v = *(const float4*)p;
            p0 = pack_bf2(v.x, v.y);
            p1 = pack_bf2(v.z, v.w);
        }
        ksm[i*KSW + (d >> 1)]     = p0;
        ksm[i*KSW + (d >> 1) + 1] = p1;
    }
    for (int idx = tid; idx < 200 * 64; idx += 256) {
        int j = idx >> 6, d = idx & 63;
        unsigned v = 0u;
        if (j < cv)
            v = f2tf(QKV[(size_t)(b*NTOK + t0 + j)*NQKV + 2*DIM + h*DH + d]);
        vsm[d*VS2 + j] = v;
    }
    for (int idx = tid; idx < 399 * 32; idx += 256) {
        int r = idx >> 5, e2 = (idx & 31) * 2;
        float2 tv = *(const float2*)&T[(size_t)(313 + r) * DH + e2];
        tsm32[r*TSW + (e2 >> 1)] = pack_bf2(tv.x, tv.y);
    }
    __syncthreads();

    unsigned short* E0 = esm + w * 16 * ESTR;

    for (int it = w; it * 16 < cv; it += 8) {
        const int i0 = it * 16;
        const int r0 = i0 + lr, r1 = r0 + 8;
        const bool v0 = r0 < cv, v1 = r1 < cv;
        unsigned short* Ea = E0 + lr * ESTR;
        unsigned short* Eb = E0 + (lr + 8) * ESTR;

        unsigned aq[4][4];
        {
            const float* q0 = &QKV[(size_t)(b*NTOK + t0 + r0)*NQKV + h*DH];
            const float* q1 = &QKV[(size_t)(b*NTOK + t0 + r1)*NQKV + h*DH];
#pragma unroll
            for (int kt = 0; kt < 4; kt++) {
                float2 x0 = v0 ? *(const float2*)&q0[kt*16 + 2*lq]
                               : make_float2(0.f, 0.f);
                float2 x1 = v1 ? *(const float2*)&q1[kt*16 + 2*lq]
                               : make_float2(0.f, 0.f);
                float2 y0 = v0 ? *(const float2*)&q0[kt*16 + 2*lq + 8]
                               : make_float2(0.f, 0.f);
                float2 y1 = v1 ? *(const float2*)&q1[kt*16 + 2*lq + 8]
                               : make_float2(0.f, 0.f);
                aq[kt][0] = pack_bf2(0.125f*x0.x, 0.125f*x0.y);
                aq[kt][1] = pack_bf2(0.125f*x1.x, 0.125f*x1.y);
                aq[kt][2] = pack_bf2(0.125f*y0.x, 0.125f*y0.y);
                aq[kt][3] = pack_bf2(0.125f*y1.x, 0.125f*y1.y);
            }
        }

#pragma unroll 3
        for (int rt = 0; rt < 27; rt++) {
            float ec[4] = {0.f, 0.f, 0.f, 0.f};
            int rg = i0 + rt * 8 + lr;
            bool tv = rg <= 398;
            const unsigned* trow = tsm32 + rg * TSW + lq;
#pragma unroll
            for (int kt = 0; kt < 4; kt++) {
                unsigned b0 = tv ? trow[kt*8]     : 0u;
                unsigned b1 = tv ? trow[kt*8 + 4] : 0u;
                mma_bf16(ec, aq[kt], b0, b1);
            }
            int c0 = rt * 8 + 2 * lq;
            *(unsigned*)&Ea[c0] = pack_bf2(ec[0], ec[1]);
            *(unsigned*)&Eb[c0] = pack_bf2(ec[2], ec[3]);
        }
        __syncwarp();

        float s[25][4];
#pragma unroll
        for (int nt = 0; nt < 25; nt++)
            s[nt][0] = s[nt][1] = s[nt][2] = s[nt][3] = 0.f;
#pragma unroll
        for (int kt = 0; kt < 4; kt++) {
#pragma unroll
            for (int nt = 0; nt < 25; nt++) {
                const unsigned* kr = ksm + (nt*8 + lr)*KSW + kt*8 + lq;
                mma_bf16(s[nt], aq[kt], kr[0], kr[4]);
            }
        }

        float mx0 = -1e30f, mx1 = -1e30f;
#pragma unroll
        for (int nt = 0; nt < 25; nt++) {
            int j0 = nt * 8 + 2 * lq;
#pragma unroll
            for (int e = 0; e < 2; e++) {
                int j = j0 + e;
                float b0f = __uint_as_float((unsigned)Ea[lr     + 199 - j] << 16);
                float b1f = __uint_as_float((unsigned)Eb[lr + 8 + 199 - j] << 16);
                float a0 = s[nt][e]     + b0f;
                float a1 = s[nt][2 + e] + b1f;
                if (j >= cv) { a0 = -1e30f; a1 = -1e30f; }
                s[nt][e] = a0; s[nt][2 + e] = a1;
                mx0 = fmaxf(mx0, a0); mx1 = fmaxf(mx1, a1);
            }
        }
        mx0 = fmaxf(mx0, __shfl_xor_sync(~0u, mx0, 1));
        mx0 = fmaxf(mx0, __shfl_xor_sync(~0u, mx0, 2));
        mx1 = fmaxf(mx1, __shfl_xor_sync(~0u, mx1, 1));
        mx1 = fmaxf(mx1, __shfl_xor_sync(~0u, mx1, 2));

        float sum0 = 0.f, sum1 = 0.f;
#pragma unroll
        for (int nt = 0; nt < 25; nt++) {
#pragma unroll
            for (int e = 0; e < 2; e++) {
                float p0 = __expf(s[nt][e]     - mx0);
                float p1 = __expf(s[nt][2 + e] - mx1);
                s[nt][e] = p0; s[nt][2 + e] = p1;
                sum0 += p0; sum1 += p1;
            }
        }
        sum0 += __shfl_xor_sync(~0u, sum0, 1);
        sum0 += __shfl_xor_sync(~0u, sum0, 2);
        sum1 += __shfl_xor_sync(~0u, sum1, 1);
        sum1 += __shfl_xor_sync(~0u, sum1, 2);
        const float inv0 = 1.f / sum0, inv1 = 1.f / sum1;

        float o[8][4];
#pragma unroll
        for (int nt = 0; nt < 8; nt++)
            o[nt][0] = o[nt][1] = o[nt][2] = o[nt][3] = 0.f;

        const int src1 = (lane & ~3) | (lq >> 1);
        const int src2 = src1 + 2;
        const bool odd = lq & 1;
#pragma unroll
        for (int kt = 0; kt < 25; kt++) {
            float x0 = __shfl_sync(~0u, s[kt][0], src1);
            float x1 = __shfl_sync(~0u, s[kt][1], src1);
            float y0 = __shfl_sync(~0u, s[kt][2], src1);
            float y1 = __shfl_sync(~0u, s[kt][3], src1);
            float z0 = __shfl_sync(~0u, s[kt][0], src2);
            float z1 = __shfl_sync(~0u, s[kt][1], src2);
            float u0 = __shfl_sync(~0u, s[kt][2], src2);
            float u1 = __shfl_sync(~0u, s[kt][3], src2);
            unsigned pa[4];
            pa[0] = f2tf(odd ? x1 : x0);
            pa[1] = f2tf(odd ? y1 : y0);
            pa[2] = f2tf(odd ? z1 : z0);
            pa[3] = f2tf(odd ? u1 : u0);
#pragma unroll
            for (int nt = 0; nt < 8; nt++) {
                unsigned b0 = vsm[(nt*8 + lr)*VS2 + kt*8 + lq];
                unsigned b1 = vsm[(nt*8 + lr)*VS2 + kt*8 + lq + 4];
                mma_tf32(o[nt], pa, b0, b1);
            }
        }

#pragma unroll
        for (int nt = 0; nt < 8; nt++) {
            int col = h*DH + nt*8 + 2*lq;
            if (v0) {
                float2 t2 = make_float2(f2tf_f(o[nt][0]*inv0), f2tf_f(o[nt][1]*inv0));
                *(float2*)&AO[(size_t)(b*NTOK + t0 + r0)*DIM + col] = t2;
            }
            if (v1) {
                float2 t2 = make_float2(f2tf_f(o[nt][2]*inv1), f2tf_f(o[nt][3]*inv1));
                *(float2*)&AO[(size_t)(b*NTOK + t0 + r1)*DIM + col] = t2;
            }
        }
        __syncwarp();
    }
}

// ---------------- launcher ----------------
extern "C" void kernel_launch(void* const* d_in, const int* in_sizes, int n_in,
                              void* d_out, int out_size)
{
    const float* x      = (const float*)d_in[0];
    const float* wq     = (const float*)d_in[1];
    const float* wkv    = (const float*)d_in[2];
    const float* wout_w = (const float*)d_in[3];
    const float* wout_b = (const float*)d_in[4];
    const float* rel    = (const float*)d_in[5];
    float* out = (float*)d_out;

    void *pqkv, *pao, *px, *pxh, *pwqk, *pwv, *pwo;
    cudaGetSymbolAddress(&pqkv, g_qkv);
    cudaGetSymbolAddress(&pao,  g_ao);
    cudaGetSymbolAddress(&px,   g_x);
    cudaGetSymbolAddress(&pxh,  g_xh);
    cudaGetSymbolAddress(&pwqk, g_wqkh);
    cudaGetSymbolAddress(&pwv,  g_wv);
    cudaGetSymbolAddress(&pwo,  g_wo);

    cudaFuncSetAttribute(attn_mma,
                         cudaFuncAttributeMaxDynamicSharedMemorySize, ATTN_SMEM);
    cudaFuncSetAttribute(gemm_tf32<false>,
                         cudaFuncAttributeMaxDynamicSharedMemorySize, GEMM_SMEM);
    cudaFuncSetAttribute(gemm_tf32<true>,
                         cudaFuncAttributeMaxDynamicSharedMemorySize, GEMM_SMEM);
    cudaFuncSetAttribute(gemm_bf16,
                         cudaFuncAttributeMaxDynamicSharedMemorySize, GEMMH_SMEM);

    const int M = MROWS;
    dim3 blk(256);

    round_x<<<(MROWS * DIM / 4 + 255) / 256, 256>>>(x, (float*)px,
                                                    (__nv_bfloat16*)pxh);
    pack_wqk<<<((DIM/2) * 1024 + 255) / 256, 256>>>(wq, wkv, (unsigned*)pwqk);
    pack_wv<<<(DIM * DIM + 255) / 256, 256>>>(wkv, (float*)pwv);
    pack_wo<<<(DIM * DIM + 255) / 256, 256>>>(wout_w, (float*)pwo);

    // Q|K = Xh @ Wqk (bf16)  -> g_qkv cols 0..1023
    dim3 gqk(1024 / BN, (M + BM - 1) / BM);
    gemm_bf16<<<gqk, blk, GEMMH_SMEM>>>((const __nv_bfloat16*)pxh,
                                        (const unsigned*)pwqk,
                                        (float*)pqkv, M, 1024, DIM, NQKV);

    // V = X @ Wv (tf32) -> g_qkv cols 1024..1535
    dim3 gv(DIM / BN, (M + BM - 1) / BM);
    gemm_tf32<false><<<gv, blk, GEMM_SMEM>>>((const float*)px, (const float*)pwv,
                                             nullptr, (float*)pqkv + 2*DIM,
                                             M, DIM, DIM, NQKV);

    attn_mma<<<dim3(NB * HEADS, BS), blk, ATTN_SMEM>>>(
        (const float*)pqkv, rel, (float*)pao);

    dim3 gout(DIM / BN, (M + BM - 1) / BM);
    gemm_tf32<true><<<gout, blk, GEMM_SMEM>>>((const float*)pao, (const float*)pwo,
                                              wout_b, out, M, DIM, DIM, DIM);
}

// round 13
// speedup vs baseline: 5.1985x; 1.0494x over previous
#include <cuda_runtime.h>
#include <cuda_bf16.h>

// ---------------- problem constants ----------------
#define BS    16
#define NTOK  3900
#define DIM   512
#define HEADS 8
#define DH    64
#define CTX   200
#define NB    20
#define MROWS (BS*NTOK)   // 62400
#define NQKV  1536        // fused q|k|v output width

// ---------------- scratch ----------------
__device__ float g_qkv[(size_t)MROWS * NQKV];          // 383 MB
__device__ float g_ao [(size_t)MROWS * DIM];           // 128 MB
__device__ float g_x  [(size_t)MROWS * DIM];           // 128 MB tf32-rounded X
__device__ __nv_bfloat16 g_xh[(size_t)MROWS * DIM];    // 64 MB bf16 X
__device__ unsigned g_wqkh[(DIM/2) * 1024];            // bf16-pair W[Q|K] [kp][n]
__device__ float g_wv [DIM * DIM];                     // tf32 V weights
__device__ float g_wo [DIM * DIM];                     // tf32 Wout

__device__ __forceinline__ unsigned f2tf(float f) {
    unsigned u; asm("cvt.rna.tf32.f32 %0, %1;" : "=r"(u) : "f"(f)); return u;
}
__device__ __forceinline__ float f2tf_f(float f) {
    return __uint_as_float(f2tf(f));
}
__device__ __forceinline__ unsigned pack_bf2(float lo, float hi) {
    __nv_bfloat162 p = __floats2bfloat162_rn(lo, hi);
    return *(unsigned*)&p;
}

// ---------------- rounding / packing kernels ----------------
__global__ void round_x(const float* __restrict__ x, float* __restrict__ y,
                        __nv_bfloat16* __restrict__ yh)
{
    size_t i = ((size_t)blockIdx.x * 256 + threadIdx.x) * 4;
    if (i >= (size_t)MROWS * DIM) return;
    float4 v = *(const float4*)&x[i];
    float4 r;
    r.x = f2tf_f(v.x); r.y = f2tf_f(v.y); r.z = f2tf_f(v.z); r.w = f2tf_f(v.w);
    *(float4*)&y[i] = r;
    uint2 h;
    h.x = pack_bf2(v.x, v.y);
    h.y = pack_bf2(v.z, v.w);
    *(uint2*)&yh[i] = h;
}

// W[Q|K] into bf16 k-pair layout: word(kp, n) = (W[2kp][n], W[2kp+1][n])
__global__ void pack_wqk(const float* __restrict__ wq, const float* __restrict__ wkv,
                         unsigned* __restrict__ w)
{
    int idx = blockIdx.x * 256 + threadIdx.x;
    if (idx >= (DIM/2) * 1024) return;
    int kp = idx >> 10, n = idx & 1023;
    float a, b;
    if (n < DIM) { a = wq[(2*kp) * DIM + n];       b = wq[(2*kp+1) * DIM + n]; }
    else         { a = wkv[(2*kp) * 1024 + n-DIM]; b = wkv[(2*kp+1) * 1024 + n-DIM]; }
    w[idx] = pack_bf2(a, b);
}

__global__ void pack_wv(const float* __restrict__ wkv, float* __restrict__ w)
{
    int idx = blockIdx.x * 256 + threadIdx.x;
    if (idx >= DIM * DIM) return;
    int k = idx >> 9, c = idx & 511;
    w[idx] = f2tf_f(wkv[k * 1024 + DIM + c]);
}

__global__ void pack_wo(const float* __restrict__ wo, float* __restrict__ w)
{
    int idx = blockIdx.x * 256 + threadIdx.x;
    if (idx >= DIM * DIM) return;
    w[idx] = f2tf_f(wo[idx]);
}

__device__ __forceinline__ void mma_tf32(float* c, const unsigned* a,
                                         unsigned b0, unsigned b1)
{
    asm volatile(
        "mma.sync.aligned.m16n8k8.row.col.f32.tf32.tf32.f32 "
        "{%0,%1,%2,%3}, {%4,%5,%6,%7}, {%8,%9}, {%0,%1,%2,%3};\n"
        : "+f"(c[0]), "+f"(c[1]), "+f"(c[2]), "+f"(c[3])
        : "r"(a[0]), "r"(a[1]), "r"(a[2]), "r"(a[3]), "r"(b0), "r"(b1));
}

__device__ __forceinline__ void mma_bf16(float* c, const unsigned* a,
                                         unsigned b0, unsigned b1)
{
    asm volatile(
        "mma.sync.aligned.m16n8k16.row.col.f32.bf16.bf16.f32 "
        "{%0,%1,%2,%3}, {%4,%5,%6,%7}, {%8,%9}, {%0,%1,%2,%3};\n"
        : "+f"(c[0]), "+f"(c[1]), "+f"(c[2]), "+f"(c[3])
        : "r"(a[0]), "r"(a[1]), "r"(a[2]), "r"(a[3]), "r"(b0), "r"(b1));
}

__device__ __forceinline__ void cp16(unsigned dst, const void* src, bool pred) {
    int sz = pred ? 16 : 0;
    asm volatile("cp.async.cg.shared.global [%0], [%1], 16, %2;\n"
                 :: "r"(dst), "l"(src), "r"(sz));
}

// ---------------- pipelined tf32 GEMM (round-7 validated, + ldc) -------------
#define BM 128
#define BN 128
#define BK2 32
#define ASTR3 36
#define BSTR 136
#define A_TILE_U32 (BM * ASTR3)          // 4608
#define B_TILE_U32 (BK2 * BSTR)          // 4352
#define GEMM_SMEM ((3 * (A_TILE_U32 + B_TILE_U32)) * 4)  // 107520 B

template<bool BIAS>
__global__ void __launch_bounds__(256, 2)
gemm_tf32(const float* __restrict__ A, const float* __restrict__ B,
          const float* __restrict__ bias, float* __restrict__ C,
          int M, int N, int K, int ldc)
{
    extern __shared__ unsigned gsm[];
    unsigned* As = gsm;
    unsigned* Bs = gsm + 3 * A_TILE_U32;

    const int tid  = threadIdx.x;
    const int m0   = blockIdx.y * BM;
    const int n0   = blockIdx.x * BN;
    const int lane = tid & 31;
    const int wid  = tid >> 5;
    const int wm   = (wid & 1) * 64;
    const int wn   = (wid >> 1) * 32;
    const int lq   = lane & 3;
    const int lr   = lane >> 2;

    const unsigned aBase = (unsigned)__cvta_generic_to_shared(As);
    const unsigned bBase = (unsigned)__cvta_generic_to_shared(Bs);

    auto loadA = [&](int st, int k0) {
#pragma unroll
        for (int c = 0; c < 4; c++) {
            int chunk = c * 256 + tid;
            int row = chunk >> 3;
            int ch  = chunk & 7;
            bool v = (m0 + row) < M;
            cp16(aBase + (st * A_TILE_U32 + row * ASTR3 + ch * 4) * 4,
                 v ? &A[(size_t)(m0 + row) * K + k0 + ch * 4] : (const void*)A, v);
        }
    };
    auto loadB = [&](int st, int k0) {
#pragma unroll
        for (int c = 0; c < 4; c++) {
            int chunk = c * 256 + tid;
            int row = chunk >> 5;
            int ch  = chunk & 31;
            cp16(bBase + (st * B_TILE_U32 + row * BSTR + ch * 4) * 4,
                 &B[(size_t)(k0 + row) * N + n0 + ch * 4], true);
        }
    };

    float acc[4][4][4];
#pragma unroll
    for (int i = 0; i < 4; i++)
#pragma unroll
        for (int j = 0; j < 4; j++)
#pragma unroll
            for (int c = 0; c < 4; c++) acc[i][j][c] = 0.f;

    const int KT = K / BK2;

    loadA(0, 0); loadB(0, 0);
    asm volatile("cp.async.commit_group;\n");
    loadA(1, BK2); loadB(1, BK2);
    asm volatile("cp.async.commit_group;\n");

    int cur = 0, nxt = 2;
    for (int it = 0; it < KT; it++) {
        asm volatile("cp.async.wait_group %0;\n" :: "n"(1));
        __syncthreads();

        int pf = it + 2;
        if (pf < KT) { loadA(nxt, pf * BK2); loadB(nxt, pf * BK2); }
        asm volatile("cp.async.commit_group;\n");

        const unsigned* Ast = As + cur * A_TILE_U32;
        const unsigned* Bst = Bs + cur * B_TILE_U32;

#pragma unroll
        for (int ks = 0; ks < BK2; ks += 8) {
            unsigned af[4][4], bf[4][2];
#pragma unroll
            for (int tm = 0; tm < 4; tm++) {
                int m = wm + tm * 16 + lr;
                af[tm][0] = Ast[m * ASTR3 + ks + lq];
                af[tm][1] = Ast[(m + 8) * ASTR3 + ks + lq];
                af[tm][2] = Ast[m * ASTR3 + ks + lq + 4];
                af[tm][3] = Ast[(m + 8) * ASTR3 + ks + lq + 4];
            }
#pragma unroll
            for (int tn = 0; tn < 4; tn++) {
                int n = wn + tn * 8 + lr;
                bf[tn][0] = Bst[(ks + lq) * BSTR + n];
                bf[tn][1] = Bst[(ks + lq + 4) * BSTR + n];
            }
#pragma unroll
            for (int tm = 0; tm < 4; tm++)
#pragma unroll
                for (int tn = 0; tn < 4; tn++)
                    mma_tf32(acc[tm][tn], af[tm], bf[tn][0], bf[tn][1]);
        }
        cur = (cur == 2) ? 0 : cur + 1;
        nxt = (nxt == 2) ? 0 : nxt + 1;
    }

#pragma unroll
    for (int tm = 0; tm < 4; tm++) {
#pragma unroll
        for (int half = 0; half < 2; half++) {
            int row = m0 + wm + tm * 16 + lr + half * 8;
            if (row >= M) continue;
#pragma unroll
            for (int tn = 0; tn < 4; tn++) {
                int col = n0 + wn + tn * 8 + 2 * lq;
                float2 o;
                o.x = acc[tm][tn][half * 2 + 0];
                o.y = acc[tm][tn][half * 2 + 1];
                if (BIAS) { o.x += bias[col]; o.y += bias[col + 1]; }
                *(float2*)&C[(size_t)row * ldc + col] = o;
            }
        }
    }
}

// ---------------- pipelined bf16 GEMM (QK projection, round-11 validated) ----
#define AH 20                             // A row stride in u32 words (40 bf16)
#define AH_TILE (BM * AH)                 // 2560
#define BH_TILE ((BK2/2) * BSTR)          // 2176
#define GEMMH_SMEM ((3 * (AH_TILE + BH_TILE)) * 4)   // 56832 B

__global__ void __launch_bounds__(256, 2)
gemm_bf16(const __nv_bfloat16* __restrict__ A, const unsigned* __restrict__ B,
          float* __restrict__ C, int M, int N, int K, int ldc)
{
    extern __shared__ unsigned gsm[];
    unsigned* As = gsm;                     // [3][BM][AH]
    unsigned* Bs = gsm + 3 * AH_TILE;       // [3][BK2/2][BSTR]

    const int tid  = threadIdx.x;
    const int m0   = blockIdx.y * BM;
    const int n0   = blockIdx.x * BN;
    const int lane = tid & 31;
    const int wid  = tid >> 5;
    const int wm   = (wid & 1) * 64;
    const int wn   = (wid >> 1) * 32;
    const int lq   = lane & 3;
    const int lr   = lane >> 2;

    const unsigned aBase = (unsigned)__cvta_generic_to_shared(As);
    const unsigned bBase = (unsigned)__cvta_generic_to_shared(Bs);

    auto loadA = [&](int st, int k0) {
#pragma unroll
        for (int c = 0; c < 2; c++) {
            int chunk = c * 256 + tid;      // 0..511
            int row = chunk >> 2;           // 0..127
            int ch  = chunk & 3;            // 16B = 8 bf16 = 4 words
            bool v = (m0 + row) < M;
            cp16(aBase + (st * AH_TILE + row * AH + ch * 4) * 4,
                 v ? (const void*)&A[(size_t)(m0 + row) * K + k0 + ch * 8]
                   : (const void*)A, v);
        }
    };
    auto loadB = [&](int st, int k0) {      // k0 in elements; rows kp = k0/2..
        int kp0 = k0 >> 1;
#pragma unroll
        for (int c = 0; c < 2; c++) {
            int chunk = c * 256 + tid;      // 0..511
            int row = chunk >> 5;           // 0..15
            int ch  = chunk & 31;
            cp16(bBase + (st * BH_TILE + row * BSTR + ch * 4) * 4,
                 &B[(size_t)(kp0 + row) * N + n0 + ch * 4], true);
        }
    };

    float acc[4][4][4];
#pragma unroll
    for (int i = 0; i < 4; i++)
#pragma unroll
        for (int j = 0; j < 4; j++)
#pragma unroll
            for (int c = 0; c < 4; c++) acc[i][j][c] = 0.f;

    const int KT = K / BK2;

    loadA(0, 0); loadB(0, 0);
    asm volatile("cp.async.commit_group;\n");
    loadA(1, BK2); loadB(1, BK2);
    asm volatile("cp.async.commit_group;\n");

    int cur = 0, nxt = 2;
    for (int it = 0; it < KT; it++) {
        asm volatile("cp.async.wait_group %0;\n" :: "n"(1));
        __syncthreads();

        int pf = it + 2;
        if (pf < KT) { loadA(nxt, pf * BK2); loadB(nxt, pf * BK2); }
        asm volatile("cp.async.commit_group;\n");

        const unsigned* Ast = As + cur * AH_TILE;
        const unsigned* Bst = Bs + cur * BH_TILE;

#pragma unroll
        for (int kt = 0; kt < 2; kt++) {            // two k16 steps per BK2=32
            unsigned af[4][4], bf[4][2];
#pragma unroll
            for (int tm = 0; tm < 4; tm++) {
                int m = wm + tm * 16 + lr;
                af[tm][0] = Ast[m * AH + kt * 8 + lq];
                af[tm][1] = Ast[(m + 8) * AH + kt * 8 + lq];
                af[tm][2] = Ast[m * AH + kt * 8 + lq + 4];
                af[tm][3] = Ast[(m + 8) * AH + kt * 8 + lq + 4];
            }
#pragma unroll
            for (int tn = 0; tn < 4; tn++) {
                int n = wn + tn * 8 + lr;
                bf[tn][0] = Bst[(kt * 8 + lq) * BSTR + n];
                bf[tn][1] = Bst[(kt * 8 + lq + 4) * BSTR + n];
            }
#pragma unroll
            for (int tm = 0; tm < 4; tm++)
#pragma unroll
                for (int tn = 0; tn < 4; tn++)
                    mma_bf16(acc[tm][tn], af[tm], bf[tn][0], bf[tn][1]);
        }
        cur = (cur == 2) ? 0 : cur + 1;
        nxt = (nxt == 2) ? 0 : nxt + 1;
    }

#pragma unroll
    for (int tm = 0; tm < 4; tm++) {
#pragma unroll
        for (int half = 0; half < 2; half++) {
            int row = m0 + wm + tm * 16 + lr + half * 8;
            if (row >= M) continue;
#pragma unroll
            for (int tn = 0; tn < 4; tn++) {
                int col = n0 + wn + tn * 8 + 2 * lq;
                float2 o;
                o.x = acc[tm][tn][half * 2 + 0];
                o.y = acc[tm][tn][half * 2 + 1];
                *(float2*)&C[(size_t)row * ldc + col] = o;
            }
        }
    }
}

// ---------------- tensor-core chunked attention (384 threads, 12 warps) ------
#define ATHR 384
#define NW   12
#define KSW 36
#define VS2 212
#define TSW 36
#define ESTR 224
#define ATTN_SMEM ((200*KSW + 64*VS2 + 399*TSW) * 4 + NW*16*ESTR*2)

__global__ void __launch_bounds__(ATHR, 1)
attn_mma(const float* __restrict__ QKV, const float* __restrict__ T,
         float* __restrict__ AO)
{
    extern __shared__ unsigned smu[];
    unsigned* ksm   = smu;
    unsigned* vsm   = ksm + 200 * KSW;
    unsigned* tsm32 = vsm + 64 * VS2;
    unsigned short* esm = (unsigned short*)(tsm32 + 399 * TSW);

    const int b   = blockIdx.y;
    const int m   = blockIdx.x / HEADS;
    const int h   = blockIdx.x % HEADS;
    const int t0  = m * CTX;
    const int cv  = (NTOK - t0 < CTX) ? (NTOK - t0) : CTX;
    const int tid = threadIdx.x;
    const int w   = tid >> 5, lane = tid & 31;
    const int lr  = lane >> 2, lq = lane & 3;

    // ---- stage K as bf16 pairs, rows >= cv zeroed ----
    for (int idx = tid; idx < 200 * 16; idx += ATHR) {
        int i = idx >> 4, d = (idx & 15) * 4;
        unsigned p0 = 0u, p1 = 0u;
        if (i < cv) {
            const float* p = &QKV[(size_t)(b*NTOK + t0 + i)*NQKV + DIM + h*DH + d];
            float4 v = *(const float4*)p;
            p0 = pack_bf2(v.x, v.y);
            p1 = pack_bf2(v.z, v.w);
        }
        ksm[i*KSW + (d >> 1)]     = p0;
        ksm[i*KSW + (d >> 1) + 1] = p1;
    }
    // ---- stage V transposed [d][j] tf32 (float4 loads), cols >= cv zeroed ----
    for (int idx = tid; idx < 200 * 16; idx += ATHR) {
        int j = idx >> 4, d4 = (idx & 15) * 4;
        if (j < cv) {
            float4 v = *(const float4*)&QKV[(size_t)(b*NTOK + t0 + j)*NQKV
                                            + 2*DIM + h*DH + d4];
            vsm[(d4 + 0)*VS2 + j] = f2tf(v.x);
            vsm[(d4 + 1)*VS2 + j] = f2tf(v.y);
            vsm[(d4 + 2)*VS2 + j] = f2tf(v.z);
            vsm[(d4 + 3)*VS2 + j] = f2tf(v.w);
        } else {
            vsm[(d4 + 0)*VS2 + j] = 0u;
            vsm[(d4 + 1)*VS2 + j] = 0u;
            vsm[(d4 + 2)*VS2 + j] = 0u;
            vsm[(d4 + 3)*VS2 + j] = 0u;
        }
    }
    // ---- stage rel-pos table rows 313..711 as bf16 pairs ----
    for (int idx = tid; idx < 399 * 32; idx += ATHR) {
        int r = idx >> 5, e2 = (idx & 31) * 2;
        float2 tv = *(const float2*)&T[(size_t)(313 + r) * DH + e2];
        tsm32[r*TSW + (e2 >> 1)] = pack_bf2(tv.x, tv.y);
    }
    __syncthreads();

    unsigned short* E0 = esm + w * 16 * ESTR;

    for (int it = w; it * 16 < cv; it += NW) {
        const int i0 = it * 16;
        const int r0 = i0 + lr, r1 = r0 + 8;
        const bool v0 = r0 < cv, v1 = r1 < cv;
        unsigned short* Ea = E0 + lr * ESTR;
        unsigned short* Eb = E0 + (lr + 8) * ESTR;

        unsigned aq[4][4];
        {
            const float* q0 = &QKV[(size_t)(b*NTOK + t0 + r0)*NQKV + h*DH];
            const float* q1 = &QKV[(size_t)(b*NTOK + t0 + r1)*NQKV + h*DH];
#pragma unroll
            for (int kt = 0; kt < 4; kt++) {
                float2 x0 = v0 ? *(const float2*)&q0[kt*16 + 2*lq]
                               : make_float2(0.f, 0.f);
                float2 x1 = v1 ? *(const float2*)&q1[kt*16 + 2*lq]
                               : make_float2(0.f, 0.f);
                float2 y0 = v0 ? *(const float2*)&q0[kt*16 + 2*lq + 8]
                               : make_float2(0.f, 0.f);
                float2 y1 = v1 ? *(const float2*)&q1[kt*16 + 2*lq + 8]
                               : make_float2(0.f, 0.f);
                aq[kt][0] = pack_bf2(0.125f*x0.x, 0.125f*x0.y);
                aq[kt][1] = pack_bf2(0.125f*x1.x, 0.125f*x1.y);
                aq[kt][2] = pack_bf2(0.125f*y0.x, 0.125f*y0.y);
                aq[kt][3] = pack_bf2(0.125f*y1.x, 0.125f*y1.y);
            }
        }

#pragma unroll 3
        for (int rt = 0; rt < 27; rt++) {
            float ec[4] = {0.f, 0.f, 0.f, 0.f};
            int rg = i0 + rt * 8 + lr;
            bool tv = rg <= 398;
            const unsigned* trow = tsm32 + rg * TSW + lq;
#pragma unroll
            for (int kt = 0; kt < 4; kt++) {
                unsigned b0 = tv ? trow[kt*8]     : 0u;
                unsigned b1 = tv ? trow[kt*8 + 4] : 0u;
                mma_bf16(ec, aq[kt], b0, b1);
            }
            int c0 = rt * 8 + 2 * lq;
            *(unsigned*)&Ea[c0] = pack_bf2(ec[0], ec[1]);
            *(unsigned*)&Eb[c0] = pack_bf2(ec[2], ec[3]);
        }
        __syncwarp();

        float s[25][4];
#pragma unroll
        for (int nt = 0; nt < 25; nt++)
            s[nt][0] = s[nt][1] = s[nt][2] = s[nt][3] = 0.f;
#pragma unroll
        for (int kt = 0; kt < 4; kt++) {
#pragma unroll
            for (int nt = 0; nt < 25; nt++) {
                const unsigned* kr = ksm + (nt*8 + lr)*KSW + kt*8 + lq;
                mma_bf16(s[nt], aq[kt], kr[0], kr[4]);
            }
        }

        float mx0 = -1e30f, mx1 = -1e30f;
#pragma unroll
        for (int nt = 0; nt < 25; nt++) {
            int j0 = nt * 8 + 2 * lq;
#pragma unroll
            for (int e = 0; e < 2; e++) {
                int j = j0 + e;
                float b0f = __uint_as_float((unsigned)Ea[lr     + 199 - j] << 16);
                float b1f = __uint_as_float((unsigned)Eb[lr + 8 + 199 - j] << 16);
                float a0 = s[nt][e]     + b0f;
                float a1 = s[nt][2 + e] + b1f;
                if (j >= cv) { a0 = -1e30f; a1 = -1e30f; }
                s[nt][e] = a0; s[nt][2 + e] = a1;
                mx0 = fmaxf(mx0, a0); mx1 = fmaxf(mx1, a1);
            }
        }
        mx0 = fmaxf(mx0, __shfl_xor_sync(~0u, mx0, 1));
        mx0 = fmaxf(mx0, __shfl_xor_sync(~0u, mx0, 2));
        mx1 = fmaxf(mx1, __shfl_xor_sync(~0u, mx1, 1));
        mx1 = fmaxf(mx1, __shfl_xor_sync(~0u, mx1, 2));

        float sum0 = 0.f, sum1 = 0.f;
#pragma unroll
        for (int nt = 0; nt < 25; nt++) {
#pragma unroll
            for (int e = 0; e < 2; e++) {
                float p0 = __expf(s[nt][e]     - mx0);
                float p1 = __expf(s[nt][2 + e] - mx1);
                s[nt][e] = p0; s[nt][2 + e] = p1;
                sum0 += p0; sum1 += p1;
            }
        }
        sum0 += __shfl_xor_sync(~0u, sum0, 1);
        sum0 += __shfl_xor_sync(~0u, sum0, 2);
        sum1 += __shfl_xor_sync(~0u, sum1, 1);
        sum1 += __shfl_xor_sync(~0u, sum1, 2);
        const float inv0 = 1.f / sum0, inv1 = 1.f / sum1;

        float o[8][4];
#pragma unroll
        for (int nt = 0; nt < 8; nt++)
            o[nt][0] = o[nt][1] = o[nt][2] = o[nt][3] = 0.f;

        const int src1 = (lane & ~3) | (lq >> 1);
        const int src2 = src1 + 2;
        const bool odd = lq & 1;
#pragma unroll
        for (int kt = 0; kt < 25; kt++) {
            float x0 = __shfl_sync(~0u, s[kt][0], src1);
            float x1 = __shfl_sync(~0u, s[kt][1], src1);
            float y0 = __shfl_sync(~0u, s[kt][2], src1);
            float y1 = __shfl_sync(~0u, s[kt][3], src1);
            float z0 = __shfl_sync(~0u, s[kt][0], src2);
            float z1 = __shfl_sync(~0u, s[kt][1], src2);
            float u0 = __shfl_sync(~0u, s[kt][2], src2);
            float u1 = __shfl_sync(~0u, s[kt][3], src2);
            unsigned pa[4];
            pa[0] = f2tf(odd ? x1 : x0);
            pa[1] = f2tf(odd ? y1 : y0);
            pa[2] = f2tf(odd ? z1 : z0);
            pa[3] = f2tf(odd ? u1 : u0);
#pragma unroll
            for (int nt = 0; nt < 8; nt++) {
                unsigned b0 = vsm[(nt*8 + lr)*VS2 + kt*8 + lq];
                unsigned b1 = vsm[(nt*8 + lr)*VS2 + kt*8 + lq + 4];
                mma_tf32(o[nt], pa, b0, b1);
            }
        }

#pragma unroll
        for (int nt = 0; nt < 8; nt++) {
            int col = h*DH + nt*8 + 2*lq;
            if (v0) {
                float2 t2 = make_float2(f2tf_f(o[nt][0]*inv0), f2tf_f(o[nt][1]*inv0));
                *(float2*)&AO[(size_t)(b*NTOK + t0 + r0)*DIM + col] = t2;
            }
            if (v1) {
                float2 t2 = make_float2(f2tf_f(o[nt][2]*inv1), f2tf_f(o[nt][3]*inv1));
                *(float2*)&AO[(size_t)(b*NTOK + t0 + r1)*DIM + col] = t2;
            }
        }
        __syncwarp();
    }
}

// ---------------- launcher (serial; streams removed per R12 rule lesson) -----
extern "C" void kernel_launch(void* const* d_in, const int* in_sizes, int n_in,
                              void* d_out, int out_size)
{
    const float* x      = (const float*)d_in[0];
    const float* wq     = (const float*)d_in[1];
    const float* wkv    = (const float*)d_in[2];
    const float* wout_w = (const float*)d_in[3];
    const float* wout_b = (const float*)d_in[4];
    const float* rel    = (const float*)d_in[5];
    float* out = (float*)d_out;

    void *pqkv, *pao, *px, *pxh, *pwqk, *pwv, *pwo;
    cudaGetSymbolAddress(&pqkv, g_qkv);
    cudaGetSymbolAddress(&pao,  g_ao);
    cudaGetSymbolAddress(&px,   g_x);
    cudaGetSymbolAddress(&pxh,  g_xh);
    cudaGetSymbolAddress(&pwqk, g_wqkh);
    cudaGetSymbolAddress(&pwv,  g_wv);
    cudaGetSymbolAddress(&pwo,  g_wo);

    cudaFuncSetAttribute(attn_mma,
                         cudaFuncAttributeMaxDynamicSharedMemorySize, ATTN_SMEM);
    cudaFuncSetAttribute(gemm_tf32<false>,
                         cudaFuncAttributeMaxDynamicSharedMemorySize, GEMM_SMEM);
    cudaFuncSetAttribute(gemm_tf32<true>,
                         cudaFuncAttributeMaxDynamicSharedMemorySize, GEMM_SMEM);
    cudaFuncSetAttribute(gemm_bf16,
                         cudaFuncAttributeMaxDynamicSharedMemorySize, GEMMH_SMEM);

    const int M = MROWS;
    dim3 blk(256);

    round_x<<<(MROWS * DIM / 4 + 255) / 256, 256>>>(x, (float*)px,
                                                    (__nv_bfloat16*)pxh);
    pack_wqk<<<((DIM/2) * 1024 + 255) / 256, 256>>>(wq, wkv, (unsigned*)pwqk);
    pack_wv<<<(DIM * DIM + 255) / 256, 256>>>(wkv, (float*)pwv);
    pack_wo<<<(DIM * DIM + 255) / 256, 256>>>(wout_w, (float*)pwo);

    // Q|K = Xh @ Wqk (bf16)  -> g_qkv cols 0..1023
    dim3 gqk(1024 / BN, (M + BM - 1) / BM);
    gemm_bf16<<<gqk, blk, GEMMH_SMEM>>>((const __nv_bfloat16*)pxh,
                                        (const unsigned*)pwqk,
                                        (float*)pqkv, M, 1024, DIM, NQKV);

    // V = X @ Wv (tf32) -> g_qkv cols 1024..1535
    dim3 gv(DIM / BN, (M + BM - 1) / BM);
    gemm_tf32<false><<<gv, blk, GEMM_SMEM>>>((const float*)px, (const float*)pwv,
                                             nullptr, (float*)pqkv + 2*DIM,
                                             M, DIM, DIM, NQKV);

    attn_mma<<<dim3(NB * HEADS, BS), dim3(ATHR), ATTN_SMEM>>>(
        (const float*)pqkv, rel, (float*)pao);

    dim3 gout(DIM / BN, (M + BM - 1) / BM);
    gemm_tf32<true><<<gout, blk, GEMM_SMEM>>>((const float*)pao, (const float*)pwo,
                                              wout_b, out, M, DIM, DIM, DIM);
}

// round 15
// speedup vs baseline: 5.6345x; 1.0839x over previous
#include <cuda_runtime.h>
#include <cuda_bf16.h>

// ---------------- problem constants ----------------
#define BS    16
#define NTOK  3900
#define DIM   512
#define HEADS 8
#define DH    64
#define CTX   200
#define NB    20
#define MROWS (BS*NTOK)   // 62400
#define NQKV  1536        // fused q|k|v output width

// ---------------- scratch ----------------
__device__ float g_qkv[(size_t)MROWS * NQKV];          // 383 MB
__device__ float g_ao [(size_t)MROWS * DIM];           // 128 MB
__device__ float g_x  [(size_t)MROWS * DIM];           // 128 MB tf32-rounded X
__device__ __nv_bfloat16 g_xh[(size_t)MROWS * DIM];    // 64 MB bf16 X
__device__ unsigned g_wqkh[(DIM/2) * 1024];            // bf16-pair W[Q|K] [kp][n]
__device__ float g_wv [DIM * DIM];                     // tf32 V weights
__device__ float g_wo [DIM * DIM];                     // tf32 Wout

__device__ __forceinline__ unsigned f2tf(float f) {
    unsigned u; asm("cvt.rna.tf32.f32 %0, %1;" : "=r"(u) : "f"(f)); return u;
}
__device__ __forceinline__ float f2tf_f(float f) {
    return __uint_as_float(f2tf(f));
}
__device__ __forceinline__ unsigned pack_bf2(float lo, float hi) {
    __nv_bfloat162 p = __floats2bfloat162_rn(lo, hi);
    return *(unsigned*)&p;
}

// ---------------- rounding / packing kernels ----------------
__global__ void round_x(const float* __restrict__ x, float* __restrict__ y,
                        __nv_bfloat16* __restrict__ yh)
{
    size_t i = ((size_t)blockIdx.x * 256 + threadIdx.x) * 4;
    if (i >= (size_t)MROWS * DIM) return;
    float4 v = *(const float4*)&x[i];
    float4 r;
    r.x = f2tf_f(v.x); r.y = f2tf_f(v.y); r.z = f2tf_f(v.z); r.w = f2tf_f(v.w);
    *(float4*)&y[i] = r;
    uint2 h;
    h.x = pack_bf2(v.x, v.y);
    h.y = pack_bf2(v.z, v.w);
    *(uint2*)&yh[i] = h;
}

// W[Q|K] into bf16 k-pair layout: word(kp, n) = (W[2kp][n], W[2kp+1][n])
__global__ void pack_wqk(const float* __restrict__ wq, const float* __restrict__ wkv,
                         unsigned* __restrict__ w)
{
    int idx = blockIdx.x * 256 + threadIdx.x;
    if (idx >= (DIM/2) * 1024) return;
    int kp = idx >> 10, n = idx & 1023;
    float a, b;
    if (n < DIM) { a = wq[(2*kp) * DIM + n];       b = wq[(2*kp+1) * DIM + n]; }
    else         { a = wkv[(2*kp) * 1024 + n-DIM]; b = wkv[(2*kp+1) * 1024 + n-DIM]; }
    w[idx] = pack_bf2(a, b);
}

__global__ void pack_wv(const float* __restrict__ wkv, float* __restrict__ w)
{
    int idx = blockIdx.x * 256 + threadIdx.x;
    if (idx >= DIM * DIM) return;
    int k = idx >> 9, c = idx & 511;
    w[idx] = f2tf_f(wkv[k * 1024 + DIM + c]);
}

__global__ void pack_wo(const float* __restrict__ wo, float* __restrict__ w)
{
    int idx = blockIdx.x * 256 + threadIdx.x;
    if (idx >= DIM * DIM) return;
    w[idx] = f2tf_f(wo[idx]);
}

__device__ __forceinline__ void mma_tf32(float* c, const unsigned* a,
                                         unsigned b0, unsigned b1)
{
    asm volatile(
        "mma.sync.aligned.m16n8k8.row.col.f32.tf32.tf32.f32 "
        "{%0,%1,%2,%3}, {%4,%5,%6,%7}, {%8,%9}, {%0,%1,%2,%3};\n"
        : "+f"(c[0]), "+f"(c[1]), "+f"(c[2]), "+f"(c[3])
        : "r"(a[0]), "r"(a[1]), "r"(a[2]), "r"(a[3]), "r"(b0), "r"(b1));
}

__device__ __forceinline__ void mma_bf16(float* c, const unsigned* a,
                                         unsigned b0, unsigned b1)
{
    asm volatile(
        "mma.sync.aligned.m16n8k16.row.col.f32.bf16.bf16.f32 "
        "{%0,%1,%2,%3}, {%4,%5,%6,%7}, {%8,%9}, {%0,%1,%2,%3};\n"
        : "+f"(c[0]), "+f"(c[1]), "+f"(c[2]), "+f"(c[3])
        : "r"(a[0]), "r"(a[1]), "r"(a[2]), "r"(a[3]), "r"(b0), "r"(b1));
}

__device__ __forceinline__ void cp16(unsigned dst, const void* src, bool pred) {
    int sz = pred ? 16 : 0;
    asm volatile("cp.async.cg.shared.global [%0], [%1], 16, %2;\n"
                 :: "r"(dst), "l"(src), "r"(sz));
}

// ---------------- pipelined tf32 GEMM (round-7 validated, + ldc) -------------
#define BM 128
#define BN 128
#define BK2 32
#define ASTR3 36
#define BSTR 136
#define A_TILE_U32 (BM * ASTR3)          // 4608
#define B_TILE_U32 (BK2 * BSTR)          // 4352
#define GEMM_SMEM ((3 * (A_TILE_U32 + B_TILE_U32)) * 4)  // 107520 B

template<bool BIAS>
__global__ void __launch_bounds__(256, 2)
gemm_tf32(const float* __restrict__ A, const float* __restrict__ B,
          const float* __restrict__ bias, float* __restrict__ C,
          int M, int N, int K, int ldc)
{
    extern __shared__ unsigned gsm[];
    unsigned* As = gsm;
    unsigned* Bs = gsm + 3 * A_TILE_U32;

    const int tid  = threadIdx.x;
    const int m0   = blockIdx.y * BM;
    const int n0   = blockIdx.x * BN;
    const int lane = tid & 31;
    const int wid  = tid >> 5;
    const int wm   = (wid & 1) * 64;
    const int wn   = (wid >> 1) * 32;
    const int lq   = lane & 3;
    const int lr   = lane >> 2;

    const unsigned aBase = (unsigned)__cvta_generic_to_shared(As);
    const unsigned bBase = (unsigned)__cvta_generic_to_shared(Bs);

    auto loadA = [&](int st, int k0) {
#pragma unroll
        for (int c = 0; c < 4; c++) {
            int chunk = c * 256 + tid;
            int row = chunk >> 3;
            int ch  = chunk & 7;
            bool v = (m0 + row) < M;
            cp16(aBase + (st * A_TILE_U32 + row * ASTR3 + ch * 4) * 4,
                 v ? &A[(size_t)(m0 + row) * K + k0 + ch * 4] : (const void*)A, v);
        }
    };
    auto loadB = [&](int st, int k0) {
#pragma unroll
        for (int c = 0; c < 4; c++) {
            int chunk = c * 256 + tid;
            int row = chunk >> 5;
            int ch  = chunk & 31;
            cp16(bBase + (st * B_TILE_U32 + row * BSTR + ch * 4) * 4,
                 &B[(size_t)(k0 + row) * N + n0 + ch * 4], true);
        }
    };

    float acc[4][4][4];
#pragma unroll
    for (int i = 0; i < 4; i++)
#pragma unroll
        for (int j = 0; j < 4; j++)
#pragma unroll
            for (int c = 0; c < 4; c++) acc[i][j][c] = 0.f;

    const int KT = K / BK2;

    loadA(0, 0); loadB(0, 0);
    asm volatile("cp.async.commit_group;\n");
    loadA(1, BK2); loadB(1, BK2);
    asm volatile("cp.async.commit_group;\n");

    int cur = 0, nxt = 2;
    for (int it = 0; it < KT; it++) {
        asm volatile("cp.async.wait_group %0;\n" :: "n"(1));
        __syncthreads();

        int pf = it + 2;
        if (pf < KT) { loadA(nxt, pf * BK2); loadB(nxt, pf * BK2); }
        asm volatile("cp.async.commit_group;\n");

        const unsigned* Ast = As + cur * A_TILE_U32;
        const unsigned* Bst = Bs + cur * B_TILE_U32;

#pragma unroll
        for (int ks = 0; ks < BK2; ks += 8) {
            unsigned af[4][4], bf[4][2];
#pragma unroll
            for (int tm = 0; tm < 4; tm++) {
                int m = wm + tm * 16 + lr;
                af[tm][0] = Ast[m * ASTR3 + ks + lq];
                af[tm][1] = Ast[(m + 8) * ASTR3 + ks + lq];
                af[tm][2] = Ast[m * ASTR3 + ks + lq + 4];
                af[tm][3] = Ast[(m + 8) * ASTR3 + ks + lq + 4];
            }
#pragma unroll
            for (int tn = 0; tn < 4; tn++) {
                int n = wn + tn * 8 + lr;
                bf[tn][0] = Bst[(ks + lq) * BSTR + n];
                bf[tn][1] = Bst[(ks + lq + 4) * BSTR + n];
            }
#pragma unroll
            for (int tm = 0; tm < 4; tm++)
#pragma unroll
                for (int tn = 0; tn < 4; tn++)
                    mma_tf32(acc[tm][tn], af[tm], bf[tn][0], bf[tn][1]);
        }
        cur = (cur == 2) ? 0 : cur + 1;
        nxt = (nxt == 2) ? 0 : nxt + 1;
    }

#pragma unroll
    for (int tm = 0; tm < 4; tm++) {
#pragma unroll
        for (int half = 0; half < 2; half++) {
            int row = m0 + wm + tm * 16 + lr + half * 8;
            if (row >= M) continue;
#pragma unroll
            for (int tn = 0; tn < 4; tn++) {
                int col = n0 + wn + tn * 8 + 2 * lq;
                float2 o;
                o.x = acc[tm][tn][half * 2 + 0];
                o.y = acc[tm][tn][half * 2 + 1];
                if (BIAS) { o.x += bias[col]; o.y += bias[col + 1]; }
                *(float2*)&C[(size_t)row * ldc + col] = o;
            }
        }
    }
}

// ---------------- pipelined bf16 GEMM (QK projection, round-11 validated) ----
#define AH 20                             // A row stride in u32 words (40 bf16)
#define AH_TILE (BM * AH)                 // 2560
#define BH_TILE ((BK2/2) * BSTR)          // 2176
#define GEMMH_SMEM ((3 * (AH_TILE + BH_TILE)) * 4)   // 56832 B

__global__ void __launch_bounds__(256, 2)
gemm_bf16(const __nv_bfloat16* __restrict__ A, const unsigned* __restrict__ B,
          float* __restrict__ C, int M, int N, int K, int ldc)
{
    extern __shared__ unsigned gsm[];
    unsigned* As = gsm;                     // [3][BM][AH]
    unsigned* Bs = gsm + 3 * AH_TILE;       // [3][BK2/2][BSTR]

    const int tid  = threadIdx.x;
    const int m0   = blockIdx.y * BM;
    const int n0   = blockIdx.x * BN;
    const int lane = tid & 31;
    const int wid  = tid >> 5;
    const int wm   = (wid & 1) * 64;
    const int wn   = (wid >> 1) * 32;
    const int lq   = lane & 3;
    const int lr   = lane >> 2;

    const unsigned aBase = (unsigned)__cvta_generic_to_shared(As);
    const unsigned bBase = (unsigned)__cvta_generic_to_shared(Bs);

    auto loadA = [&](int st, int k0) {
#pragma unroll
        for (int c = 0; c < 2; c++) {
            int chunk = c * 256 + tid;      // 0..511
            int row = chunk >> 2;           // 0..127
            int ch  = chunk & 3;            // 16B = 8 bf16 = 4 words
            bool v = (m0 + row) < M;
            cp16(aBase + (st * AH_TILE + row * AH + ch * 4) * 4,
                 v ? (const void*)&A[(size_t)(m0 + row) * K + k0 + ch * 8]
                   : (const void*)A, v);
        }
    };
    auto loadB = [&](int st, int k0) {      // k0 in elements; rows kp = k0/2..
        int kp0 = k0 >> 1;
#pragma unroll
        for (int c = 0; c < 2; c++) {
            int chunk = c * 256 + tid;      // 0..511
            int row = chunk >> 5;           // 0..15
            int ch  = chunk & 31;
            cp16(bBase + (st * BH_TILE + row * BSTR + ch * 4) * 4,
                 &B[(size_t)(kp0 + row) * N + n0 + ch * 4], true);
        }
    };

    float acc[4][4][4];
#pragma unroll
    for (int i = 0; i < 4; i++)
#pragma unroll
        for (int j = 0; j < 4; j++)
#pragma unroll
            for (int c = 0; c < 4; c++) acc[i][j][c] = 0.f;

    const int KT = K / BK2;

    loadA(0, 0); loadB(0, 0);
    asm volatile("cp.async.commit_group;\n");
    loadA(1, BK2); loadB(1, BK2);
    asm volatile("cp.async.commit_group;\n");

    int cur = 0, nxt = 2;
    for (int it = 0; it < KT; it++) {
        asm volatile("cp.async.wait_group %0;\n" :: "n"(1));
        __syncthreads();

        int pf = it + 2;
        if (pf < KT) { loadA(nxt, pf * BK2); loadB(nxt, pf * BK2); }
        asm volatile("cp.async.commit_group;\n");

        const unsigned* Ast = As + cur * AH_TILE;
        const unsigned* Bst = Bs + cur * BH_TILE;

#pragma unroll
        for (int kt = 0; kt < 2; kt++) {            // two k16 steps per BK2=32
            unsigned af[4][4], bf[4][2];
#pragma unroll
            for (int tm = 0; tm < 4; tm++) {
                int m = wm + tm * 16 + lr;
                af[tm][0] = Ast[m * AH + kt * 8 + lq];
                af[tm][1] = Ast[(m + 8) * AH + kt * 8 + lq];
                af[tm][2] = Ast[m * AH + kt * 8 + lq + 4];
                af[tm][3] = Ast[(m + 8) * AH + kt * 8 + lq + 4];
            }
#pragma unroll
            for (int tn = 0; tn < 4; tn++) {
                int n = wn + tn * 8 + lr;
                bf[tn][0] = Bst[(kt * 8 + lq) * BSTR + n];
                bf[tn][1] = Bst[(kt * 8 + lq + 4) * BSTR + n];
            }
#pragma unroll
            for (int tm = 0; tm < 4; tm++)
#pragma unroll
                for (int tn = 0; tn < 4; tn++)
                    mma_bf16(acc[tm][tn], af[tm], bf[tn][0], bf[tn][1]);
        }
        cur = (cur == 2) ? 0 : cur + 1;
        nxt = (nxt == 2) ? 0 : nxt + 1;
    }

#pragma unroll
    for (int tm = 0; tm < 4; tm++) {
#pragma unroll
        for (int half = 0; half < 2; half++) {
            int row = m0 + wm + tm * 16 + lr + half * 8;
            if (row >= M) continue;
#pragma unroll
            for (int tn = 0; tn < 4; tn++) {
                int col = n0 + wn + tn * 8 + 2 * lq;
                float2 o;
                o.x = acc[tm][tn][half * 2 + 0];
                o.y = acc[tm][tn][half * 2 + 1];
                *(float2*)&C[(size_t)row * ldc + col] = o;
            }
        }
    }
}

// ---------------- tensor-core chunked attention (416 threads, 13 warps) ------
// 13 i-tiles of 16 rows, one per warp -> no serial tail.
#define ATHR 416
#define NW   13
#define KSW 36
#define VS2 212
#define TSW 36
#define ESTR 220
#define ATTN_SMEM ((200*KSW + 64*VS2 + 399*TSW) * 4 + NW*16*ESTR*2)  // 232048 B

__global__ void __launch_bounds__(ATHR, 1)
attn_mma(const float* __restrict__ QKV, const float* __restrict__ T,
         float* __restrict__ AO)
{
    extern __shared__ unsigned smu[];
    unsigned* ksm   = smu;
    unsigned* vsm   = ksm + 200 * KSW;
    unsigned* tsm32 = vsm + 64 * VS2;
    unsigned short* esm = (unsigned short*)(tsm32 + 399 * TSW);

    const int b   = blockIdx.y;
    const int m   = blockIdx.x / HEADS;
    const int h   = blockIdx.x % HEADS;
    const int t0  = m * CTX;
    const int cv  = (NTOK - t0 < CTX) ? (NTOK - t0) : CTX;
    const int tid = threadIdx.x;
    const int w   = tid >> 5, lane = tid & 31;
    const int lr  = lane >> 2, lq = lane & 3;

    // ---- stage K as bf16 pairs, rows >= cv zeroed ----
    for (int idx = tid; idx < 200 * 16; idx += ATHR) {
        int i = idx >> 4, d = (idx & 15) * 4;
        unsigned p0 = 0u, p1 = 0u;
        if (i < cv) {
            const float* p = &QKV[(size_t)(b*NTOK + t0 + i)*NQKV + DIM + h*DH + d];
            float4 v = *(const float4*)p;
            p0 = pack_bf2(v.x, v.y);
            p1 = pack_bf2(v.z, v.w);
        }
        ksm[i*KSW + (d >> 1)]     = p0;
        ksm[i*KSW + (d >> 1) + 1] = p1;
    }
    // ---- stage V transposed [d][j] tf32 (float4 loads), cols >= cv zeroed ----
    for (int idx = tid; idx < 200 * 16; idx += ATHR) {
        int j = idx >> 4, d4 = (idx & 15) * 4;
        if (j < cv) {
            float4 v = *(const float4*)&QKV[(size_t)(b*NTOK + t0 + j)*NQKV
                                            + 2*DIM + h*DH + d4];
            vsm[(d4 + 0)*VS2 + j] = f2tf(v.x);
            vsm[(d4 + 1)*VS2 + j] = f2tf(v.y);
            vsm[(d4 + 2)*VS2 + j] = f2tf(v.z);
            vsm[(d4 + 3)*VS2 + j] = f2tf(v.w);
        } else {
            vsm[(d4 + 0)*VS2 + j] = 0u;
            vsm[(d4 + 1)*VS2 + j] = 0u;
            vsm[(d4 + 2)*VS2 + j] = 0u;
            vsm[(d4 + 3)*VS2 + j] = 0u;
        }
    }
    // ---- stage rel-pos table rows 313..711 as bf16 pairs ----
    for (int idx = tid; idx < 399 * 32; idx += ATHR) {
        int r = idx >> 5, e2 = (idx & 31) * 2;
        float2 tv = *(const float2*)&T[(size_t)(313 + r) * DH + e2];
        tsm32[r*TSW + (e2 >> 1)] = pack_bf2(tv.x, tv.y);
    }
    __syncthreads();

    unsigned short* E0 = esm + w * 16 * ESTR;

    for (int it = w; it * 16 < cv; it += NW) {
        const int i0 = it * 16;
        const int r0 = i0 + lr, r1 = r0 + 8;
        const bool v0 = r0 < cv, v1 = r1 < cv;
        unsigned short* Ea = E0 + lr * ESTR;
        unsigned short* Eb = E0 + (lr + 8) * ESTR;

        unsigned aq[4][4];
        {
            const float* q0 = &QKV[(size_t)(b*NTOK + t0 + r0)*NQKV + h*DH];
            const float* q1 = &QKV[(size_t)(b*NTOK + t0 + r1)*NQKV + h*DH];
#pragma unroll
            for (int kt = 0; kt < 4; kt++) {
                float2 x0 = v0 ? *(const float2*)&q0[kt*16 + 2*lq]
                               : make_float2(0.f, 0.f);
                float2 x1 = v1 ? *(const float2*)&q1[kt*16 + 2*lq]
                               : make_float2(0.f, 0.f);
                float2 y0 = v0 ? *(const float2*)&q0[kt*16 + 2*lq + 8]
                               : make_float2(0.f, 0.f);
                float2 y1 = v1 ? *(const float2*)&q1[kt*16 + 2*lq + 8]
                               : make_float2(0.f, 0.f);
                aq[kt][0] = pack_bf2(0.125f*x0.x, 0.125f*x0.y);
                aq[kt][1] = pack_bf2(0.125f*x1.x, 0.125f*x1.y);
                aq[kt][2] = pack_bf2(0.125f*y0.x, 0.125f*y0.y);
                aq[kt][3] = pack_bf2(0.125f*y1.x, 0.125f*y1.y);
            }
        }

#pragma unroll 3
        for (int rt = 0; rt < 27; rt++) {
            float ec[4] = {0.f, 0.f, 0.f, 0.f};
            int rg = i0 + rt * 8 + lr;
            bool tv = rg <= 398;
            const unsigned* trow = tsm32 + rg * TSW + lq;
#pragma unroll
            for (int kt = 0; kt < 4; kt++) {
                unsigned b0 = tv ? trow[kt*8]     : 0u;
                unsigned b1 = tv ? trow[kt*8 + 4] : 0u;
                mma_bf16(ec, aq[kt], b0, b1);
            }
            int c0 = rt * 8 + 2 * lq;
            *(unsigned*)&Ea[c0] = pack_bf2(ec[0], ec[1]);
            *(unsigned*)&Eb[c0] = pack_bf2(ec[2], ec[3]);
        }
        __syncwarp();

        float s[25][4];
#pragma unroll
        for (int nt = 0; nt < 25; nt++)
            s[nt][0] = s[nt][1] = s[nt][2] = s[nt][3] = 0.f;
#pragma unroll
        for (int kt = 0; kt < 4; kt++) {
#pragma unroll
            for (int nt = 0; nt < 25; nt++) {
                const unsigned* kr = ksm + (nt*8 + lr)*KSW + kt*8 + lq;
                mma_bf16(s[nt], aq[kt], kr[0], kr[4]);
            }
        }

        float mx0 = -1e30f, mx1 = -1e30f;
#pragma unroll
        for (int nt = 0; nt < 25; nt++) {
            int j0 = nt * 8 + 2 * lq;
#pragma unroll
            for (int e = 0; e < 2; e++) {
                int j = j0 + e;
                float b0f = __uint_as_float((unsigned)Ea[lr     + 199 - j] << 16);
                float b1f = __uint_as_float((unsigned)Eb[lr + 8 + 199 - j] << 16);
                float a0 = s[nt][e]     + b0f;
                float a1 = s[nt][2 + e] + b1f;
                if (j >= cv) { a0 = -1e30f; a1 = -1e30f; }
                s[nt][e] = a0; s[nt][2 + e] = a1;
                mx0 = fmaxf(mx0, a0); mx1 = fmaxf(mx1, a1);
            }
        }
        mx0 = fmaxf(mx0, __shfl_xor_sync(~0u, mx0, 1));
        mx0 = fmaxf(mx0, __shfl_xor_sync(~0u, mx0, 2));
        mx1 = fmaxf(mx1, __shfl_xor_sync(~0u, mx1, 1));
        mx1 = fmaxf(mx1, __shfl_xor_sync(~0u, mx1, 2));

        float sum0 = 0.f, sum1 = 0.f;
#pragma unroll
        for (int nt = 0; nt < 25; nt++) {
#pragma unroll
            for (int e = 0; e < 2; e++) {
                float p0 = __expf(s[nt][e]     - mx0);
                float p1 = __expf(s[nt][2 + e] - mx1);
                s[nt][e] = p0; s[nt][2 + e] = p1;
                sum0 += p0; sum1 += p1;
            }
        }
        sum0 += __shfl_xor_sync(~0u, sum0, 1);
        sum0 += __shfl_xor_sync(~0u, sum0, 2);
        sum1 += __shfl_xor_sync(~0u, sum1, 1);
        sum1 += __shfl_xor_sync(~0u, sum1, 2);
        const float inv0 = 1.f / sum0, inv1 = 1.f / sum1;

        float o[8][4];
#pragma unroll
        for (int nt = 0; nt < 8; nt++)
            o[nt][0] = o[nt][1] = o[nt][2] = o[nt][3] = 0.f;

        const int src1 = (lane & ~3) | (lq >> 1);
        const int src2 = src1 + 2;
        const bool odd = lq & 1;
#pragma unroll
        for (int kt = 0; kt < 25; kt++) {
            float x0 = __shfl_sync(~0u, s[kt][0], src1);
            float x1 = __shfl_sync(~0u, s[kt][1], src1);
            float y0 = __shfl_sync(~0u, s[kt][2], src1);
            float y1 = __shfl_sync(~0u, s[kt][3], src1);
            float z0 = __shfl_sync(~0u, s[kt][0], src2);
            float z1 = __shfl_sync(~0u, s[kt][1], src2);
            float u0 = __shfl_sync(~0u, s[kt][2], src2);
            float u1 = __shfl_sync(~0u, s[kt][3], src2);
            unsigned pa[4];
            pa[0] = f2tf(odd ? x1 : x0);
            pa[1] = f2tf(odd ? y1 : y0);
            pa[2] = f2tf(odd ? z1 : z0);
            pa[3] = f2tf(odd ? u1 : u0);
#pragma unroll
            for (int nt = 0; nt < 8; nt++) {
                unsigned b0 = vsm[(nt*8 + lr)*VS2 + kt*8 + lq];
                unsigned b1 = vsm[(nt*8 + lr)*VS2 + kt*8 + lq + 4];
                mma_tf32(o[nt], pa, b0, b1);
            }
        }

#pragma unroll
        for (int nt = 0; nt < 8; nt++) {
            int col = h*DH + nt*8 + 2*lq;
            if (v0) {
                float2 t2 = make_float2(f2tf_f(o[nt][0]*inv0), f2tf_f(o[nt][1]*inv0));
                *(float2*)&AO[(size_t)(b*NTOK + t0 + r0)*DIM + col] = t2;
            }
            if (v1) {
                float2 t2 = make_float2(f2tf_f(o[nt][2]*inv1), f2tf_f(o[nt][3]*inv1));
                *(float2*)&AO[(size_t)(b*NTOK + t0 + r1)*DIM + col] = t2;
            }
        }
        __syncwarp();
    }
}

// ---------------- launcher ----------------
extern "C" void kernel_launch(void* const* d_in, const int* in_sizes, int n_in,
                              void* d_out, int out_size)
{
    const float* x      = (const float*)d_in[0];
    const float* wq     = (const float*)d_in[1];
    const float* wkv    = (const float*)d_in[2];
    const float* wout_w = (const float*)d_in[3];
    const float* wout_b = (const float*)d_in[4];
    const float* rel    = (const float*)d_in[5];
    float* out = (float*)d_out;

    void *pqkv, *pao, *px, *pxh, *pwqk, *pwv, *pwo;
    cudaGetSymbolAddress(&pqkv, g_qkv);
    cudaGetSymbolAddress(&pao,  g_ao);
    cudaGetSymbolAddress(&px,   g_x);
    cudaGetSymbolAddress(&pxh,  g_xh);
    cudaGetSymbolAddress(&pwqk, g_wqkh);
    cudaGetSymbolAddress(&pwv,  g_wv);
    cudaGetSymbolAddress(&pwo,  g_wo);

    cudaFuncSetAttribute(attn_mma,
                         cudaFuncAttributeMaxDynamicSharedMemorySize, ATTN_SMEM);
    cudaFuncSetAttribute(gemm_tf32<false>,
                         cudaFuncAttributeMaxDynamicSharedMemorySize, GEMM_SMEM);
    cudaFuncSetAttribute(gemm_tf32<true>,
                         cudaFuncAttributeMaxDynamicSharedMemorySize, GEMM_SMEM);
    cudaFuncSetAttribute(gemm_bf16,
                         cudaFuncAttributeMaxDynamicSharedMemorySize, GEMMH_SMEM);

    const int M = MROWS;
    dim3 blk(256);

    round_x<<<(MROWS * DIM / 4 + 255) / 256, 256>>>(x, (float*)px,
                                                    (__nv_bfloat16*)pxh);
    pack_wqk<<<((DIM/2) * 1024 + 255) / 256, 256>>>(wq, wkv, (unsigned*)pwqk);
    pack_wv<<<(DIM * DIM + 255) / 256, 256>>>(wkv, (float*)pwv);
    pack_wo<<<(DIM * DIM + 255) / 256, 256>>>(wout_w, (float*)pwo);

    // Q|K = Xh @ Wqk (bf16)  -> g_qkv cols 0..1023
    dim3 gqk(1024 / BN, (M + BM - 1) / BM);
    gemm_bf16<<<gqk, blk, GEMMH_SMEM>>>((const __nv_bfloat16*)pxh,
                                        (const unsigned*)pwqk,
                                        (float*)pqkv, M, 1024, DIM, NQKV);

    // V = X @ Wv (tf32) -> g_qkv cols 1024..1535
    dim3 gv(DIM / BN, (M + BM - 1) / BM);
    gemm_tf32<false><<<gv, blk, GEMM_SMEM>>>((const float*)px, (const float*)pwv,
                                             nullptr, (float*)pqkv + 2*DIM,
                                             M, DIM, DIM, NQKV);

    attn_mma<<<dim3(NB * HEADS, BS), dim3(ATHR), ATTN_SMEM>>>(
        (const float*)pqkv, rel, (float*)pao);

    dim3 gout(DIM / BN, (M + BM - 1) / BM);
    gemm_tf32<true><<<gout, blk, GEMM_SMEM>>>((const float*)pao, (const float*)pwo,
                                              wout_b, out, M, DIM, DIM, DIM);
}

// round 16
// speedup vs baseline: 5.6691x; 1.0061x over previous
#include <cuda_runtime.h>
#include <cuda_bf16.h>

// ---------------- problem constants ----------------
#define BS    16
#define NTOK  3900
#define DIM   512
#define HEADS 8
#define DH    64
#define CTX   200
#define NB    20
#define MROWS (BS*NTOK)   // 62400

// ---------------- scratch ----------------
__device__ __nv_bfloat16 g_qkh[(size_t)MROWS * 1024];  // 128 MB bf16 [Q(scaled)|K]
__device__ float g_v  [(size_t)MROWS * DIM];           // 128 MB tf32 V
__device__ float g_ao [(size_t)MROWS * DIM];           // 128 MB attention out
__device__ __nv_bfloat16 g_xh[(size_t)MROWS * DIM];    // 64 MB bf16 X
__device__ unsigned g_wqkh[(DIM/2) * 1024];            // bf16-pair W[Qs|K] [kp][n]
__device__ float g_wv [DIM * DIM];                     // tf32 V weights
__device__ float g_wo [DIM * DIM];                     // tf32 Wout
__device__ unsigned g_th [399 * 32];                   // bf16-pair rel table rows 313..711

__device__ __forceinline__ unsigned f2tf(float f) {
    unsigned u; asm("cvt.rna.tf32.f32 %0, %1;" : "=r"(u) : "f"(f)); return u;
}
__device__ __forceinline__ float f2tf_f(float f) {
    return __uint_as_float(f2tf(f));
}
__device__ __forceinline__ unsigned pack_bf2(float lo, float hi) {
    __nv_bfloat162 p = __floats2bfloat162_rn(lo, hi);
    return *(unsigned*)&p;
}

// ---------------- packing kernels ----------------
__global__ void round_xh(const float* __restrict__ x, __nv_bfloat16* __restrict__ yh)
{
    size_t i = ((size_t)blockIdx.x * 256 + threadIdx.x) * 4;
    if (i >= (size_t)MROWS * DIM) return;
    float4 v = *(const float4*)&x[i];
    uint2 h;
    h.x = pack_bf2(v.x, v.y);
    h.y = pack_bf2(v.z, v.w);
    *(uint2*)&yh[i] = h;
}

// W[0.125*Wq | Wk] into bf16 k-pair layout: word(kp, n) = (W[2kp][n], W[2kp+1][n])
__global__ void pack_wqk(const float* __restrict__ wq, const float* __restrict__ wkv,
                         unsigned* __restrict__ w)
{
    int idx = blockIdx.x * 256 + threadIdx.x;
    if (idx >= (DIM/2) * 1024) return;
    int kp = idx >> 10, n = idx & 1023;
    float a, b;
    if (n < DIM) {
        a = 0.125f * wq[(2*kp) * DIM + n];
        b = 0.125f * wq[(2*kp+1) * DIM + n];
    } else {
        a = wkv[(2*kp) * 1024 + n-DIM];
        b = wkv[(2*kp+1) * 1024 + n-DIM];
    }
    w[idx] = pack_bf2(a, b);
}

__global__ void pack_wv(const float* __restrict__ wkv, float* __restrict__ w)
{
    int idx = blockIdx.x * 256 + threadIdx.x;
    if (idx >= DIM * DIM) return;
    int k = idx >> 9, c = idx & 511;
    w[idx] = f2tf_f(wkv[k * 1024 + DIM + c]);
}

__global__ void pack_wo(const float* __restrict__ wo, float* __restrict__ w)
{
    int idx = blockIdx.x * 256 + threadIdx.x;
    if (idx >= DIM * DIM) return;
    w[idx] = f2tf_f(wo[idx]);
}

__global__ void pack_t(const float* __restrict__ T, unsigned* __restrict__ th)
{
    int idx = blockIdx.x * 256 + threadIdx.x;
    if (idx >= 399 * 32) return;
    int r = idx >> 5, c2 = (idx & 31) * 2;
    float2 tv = *(const float2*)&T[(size_t)(313 + r) * DH + c2];
    th[idx] = pack_bf2(tv.x, tv.y);
}

__device__ __forceinline__ void mma_tf32(float* c, const unsigned* a,
                                         unsigned b0, unsigned b1)
{
    asm volatile(
        "mma.sync.aligned.m16n8k8.row.col.f32.tf32.tf32.f32 "
        "{%0,%1,%2,%3}, {%4,%5,%6,%7}, {%8,%9}, {%0,%1,%2,%3};\n"
        : "+f"(c[0]), "+f"(c[1]), "+f"(c[2]), "+f"(c[3])
        : "r"(a[0]), "r"(a[1]), "r"(a[2]), "r"(a[3]), "r"(b0), "r"(b1));
}

__device__ __forceinline__ void mma_bf16(float* c, const unsigned* a,
                                         unsigned b0, unsigned b1)
{
    asm volatile(
        "mma.sync.aligned.m16n8k16.row.col.f32.bf16.bf16.f32 "
        "{%0,%1,%2,%3}, {%4,%5,%6,%7}, {%8,%9}, {%0,%1,%2,%3};\n"
        : "+f"(c[0]), "+f"(c[1]), "+f"(c[2]), "+f"(c[3])
        : "r"(a[0]), "r"(a[1]), "r"(a[2]), "r"(a[3]), "r"(b0), "r"(b1));
}

__device__ __forceinline__ void cp16(unsigned dst, const void* src, bool pred) {
    int sz = pred ? 16 : 0;
    asm volatile("cp.async.cg.shared.global [%0], [%1], 16, %2;\n"
                 :: "r"(dst), "l"(src), "r"(sz));
}

// ---------------- pipelined tf32 GEMM (+ in-register A rounding) -------------
#define BM 128
#define BN 128
#define BK2 32
#define ASTR3 36
#define BSTR 136
#define A_TILE_U32 (BM * ASTR3)          // 4608
#define B_TILE_U32 (BK2 * BSTR)          // 4352
#define GEMM_SMEM ((3 * (A_TILE_U32 + B_TILE_U32)) * 4)  // 107520 B

template<bool BIAS, bool CVTA>
__global__ void __launch_bounds__(256, 2)
gemm_tf32(const float* __restrict__ A, const float* __restrict__ B,
          const float* __restrict__ bias, float* __restrict__ C,
          int M, int N, int K, int ldc)
{
    extern __shared__ unsigned gsm[];
    unsigned* As = gsm;
    unsigned* Bs = gsm + 3 * A_TILE_U32;

    const int tid  = threadIdx.x;
    const int m0   = blockIdx.y * BM;
    const int n0   = blockIdx.x * BN;
    const int lane = tid & 31;
    const int wid  = tid >> 5;
    const int wm   = (wid & 1) * 64;
    const int wn   = (wid >> 1) * 32;
    const int lq   = lane & 3;
    const int lr   = lane >> 2;

    const unsigned aBase = (unsigned)__cvta_generic_to_shared(As);
    const unsigned bBase = (unsigned)__cvta_generic_to_shared(Bs);

    auto loadA = [&](int st, int k0) {
#pragma unroll
        for (int c = 0; c < 4; c++) {
            int chunk = c * 256 + tid;
            int row = chunk >> 3;
            int ch  = chunk & 7;
            bool v = (m0 + row) < M;
            cp16(aBase + (st * A_TILE_U32 + row * ASTR3 + ch * 4) * 4,
                 v ? &A[(size_t)(m0 + row) * K + k0 + ch * 4] : (const void*)A, v);
        }
    };
    auto loadB = [&](int st, int k0) {
#pragma unroll
        for (int c = 0; c < 4; c++) {
            int chunk = c * 256 + tid;
            int row = chunk >> 5;
            int ch  = chunk & 31;
            cp16(bBase + (st * B_TILE_U32 + row * BSTR + ch * 4) * 4,
                 &B[(size_t)(k0 + row) * N + n0 + ch * 4], true);
        }
    };

    float acc[4][4][4];
#pragma unroll
    for (int i = 0; i < 4; i++)
#pragma unroll
        for (int j = 0; j < 4; j++)
#pragma unroll
            for (int c = 0; c < 4; c++) acc[i][j][c] = 0.f;

    const int KT = K / BK2;

    loadA(0, 0); loadB(0, 0);
    asm volatile("cp.async.commit_group;\n");
    loadA(1, BK2); loadB(1, BK2);
    asm volatile("cp.async.commit_group;\n");

    int cur = 0, nxt = 2;
    for (int it = 0; it < KT; it++) {
        asm volatile("cp.async.wait_group %0;\n" :: "n"(1));
        __syncthreads();

        int pf = it + 2;
        if (pf < KT) { loadA(nxt, pf * BK2); loadB(nxt, pf * BK2); }
        asm volatile("cp.async.commit_group;\n");

        const unsigned* Ast = As + cur * A_TILE_U32;
        const unsigned* Bst = Bs + cur * B_TILE_U32;

#pragma unroll
        for (int ks = 0; ks < BK2; ks += 8) {
            unsigned af[4][4], bf[4][2];
#pragma unroll
            for (int tm = 0; tm < 4; tm++) {
                int m = wm + tm * 16 + lr;
                af[tm][0] = Ast[m * ASTR3 + ks + lq];
                af[tm][1] = Ast[(m + 8) * ASTR3 + ks + lq];
                af[tm][2] = Ast[m * ASTR3 + ks + lq + 4];
                af[tm][3] = Ast[(m + 8) * ASTR3 + ks + lq + 4];
                if (CVTA) {
                    af[tm][0] = f2tf(__uint_as_float(af[tm][0]));
                    af[tm][1] = f2tf(__uint_as_float(af[tm][1]));
                    af[tm][2] = f2tf(__uint_as_float(af[tm][2]));
                    af[tm][3] = f2tf(__uint_as_float(af[tm][3]));
                }
            }
#pragma unroll
            for (int tn = 0; tn < 4; tn++) {
                int n = wn + tn * 8 + lr;
                bf[tn][0] = Bst[(ks + lq) * BSTR + n];
                bf[tn][1] = Bst[(ks + lq + 4) * BSTR + n];
            }
#pragma unroll
            for (int tm = 0; tm < 4; tm++)
#pragma unroll
                for (int tn = 0; tn < 4; tn++)
                    mma_tf32(acc[tm][tn], af[tm], bf[tn][0], bf[tn][1]);
        }
        cur = (cur == 2) ? 0 : cur + 1;
        nxt = (nxt == 2) ? 0 : nxt + 1;
    }

#pragma unroll
    for (int tm = 0; tm < 4; tm++) {
#pragma unroll
        for (int half = 0; half < 2; half++) {
            int row = m0 + wm + tm * 16 + lr + half * 8;
            if (row >= M) continue;
#pragma unroll
            for (int tn = 0; tn < 4; tn++) {
                int col = n0 + wn + tn * 8 + 2 * lq;
                float2 o;
                o.x = acc[tm][tn][half * 2 + 0];
                o.y = acc[tm][tn][half * 2 + 1];
                if (BIAS) { o.x += bias[col]; o.y += bias[col + 1]; }
                *(float2*)&C[(size_t)row * ldc + col] = o;
            }
        }
    }
}

// ---------------- pipelined bf16 GEMM (QK projection, bf16 output) -----------
#define AH 20
#define AH_TILE (BM * AH)                 // 2560
#define BH_TILE ((BK2/2) * BSTR)          // 2176
#define GEMMH_SMEM ((3 * (AH_TILE + BH_TILE)) * 4)   // 56832 B

__global__ void __launch_bounds__(256, 2)
gemm_bf16(const __nv_bfloat16* __restrict__ A, const unsigned* __restrict__ B,
          __nv_bfloat16* __restrict__ C, int M, int N, int K, int ldc)
{
    extern __shared__ unsigned gsm[];
    unsigned* As = gsm;
    unsigned* Bs = gsm + 3 * AH_TILE;

    const int tid  = threadIdx.x;
    const int m0   = blockIdx.y * BM;
    const int n0   = blockIdx.x * BN;
    const int lane = tid & 31;
    const int wid  = tid >> 5;
    const int wm   = (wid & 1) * 64;
    const int wn   = (wid >> 1) * 32;
    const int lq   = lane & 3;
    const int lr   = lane >> 2;

    const unsigned aBase = (unsigned)__cvta_generic_to_shared(As);
    const unsigned bBase = (unsigned)__cvta_generic_to_shared(Bs);

    auto loadA = [&](int st, int k0) {
#pragma unroll
        for (int c = 0; c < 2; c++) {
            int chunk = c * 256 + tid;
            int row = chunk >> 2;
            int ch  = chunk & 3;
            bool v = (m0 + row) < M;
            cp16(aBase + (st * AH_TILE + row * AH + ch * 4) * 4,
                 v ? (const void*)&A[(size_t)(m0 + row) * K + k0 + ch * 8]
                   : (const void*)A, v);
        }
    };
    auto loadB = [&](int st, int k0) {
        int kp0 = k0 >> 1;
#pragma unroll
        for (int c = 0; c < 2; c++) {
            int chunk = c * 256 + tid;
            int row = chunk >> 5;
            int ch  = chunk & 31;
            cp16(bBase + (st * BH_TILE + row * BSTR + ch * 4) * 4,
                 &B[(size_t)(kp0 + row) * N + n0 + ch * 4], true);
        }
    };

    float acc[4][4][4];
#pragma unroll
    for (int i = 0; i < 4; i++)
#pragma unroll
        for (int j = 0; j < 4; j++)
#pragma unroll
            for (int c = 0; c < 4; c++) acc[i][j][c] = 0.f;

    const int KT = K / BK2;

    loadA(0, 0); loadB(0, 0);
    asm volatile("cp.async.commit_group;\n");
    loadA(1, BK2); loadB(1, BK2);
    asm volatile("cp.async.commit_group;\n");

    int cur = 0, nxt = 2;
    for (int it = 0; it < KT; it++) {
        asm volatile("cp.async.wait_group %0;\n" :: "n"(1));
        __syncthreads();

        int pf = it + 2;
        if (pf < KT) { loadA(nxt, pf * BK2); loadB(nxt, pf * BK2); }
        asm volatile("cp.async.commit_group;\n");

        const unsigned* Ast = As + cur * AH_TILE;
        const unsigned* Bst = Bs + cur * BH_TILE;

#pragma unroll
        for (int kt = 0; kt < 2; kt++) {
            unsigned af[4][4], bf[4][2];
#pragma unroll
            for (int tm = 0; tm < 4; tm++) {
                int m = wm + tm * 16 + lr;
                af[tm][0] = Ast[m * AH + kt * 8 + lq];
                af[tm][1] = Ast[(m + 8) * AH + kt * 8 + lq];
                af[tm][2] = Ast[m * AH + kt * 8 + lq + 4];
                af[tm][3] = Ast[(m + 8) * AH + kt * 8 + lq + 4];
            }
#pragma unroll
            for (int tn = 0; tn < 4; tn++) {
                int n = wn + tn * 8 + lr;
                bf[tn][0] = Bst[(kt * 8 + lq) * BSTR + n];
                bf[tn][1] = Bst[(kt * 8 + lq + 4) * BSTR + n];
            }
#pragma unroll
            for (int tm = 0; tm < 4; tm++)
#pragma unroll
                for (int tn = 0; tn < 4; tn++)
                    mma_bf16(acc[tm][tn], af[tm], bf[tn][0], bf[tn][1]);
        }
        cur = (cur == 2) ? 0 : cur + 1;
        nxt = (nxt == 2) ? 0 : nxt + 1;
    }

    // epilogue: write bf16 pairs directly
#pragma unroll
    for (int tm = 0; tm < 4; tm++) {
#pragma unroll
        for (int half = 0; half < 2; half++) {
            int row = m0 + wm + tm * 16 + lr + half * 8;
            if (row >= M) continue;
#pragma unroll
            for (int tn = 0; tn < 4; tn++) {
                int col = n0 + wn + tn * 8 + 2 * lq;     // even
                unsigned pr = pack_bf2(acc[tm][tn][half * 2 + 0],
                                       acc[tm][tn][half * 2 + 1]);
                *(unsigned*)&C[(size_t)row * ldc + col] = pr;
            }
        }
    }
}

// ---------------- tensor-core chunked attention (416 threads, 13 warps) ------
#define ATHR 416
#define NW   13
#define KSW 36
#define VS2 212
#define TSW 36
#define ESTR 220
#define ATTN_SMEM ((200*KSW + 64*VS2 + 399*TSW) * 4 + NW*16*ESTR*2)  // 232048 B

__global__ void __launch_bounds__(ATHR, 1)
attn_mma(const unsigned* __restrict__ QKh,   // bf16-pair words, [row][512]
         const float* __restrict__ V,        // [row][512] tf32 values
         const unsigned* __restrict__ Th,    // [399][32] bf16-pair words
         float* __restrict__ AO)
{
    extern __shared__ unsigned smu[];
    unsigned* ksm   = smu;
    unsigned* vsm   = ksm + 200 * KSW;
    unsigned* tsm32 = vsm + 64 * VS2;
    unsigned short* esm = (unsigned short*)(tsm32 + 399 * TSW);

    const int b   = blockIdx.y;
    const int m   = blockIdx.x / HEADS;
    const int h   = blockIdx.x % HEADS;
    const int t0  = m * CTX;
    const int cv  = (NTOK - t0 < CTX) ? (NTOK - t0) : CTX;
    const int tid = threadIdx.x;
    const int w   = tid >> 5, lane = tid & 31;
    const int lr  = lane >> 2, lq = lane & 3;

    // ---- stage K (bf16 words, direct copy), rows >= cv zeroed ----
    for (int idx = tid; idx < 200 * 16; idx += ATHR) {
        int i = idx >> 4, jw2 = (idx & 15) * 2;
        uint2 v = make_uint2(0u, 0u);
        if (i < cv)
            v = *(const uint2*)&QKh[(size_t)(b*NTOK + t0 + i)*512 + 256 + h*32 + jw2];
        *(uint2*)&ksm[i*KSW + jw2] = v;
    }
    // ---- stage V transposed [d][j] tf32, cols >= cv zeroed ----
    for (int idx = tid; idx < 200 * 16; idx += ATHR) {
        int j = idx >> 4, d4 = (idx & 15) * 4;
        if (j < cv) {
            float4 v = *(const float4*)&V[(size_t)(b*NTOK + t0 + j)*512 + h*DH + d4];
            vsm[(d4 + 0)*VS2 + j] = f2tf(v.x);
            vsm[(d4 + 1)*VS2 + j] = f2tf(v.y);
            vsm[(d4 + 2)*VS2 + j] = f2tf(v.z);
            vsm[(d4 + 3)*VS2 + j] = f2tf(v.w);
        } else {
            vsm[(d4 + 0)*VS2 + j] = 0u;
            vsm[(d4 + 1)*VS2 + j] = 0u;
            vsm[(d4 + 2)*VS2 + j] = 0u;
            vsm[(d4 + 3)*VS2 + j] = 0u;
        }
    }
    // ---- stage rel-pos table (bf16 words, direct copy) ----
    for (int idx = tid; idx < 399 * 16; idx += ATHR) {
        int r = idx >> 4, c2 = (idx & 15) * 2;
        *(uint2*)&tsm32[r*TSW + c2] = *(const uint2*)&Th[r*32 + c2];
    }
    __syncthreads();

    unsigned short* E0 = esm + w * 16 * ESTR;

    for (int it = w; it * 16 < cv; it += NW) {
        const int i0 = it * 16;
        const int r0 = i0 + lr, r1 = r0 + 8;
        const bool v0 = r0 < cv, v1 = r1 < cv;
        unsigned short* Ea = E0 + lr * ESTR;
        unsigned short* Eb = E0 + (lr + 8) * ESTR;

        // ---- Q fragments: direct bf16-pair word loads (prescaled at proj) ----
        unsigned aq[4][4];
        {
            const unsigned* q0 = &QKh[(size_t)(b*NTOK + t0 + r0)*512 + h*32];
            const unsigned* q1 = &QKh[(size_t)(b*NTOK + t0 + r1)*512 + h*32];
#pragma unroll
            for (int kt = 0; kt < 4; kt++) {
                aq[kt][0] = v0 ? q0[kt*8 + lq]     : 0u;
                aq[kt][1] = v1 ? q1[kt*8 + lq]     : 0u;
                aq[kt][2] = v0 ? q0[kt*8 + lq + 4] : 0u;
                aq[kt][3] = v1 ? q1[kt*8 + lq + 4] : 0u;
            }
        }

        // ---- E[16][216] = Q @ T^T (bf16 k16) ----
#pragma unroll 3
        for (int rt = 0; rt < 27; rt++) {
            float ec[4] = {0.f, 0.f, 0.f, 0.f};
            int rg = i0 + rt * 8 + lr;
            bool tv = rg <= 398;
            const unsigned* trow = tsm32 + rg * TSW + lq;
#pragma unroll
            for (int kt = 0; kt < 4; kt++) {
                unsigned b0 = tv ? trow[kt*8]     : 0u;
                unsigned b1 = tv ? trow[kt*8 + 4] : 0u;
                mma_bf16(ec, aq[kt], b0, b1);
            }
            int c0 = rt * 8 + 2 * lq;
            *(unsigned*)&Ea[c0] = pack_bf2(ec[0], ec[1]);
            *(unsigned*)&Eb[c0] = pack_bf2(ec[2], ec[3]);
        }
        __syncwarp();

        // ---- S = Q @ K^T (bf16 k16) ----
        float s[25][4];
#pragma unroll
        for (int nt = 0; nt < 25; nt++)
            s[nt][0] = s[nt][1] = s[nt][2] = s[nt][3] = 0.f;
#pragma unroll
        for (int kt = 0; kt < 4; kt++) {
#pragma unroll
            for (int nt = 0; nt < 25; nt++) {
                const unsigned* kr = ksm + (nt*8 + lr)*KSW + kt*8 + lq;
                mma_bf16(s[nt], aq[kt], kr[0], kr[4]);
            }
        }

        // ---- bias gather + mask + row max ----
        float mx0 = -1e30f, mx1 = -1e30f;
#pragma unroll
        for (int nt = 0; nt < 25; nt++) {
            int j0 = nt * 8 + 2 * lq;
#pragma unroll
            for (int e = 0; e < 2; e++) {
                int j = j0 + e;
                float b0f = __uint_as_float((unsigned)Ea[lr     + 199 - j] << 16);
                float b1f = __uint_as_float((unsigned)Eb[lr + 8 + 199 - j] << 16);
                float a0 = s[nt][e]     + b0f;
                float a1 = s[nt][2 + e] + b1f;
                if (j >= cv) { a0 = -1e30f; a1 = -1e30f; }
                s[nt][e] = a0; s[nt][2 + e] = a1;
                mx0 = fmaxf(mx0, a0); mx1 = fmaxf(mx1, a1);
            }
        }
        mx0 = fmaxf(mx0, __shfl_xor_sync(~0u, mx0, 1));
        mx0 = fmaxf(mx0, __shfl_xor_sync(~0u, mx0, 2));
        mx1 = fmaxf(mx1, __shfl_xor_sync(~0u, mx1, 1));
        mx1 = fmaxf(mx1, __shfl_xor_sync(~0u, mx1, 2));

        float sum0 = 0.f, sum1 = 0.f;
#pragma unroll
        for (int nt = 0; nt < 25; nt++) {
#pragma unroll
            for (int e = 0; e < 2; e++) {
                float p0 = __expf(s[nt][e]     - mx0);
                float p1 = __expf(s[nt][2 + e] - mx1);
                s[nt][e] = p0; s[nt][2 + e] = p1;
                sum0 += p0; sum1 += p1;
            }
        }
        sum0 += __shfl_xor_sync(~0u, sum0, 1);
        sum0 += __shfl_xor_sync(~0u, sum0, 2);
        sum1 += __shfl_xor_sync(~0u, sum1, 1);
        sum1 += __shfl_xor_sync(~0u, sum1, 2);
        const float inv0 = 1.f / sum0, inv1 = 1.f / sum1;

        // ---- O = P @ V (tf32), P fragments via shuffle ----
        float o[8][4];
#pragma unroll
        for (int nt = 0; nt < 8; nt++)
            o[nt][0] = o[nt][1] = o[nt][2] = o[nt][3] = 0.f;

        const int src1 = (lane & ~3) | (lq >> 1);
        const int src2 = src1 + 2;
        const bool odd = lq & 1;
#pragma unroll
        for (int kt = 0; kt < 25; kt++) {
            float x0 = __shfl_sync(~0u, s[kt][0], src1);
            float x1 = __shfl_sync(~0u, s[kt][1], src1);
            float y0 = __shfl_sync(~0u, s[kt][2], src1);
            float y1 = __shfl_sync(~0u, s[kt][3], src1);
            float z0 = __shfl_sync(~0u, s[kt][0], src2);
            float z1 = __shfl_sync(~0u, s[kt][1], src2);
            float u0 = __shfl_sync(~0u, s[kt][2], src2);
            float u1 = __shfl_sync(~0u, s[kt][3], src2);
            unsigned pa[4];
            pa[0] = f2tf(odd ? x1 : x0);
            pa[1] = f2tf(odd ? y1 : y0);
            pa[2] = f2tf(odd ? z1 : z0);
            pa[3] = f2tf(odd ? u1 : u0);
#pragma unroll
            for (int nt = 0; nt < 8; nt++) {
                unsigned b0 = vsm[(nt*8 + lr)*VS2 + kt*8 + lq];
                unsigned b1 = vsm[(nt*8 + lr)*VS2 + kt*8 + lq + 4];
                mma_tf32(o[nt], pa, b0, b1);
            }
        }

        // ---- write O (normalized, tf32-rounded for exact out-proj) ----
#pragma unroll
        for (int nt = 0; nt < 8; nt++) {
            int col = h*DH + nt*8 + 2*lq;
            if (v0) {
                float2 t2 = make_float2(f2tf_f(o[nt][0]*inv0), f2tf_f(o[nt][1]*inv0));
                *(float2*)&AO[(size_t)(b*NTOK + t0 + r0)*DIM + col] = t2;
            }
            if (v1) {
                float2 t2 = make_float2(f2tf_f(o[nt][2]*inv1), f2tf_f(o[nt][3]*inv1));
                *(float2*)&AO[(size_t)(b*NTOK + t0 + r1)*DIM + col] = t2;
            }
        }
        __syncwarp();
    }
}

// ---------------- launcher ----------------
extern "C" void kernel_launch(void* const* d_in, const int* in_sizes, int n_in,
                              void* d_out, int out_size)
{
    const float* x      = (const float*)d_in[0];
    const float* wq     = (const float*)d_in[1];
    const float* wkv    = (const float*)d_in[2];
    const float* wout_w = (const float*)d_in[3];
    const float* wout_b = (const float*)d_in[4];
    const float* rel    = (const float*)d_in[5];
    float* out = (float*)d_out;

    void *pqkh, *pv, *pao, *pxh, *pwqk, *pwv, *pwo, *pth;
    cudaGetSymbolAddress(&pqkh, g_qkh);
    cudaGetSymbolAddress(&pv,   g_v);
    cudaGetSymbolAddress(&pao,  g_ao);
    cudaGetSymbolAddress(&pxh,  g_xh);
    cudaGetSymbolAddress(&pwqk, g_wqkh);
    cudaGetSymbolAddress(&pwv,  g_wv);
    cudaGetSymbolAddress(&pwo,  g_wo);
    cudaGetSymbolAddress(&pth,  g_th);

    cudaFuncSetAttribute(attn_mma,
                         cudaFuncAttributeMaxDynamicSharedMemorySize, ATTN_SMEM);
    cudaFuncSetAttribute(gemm_tf32<false, true>,
                         cudaFuncAttributeMaxDynamicSharedMemorySize, GEMM_SMEM);
    cudaFuncSetAttribute(gemm_tf32<true, false>,
                         cudaFuncAttributeMaxDynamicSharedMemorySize, GEMM_SMEM);
    cudaFuncSetAttribute(gemm_bf16,
                         cudaFuncAttributeMaxDynamicSharedMemorySize, GEMMH_SMEM);

    const int M = MROWS;
    dim3 blk(256);

    round_xh<<<(MROWS * DIM / 4 + 255) / 256, 256>>>(x, (__nv_bfloat16*)pxh);
    pack_wqk<<<((DIM/2) * 1024 + 255) / 256, 256>>>(wq, wkv, (unsigned*)pwqk);
    pack_wv<<<(DIM * DIM + 255) / 256, 256>>>(wkv, (float*)pwv);
    pack_wo<<<(DIM * DIM + 255) / 256, 256>>>(wout_w, (float*)pwo);
    pack_t<<<(399 * 32 + 255) / 256, 256>>>(rel, (unsigned*)pth);

    // [0.125*Q | K] = Xh @ Wqk (bf16 in, bf16 out)
    dim3 gqk(1024 / BN, (M + BM - 1) / BM);
    gemm_bf16<<<gqk, blk, GEMMH_SMEM>>>((const __nv_bfloat16*)pxh,
                                        (const unsigned*)pwqk,
                                        (__nv_bfloat16*)pqkh, M, 1024, DIM, 1024);

    // V = X @ Wv (tf32, A rounded in-register)
    dim3 gv(DIM / BN, (M + BM - 1) / BM);
    gemm_tf32<false, true><<<gv, blk, GEMM_SMEM>>>(x, (const float*)pwv,
                                                   nullptr, (float*)pv,
                                                   M, DIM, DIM, DIM);

    attn_mma<<<dim3(NB * HEADS, BS), dim3(ATHR), ATTN_SMEM>>>(
        (const unsigned*)pqkh, (const float*)pv, (const unsigned*)pth,
        (float*)pao);

    dim3 gout(DIM / BN, (M + BM - 1) / BM);
    gemm_tf32<true, false><<<gout, blk, GEMM_SMEM>>>((const float*)pao,
                                                     (const float*)pwo,
                                                     wout_b, out, M, DIM, DIM, DIM);
}